// round 1
// baseline (speedup 1.0000x reference)
#include <cuda_runtime.h>

#define BB 8
#define NN_ 8192
#define MM 2048
#define C1 128
#define C2 256
#define CIN 384
#define CO 256

typedef unsigned long long ull;

// ---------------- device scratch (no allocations allowed) ----------------
__device__ int   g_idx[BB * NN_];
__device__ float g_y0[(size_t)BB * CO * NN_];   // 64MB pre-BN output of layer 0
__device__ float g_ab0[2 * CO];                 // a,b affine for BN0
__device__ float g_ab1[2 * CO];                 // a,b affine for BN1

// ---------------- packed f32x2 helpers (IEEE-exact per lane) -------------
__device__ __forceinline__ ull f2_add(ull a, ull b) {
    ull r; asm("add.rn.f32x2 %0, %1, %2;" : "=l"(r) : "l"(a), "l"(b)); return r;
}
__device__ __forceinline__ ull f2_mul(ull a, ull b) {
    ull r; asm("mul.rn.f32x2 %0, %1, %2;" : "=l"(r) : "l"(a), "l"(b)); return r;
}
__device__ __forceinline__ ull f2_pack(float lo, float hi) {
    ull r; asm("mov.b64 %0, {%1, %2};" : "=l"(r) : "f"(lo), "f"(hi)); return r;
}
__device__ __forceinline__ void f2_unpack(float& lo, float& hi, ull v) {
    asm("mov.b64 {%0, %1}, %2;" : "=f"(lo), "=f"(hi) : "l"(v));
}

// ---------------- 1) nearest neighbor (exact, bitwise-matching) ----------
// d = ((px-qx)^2 + (py-qy)^2) + (pz-qz)^2, separate roundings (no FMA),
// matching XLA's mul-then-reduce semantics. Subtraction realized as
// px + (-qx) with negation done once in SMEM (exact).
// Grid: (N/256, B); 128 threads, 2 points per thread; even/odd m streams.
__global__ __launch_bounds__(128) void nn_kernel(const float* __restrict__ xyz1,
                                                 const float* __restrict__ xyz2) {
    __shared__ __align__(16) float nq[3][MM];  // negated xyz2, 24KB
    const int b  = blockIdx.y;
    const int n0 = blockIdx.x * 256;
    const int tid = threadIdx.x;

    const float* x2 = xyz2 + (size_t)b * MM * 3;
    for (int m = tid; m < MM; m += 128) {
        nq[0][m] = -x2[3 * m + 0];
        nq[1][m] = -x2[3 * m + 1];
        nq[2][m] = -x2[3 * m + 2];
    }
    __syncthreads();

    const ull* qx2 = (const ull*)nq[0];
    const ull* qy2 = (const ull*)nq[1];
    const ull* qz2 = (const ull*)nq[2];

    const int ng0 = n0 + tid;
    const int ng1 = n0 + tid + 128;
    const float* p0 = xyz1 + ((size_t)b * NN_ + ng0) * 3;
    const float* p1 = xyz1 + ((size_t)b * NN_ + ng1) * 3;

    const ull px0 = f2_pack(p0[0], p0[0]);
    const ull py0 = f2_pack(p0[1], p0[1]);
    const ull pz0 = f2_pack(p0[2], p0[2]);
    const ull px1 = f2_pack(p1[0], p1[0]);
    const ull py1 = f2_pack(p1[1], p1[1]);
    const ull pz1 = f2_pack(p1[2], p1[2]);

    float be0 = 3.0e38f, bo0 = 3.0e38f, be1 = 3.0e38f, bo1 = 3.0e38f;
    int   ie0 = 0, io0 = 1, ie1 = 0, io1 = 1;

#pragma unroll 4
    for (int m2 = 0; m2 < MM / 2; ++m2) {
        const ull qx = qx2[m2], qy = qy2[m2], qz = qz2[m2];
        {
            ull dx = f2_add(px0, qx), dy = f2_add(py0, qy), dz = f2_add(pz0, qz);
            ull d  = f2_add(f2_add(f2_mul(dx, dx), f2_mul(dy, dy)), f2_mul(dz, dz));
            float dl, dh; f2_unpack(dl, dh, d);
            if (dl < be0) { be0 = dl; ie0 = 2 * m2; }
            if (dh < bo0) { bo0 = dh; io0 = 2 * m2 + 1; }
        }
        {
            ull dx = f2_add(px1, qx), dy = f2_add(py1, qy), dz = f2_add(pz1, qz);
            ull d  = f2_add(f2_add(f2_mul(dx, dx), f2_mul(dy, dy)), f2_mul(dz, dz));
            float dl, dh; f2_unpack(dl, dh, d);
            if (dl < be1) { be1 = dl; ie1 = 2 * m2; }
            if (dh < bo1) { bo1 = dh; io1 = 2 * m2 + 1; }
        }
    }
    // combine even/odd streams with first-occurrence (lowest index) tie-break
    int bi0 = ie0;
    if (bo0 < be0 || (bo0 == be0 && io0 < ie0)) bi0 = io0;
    int bi1 = ie1;
    if (bo1 < be1 || (bo1 == be1 && io1 < ie1)) bi1 = io1;

    g_idx[b * NN_ + ng0] = bi0;
    g_idx[b * NN_ + ng1] = bi1;
}

// ---------------- 2) GEMM layer 0 (fused gather), writes raw y0 ----------
// y0[b,o,n] = sum_c W0[o,c] * x[b,c,n], x = concat(features1, gather(features2))
// Tiles: 128 out-ch x 128 points, K-step 16, 256 threads, 8x8 microtile.
#define KT 16
__global__ __launch_bounds__(256) void gemm0_kernel(const float* __restrict__ f1,
                                                    const float* __restrict__ f2,
                                                    const float* __restrict__ w0) {
    __shared__ float Ws[KT][128];
    __shared__ float Xs[KT][132];
    __shared__ int   sidx[128];

    const int bx = blockIdx.x;          // b * 64 + ntile
    const int b  = bx >> 6;
    const int n0 = (bx & 63) << 7;
    const int o0 = blockIdx.y << 7;
    const int tid = threadIdx.x;
    const int tx = tid & 15, ty = tid >> 4;

    if (tid < 128) sidx[tid] = g_idx[b * NN_ + n0 + tid];

    float acc[8][8] = {};
    const float* f1b = f1 + (size_t)b * C1 * NN_ + n0;
    const float* f2b = f2 + (size_t)b * C2 * MM;

    for (int k0 = 0; k0 < CIN; k0 += KT) {
        __syncthreads();
        // W tile: Ws[kk][o], coalesced read along CIN
        {
            const int o = tid >> 1;
            const int c = (tid & 1) << 3;
            const float4* wp = (const float4*)(w0 + (size_t)(o0 + o) * CIN + k0 + c);
            float4 v0 = wp[0], v1 = wp[1];
            Ws[c + 0][o] = v0.x; Ws[c + 1][o] = v0.y; Ws[c + 2][o] = v0.z; Ws[c + 3][o] = v0.w;
            Ws[c + 4][o] = v1.x; Ws[c + 5][o] = v1.y; Ws[c + 6][o] = v1.z; Ws[c + 7][o] = v1.w;
        }
        // X tile: Xs[kk][n]; rows < C1 coalesced from f1, rows >= C1 gathered
        {
            const int kk = tid >> 4;
            const int nn = (tid & 15) << 3;
            const int c = k0 + kk;
            if (c < C1) {
                const float4* p = (const float4*)(f1b + (size_t)c * NN_ + nn);
                float4 v0 = p[0], v1 = p[1];
                *(float4*)&Xs[kk][nn]     = v0;
                *(float4*)&Xs[kk][nn + 4] = v1;
            } else {
                const float* p = f2b + (size_t)(c - C1) * MM;
#pragma unroll
                for (int j = 0; j < 8; j++) Xs[kk][nn + j] = __ldg(p + sidx[nn + j]);
            }
        }
        __syncthreads();
#pragma unroll
        for (int kk = 0; kk < KT; kk++) {
            float a[8], x[8];
            *(float4*)&a[0] = *(const float4*)&Ws[kk][ty * 8];
            *(float4*)&a[4] = *(const float4*)&Ws[kk][ty * 8 + 4];
            *(float4*)&x[0] = *(const float4*)&Xs[kk][tx * 8];
            *(float4*)&x[4] = *(const float4*)&Xs[kk][tx * 8 + 4];
#pragma unroll
            for (int i = 0; i < 8; i++)
#pragma unroll
                for (int j = 0; j < 8; j++) acc[i][j] = fmaf(a[i], x[j], acc[i][j]);
        }
    }
#pragma unroll
    for (int i = 0; i < 8; i++) {
        float* dst = g_y0 + ((size_t)(b * CO + o0 + ty * 8 + i)) * NN_ + n0 + tx * 8;
        *(float4*)dst       = make_float4(acc[i][0], acc[i][1], acc[i][2], acc[i][3]);
        *(float4*)(dst + 4) = make_float4(acc[i][4], acc[i][5], acc[i][6], acc[i][7]);
    }
}

// ---------------- 3) per-channel BN stats (deterministic tree) -----------
template <bool FIRST>
__global__ __launch_bounds__(256) void stats_kernel(const float* __restrict__ yparam,
                                                    const float* __restrict__ gamma,
                                                    const float* __restrict__ beta) {
    const float* y = FIRST ? (const float*)g_y0 : yparam;
    float* ab = FIRST ? g_ab0 : g_ab1;
    const int o = blockIdx.x;
    const int tid = threadIdx.x;

    float s = 0.f, s2 = 0.f;
    for (int i4 = tid; i4 < (BB * NN_) / 4; i4 += 256) {
        const int bb = i4 >> 11;         // N/4 = 2048 vectors per batch
        const int n4 = i4 & 2047;
        const float4 v = *(const float4*)(y + ((size_t)(bb * CO + o)) * NN_ + n4 * 4);
        s  += (v.x + v.y) + (v.z + v.w);
        s2 += (v.x * v.x + v.y * v.y) + (v.z * v.z + v.w * v.w);
    }
    __shared__ float ss[256], sq[256];
    ss[tid] = s; sq[tid] = s2;
    __syncthreads();
    for (int st = 128; st > 0; st >>= 1) {
        if (tid < st) { ss[tid] += ss[tid + st]; sq[tid] += sq[tid + st]; }
        __syncthreads();
    }
    if (tid == 0) {
        const float inv = 1.f / (float)(BB * NN_);
        const float mu  = ss[0] * inv;
        const float var = sq[0] * inv - mu * mu;
        const float a   = gamma[o] * rsqrtf(var + 1e-5f);
        ab[o]      = a;
        ab[CO + o] = beta[o] - mu * a;
    }
}

// ---------------- 4) GEMM layer 1 (BN0+ReLU applied on load) -------------
__global__ __launch_bounds__(256) void gemm1_kernel(const float* __restrict__ w1,
                                                    float* __restrict__ out) {
    __shared__ float Ws[KT][128];
    __shared__ float Xs[KT][132];
    __shared__ float sA[CO], sB[CO];

    const int bx = blockIdx.x;
    const int b  = bx >> 6;
    const int n0 = (bx & 63) << 7;
    const int o0 = blockIdx.y << 7;
    const int tid = threadIdx.x;
    const int tx = tid & 15, ty = tid >> 4;

    sA[tid] = g_ab0[tid];
    sB[tid] = g_ab0[CO + tid];

    float acc[8][8] = {};
    const float* yb = g_y0 + (size_t)b * CO * NN_ + n0;

    for (int k0 = 0; k0 < CO; k0 += KT) {
        __syncthreads();
        {
            const int o = tid >> 1;
            const int c = (tid & 1) << 3;
            const float4* wp = (const float4*)(w1 + (size_t)(o0 + o) * CO + k0 + c);
            float4 v0 = wp[0], v1 = wp[1];
            Ws[c + 0][o] = v0.x; Ws[c + 1][o] = v0.y; Ws[c + 2][o] = v0.z; Ws[c + 3][o] = v0.w;
            Ws[c + 4][o] = v1.x; Ws[c + 5][o] = v1.y; Ws[c + 6][o] = v1.z; Ws[c + 7][o] = v1.w;
        }
        {
            const int kk = tid >> 4;
            const int nn = (tid & 15) << 3;
            const int c = k0 + kk;
            const float a = sA[c], bb2 = sB[c];
            const float4* p = (const float4*)(yb + (size_t)c * NN_ + nn);
            float4 v0 = p[0], v1 = p[1];
            Xs[kk][nn + 0] = fmaxf(fmaf(a, v0.x, bb2), 0.f);
            Xs[kk][nn + 1] = fmaxf(fmaf(a, v0.y, bb2), 0.f);
            Xs[kk][nn + 2] = fmaxf(fmaf(a, v0.z, bb2), 0.f);
            Xs[kk][nn + 3] = fmaxf(fmaf(a, v0.w, bb2), 0.f);
            Xs[kk][nn + 4] = fmaxf(fmaf(a, v1.x, bb2), 0.f);
            Xs[kk][nn + 5] = fmaxf(fmaf(a, v1.y, bb2), 0.f);
            Xs[kk][nn + 6] = fmaxf(fmaf(a, v1.z, bb2), 0.f);
            Xs[kk][nn + 7] = fmaxf(fmaf(a, v1.w, bb2), 0.f);
        }
        __syncthreads();
#pragma unroll
        for (int kk = 0; kk < KT; kk++) {
            float a[8], x[8];
            *(float4*)&a[0] = *(const float4*)&Ws[kk][ty * 8];
            *(float4*)&a[4] = *(const float4*)&Ws[kk][ty * 8 + 4];
            *(float4*)&x[0] = *(const float4*)&Xs[kk][tx * 8];
            *(float4*)&x[4] = *(const float4*)&Xs[kk][tx * 8 + 4];
#pragma unroll
            for (int i = 0; i < 8; i++)
#pragma unroll
                for (int j = 0; j < 8; j++) acc[i][j] = fmaf(a[i], x[j], acc[i][j]);
        }
    }
#pragma unroll
    for (int i = 0; i < 8; i++) {
        float* dst = out + ((size_t)(b * CO + o0 + ty * 8 + i)) * NN_ + n0 + tx * 8;
        *(float4*)dst       = make_float4(acc[i][0], acc[i][1], acc[i][2], acc[i][3]);
        *(float4*)(dst + 4) = make_float4(acc[i][4], acc[i][5], acc[i][6], acc[i][7]);
    }
}

// ---------------- 5) final BN1 + ReLU in place on d_out ------------------
__global__ __launch_bounds__(256) void bnrelu_kernel(float* __restrict__ y) {
    const size_t i = ((size_t)blockIdx.x * blockDim.x + threadIdx.x) * 4;
    const int c = (int)((i >> 13) & (CO - 1));
    const float a = g_ab1[c], bb = g_ab1[CO + c];
    float4 v = *(float4*)(y + i);
    v.x = fmaxf(fmaf(a, v.x, bb), 0.f);
    v.y = fmaxf(fmaf(a, v.y, bb), 0.f);
    v.z = fmaxf(fmaf(a, v.z, bb), 0.f);
    v.w = fmaxf(fmaf(a, v.w, bb), 0.f);
    *(float4*)(y + i) = v;
}

// ---------------- launcher ------------------------------------------------
extern "C" void kernel_launch(void* const* d_in, const int* in_sizes, int n_in,
                              void* d_out, int out_size) {
    const float* xyz1   = (const float*)d_in[0];
    const float* xyz2   = (const float*)d_in[1];
    const float* f1     = (const float*)d_in[2];
    const float* f2     = (const float*)d_in[3];
    const float* w0     = (const float*)d_in[4];
    const float* gamma0 = (const float*)d_in[5];
    const float* beta0  = (const float*)d_in[6];
    const float* w1     = (const float*)d_in[7];
    const float* gamma1 = (const float*)d_in[8];
    const float* beta1  = (const float*)d_in[9];
    float* out = (float*)d_out;

    nn_kernel<<<dim3(NN_ / 256, BB), 128>>>(xyz1, xyz2);
    gemm0_kernel<<<dim3(BB * (NN_ / 128), CO / 128), 256>>>(f1, f2, w0);
    stats_kernel<true><<<CO, 256>>>(nullptr, gamma0, beta0);
    gemm1_kernel<<<dim3(BB * (NN_ / 128), CO / 128), 256>>>(w1, out);
    stats_kernel<false><<<CO, 256>>>(out, gamma1, beta1);
    bnrelu_kernel<<<(BB * CO * NN_) / (4 * 256), 256>>>(out);
}

// round 2
// speedup vs baseline: 1.0000x; 1.0000x over previous
#include <cuda_runtime.h>

#define BB 8
#define NN_ 8192
#define MM 2048
#define C1 128
#define C2 256
#define CIN 384
#define CO 256

typedef unsigned long long ull;

// ---------------- device scratch (no allocations allowed) ----------------
__device__ int   g_idx[BB * NN_];
__device__ float g_y0[(size_t)BB * CO * NN_];   // 64MB pre-BN output of layer 0
__device__ float g_ab0[2 * CO];                 // a,b affine for BN0
__device__ float g_ab1[2 * CO];                 // a,b affine for BN1

// ---------------- packed f32x2 helpers (IEEE-exact per lane) -------------
__device__ __forceinline__ ull f2_add(ull a, ull b) {
    ull r; asm("add.rn.f32x2 %0, %1, %2;" : "=l"(r) : "l"(a), "l"(b)); return r;
}
__device__ __forceinline__ ull f2_mul(ull a, ull b) {
    ull r; asm("mul.rn.f32x2 %0, %1, %2;" : "=l"(r) : "l"(a), "l"(b)); return r;
}
__device__ __forceinline__ ull f2_pack(float lo, float hi) {
    ull r; asm("mov.b64 %0, {%1, %2};" : "=l"(r) : "f"(lo), "f"(hi)); return r;
}
__device__ __forceinline__ void f2_unpack(float& lo, float& hi, ull v) {
    asm("mov.b64 {%0, %1}, %2;" : "=f"(lo), "=f"(hi) : "l"(v));
}

// ---------------- 1) nearest neighbor (exact, bitwise-matching) ----------
// d = ((px-qx)^2 + (py-qy)^2) + (pz-qz)^2, separate roundings (no FMA),
// matching XLA's mul-then-reduce semantics. Subtraction realized as
// px + (-qx) with negation done once in SMEM (exact).
// Grid: (N/256, B); 128 threads, 2 points per thread; even/odd m streams.
__global__ __launch_bounds__(128) void nn_kernel(const float* __restrict__ xyz1,
                                                 const float* __restrict__ xyz2) {
    __shared__ __align__(16) float nq[3][MM];  // negated xyz2, 24KB
    const int b  = blockIdx.y;
    const int n0 = blockIdx.x * 256;
    const int tid = threadIdx.x;

    const float* x2 = xyz2 + (size_t)b * MM * 3;
    for (int m = tid; m < MM; m += 128) {
        nq[0][m] = -x2[3 * m + 0];
        nq[1][m] = -x2[3 * m + 1];
        nq[2][m] = -x2[3 * m + 2];
    }
    __syncthreads();

    const ull* qx2 = (const ull*)nq[0];
    const ull* qy2 = (const ull*)nq[1];
    const ull* qz2 = (const ull*)nq[2];

    const int ng0 = n0 + tid;
    const int ng1 = n0 + tid + 128;
    const float* p0 = xyz1 + ((size_t)b * NN_ + ng0) * 3;
    const float* p1 = xyz1 + ((size_t)b * NN_ + ng1) * 3;

    const ull px0 = f2_pack(p0[0], p0[0]);
    const ull py0 = f2_pack(p0[1], p0[1]);
    const ull pz0 = f2_pack(p0[2], p0[2]);
    const ull px1 = f2_pack(p1[0], p1[0]);
    const ull py1 = f2_pack(p1[1], p1[1]);
    const ull pz1 = f2_pack(p1[2], p1[2]);

    float be0 = 3.0e38f, bo0 = 3.0e38f, be1 = 3.0e38f, bo1 = 3.0e38f;
    int   ie0 = 0, io0 = 1, ie1 = 0, io1 = 1;

#pragma unroll 4
    for (int m2 = 0; m2 < MM / 2; ++m2) {
        const ull qx = qx2[m2], qy = qy2[m2], qz = qz2[m2];
        {
            ull dx = f2_add(px0, qx), dy = f2_add(py0, qy), dz = f2_add(pz0, qz);
            ull d  = f2_add(f2_add(f2_mul(dx, dx), f2_mul(dy, dy)), f2_mul(dz, dz));
            float dl, dh; f2_unpack(dl, dh, d);
            if (dl < be0) { be0 = dl; ie0 = 2 * m2; }
            if (dh < bo0) { bo0 = dh; io0 = 2 * m2 + 1; }
        }
        {
            ull dx = f2_add(px1, qx), dy = f2_add(py1, qy), dz = f2_add(pz1, qz);
            ull d  = f2_add(f2_add(f2_mul(dx, dx), f2_mul(dy, dy)), f2_mul(dz, dz));
            float dl, dh; f2_unpack(dl, dh, d);
            if (dl < be1) { be1 = dl; ie1 = 2 * m2; }
            if (dh < bo1) { bo1 = dh; io1 = 2 * m2 + 1; }
        }
    }
    // combine even/odd streams with first-occurrence (lowest index) tie-break
    int bi0 = ie0;
    if (bo0 < be0 || (bo0 == be0 && io0 < ie0)) bi0 = io0;
    int bi1 = ie1;
    if (bo1 < be1 || (bo1 == be1 && io1 < ie1)) bi1 = io1;

    g_idx[b * NN_ + ng0] = bi0;
    g_idx[b * NN_ + ng1] = bi1;
}

// ---------------- 2) GEMM layer 0 (fused gather), writes raw y0 ----------
// y0[b,o,n] = sum_c W0[o,c] * x[b,c,n], x = concat(features1, gather(features2))
// Tiles: 128 out-ch x 128 points, K-step 16, 256 threads, 8x8 microtile.
#define KT 16
__global__ __launch_bounds__(256) void gemm0_kernel(const float* __restrict__ f1,
                                                    const float* __restrict__ f2,
                                                    const float* __restrict__ w0) {
    __shared__ float Ws[KT][128];
    __shared__ float Xs[KT][132];
    __shared__ int   sidx[128];

    const int bx = blockIdx.x;          // b * 64 + ntile
    const int b  = bx >> 6;
    const int n0 = (bx & 63) << 7;
    const int o0 = blockIdx.y << 7;
    const int tid = threadIdx.x;
    const int tx = tid & 15, ty = tid >> 4;

    if (tid < 128) sidx[tid] = g_idx[b * NN_ + n0 + tid];

    float acc[8][8] = {};
    const float* f1b = f1 + (size_t)b * C1 * NN_ + n0;
    const float* f2b = f2 + (size_t)b * C2 * MM;

    for (int k0 = 0; k0 < CIN; k0 += KT) {
        __syncthreads();
        // W tile: Ws[kk][o], coalesced read along CIN
        {
            const int o = tid >> 1;
            const int c = (tid & 1) << 3;
            const float4* wp = (const float4*)(w0 + (size_t)(o0 + o) * CIN + k0 + c);
            float4 v0 = wp[0], v1 = wp[1];
            Ws[c + 0][o] = v0.x; Ws[c + 1][o] = v0.y; Ws[c + 2][o] = v0.z; Ws[c + 3][o] = v0.w;
            Ws[c + 4][o] = v1.x; Ws[c + 5][o] = v1.y; Ws[c + 6][o] = v1.z; Ws[c + 7][o] = v1.w;
        }
        // X tile: Xs[kk][n]; rows < C1 coalesced from f1, rows >= C1 gathered
        {
            const int kk = tid >> 4;
            const int nn = (tid & 15) << 3;
            const int c = k0 + kk;
            if (c < C1) {
                const float4* p = (const float4*)(f1b + (size_t)c * NN_ + nn);
                float4 v0 = p[0], v1 = p[1];
                *(float4*)&Xs[kk][nn]     = v0;
                *(float4*)&Xs[kk][nn + 4] = v1;
            } else {
                const float* p = f2b + (size_t)(c - C1) * MM;
#pragma unroll
                for (int j = 0; j < 8; j++) Xs[kk][nn + j] = __ldg(p + sidx[nn + j]);
            }
        }
        __syncthreads();
#pragma unroll
        for (int kk = 0; kk < KT; kk++) {
            float a[8], x[8];
            *(float4*)&a[0] = *(const float4*)&Ws[kk][ty * 8];
            *(float4*)&a[4] = *(const float4*)&Ws[kk][ty * 8 + 4];
            *(float4*)&x[0] = *(const float4*)&Xs[kk][tx * 8];
            *(float4*)&x[4] = *(const float4*)&Xs[kk][tx * 8 + 4];
#pragma unroll
            for (int i = 0; i < 8; i++)
#pragma unroll
                for (int j = 0; j < 8; j++) acc[i][j] = fmaf(a[i], x[j], acc[i][j]);
        }
    }
#pragma unroll
    for (int i = 0; i < 8; i++) {
        float* dst = g_y0 + ((size_t)(b * CO + o0 + ty * 8 + i)) * NN_ + n0 + tx * 8;
        *(float4*)dst       = make_float4(acc[i][0], acc[i][1], acc[i][2], acc[i][3]);
        *(float4*)(dst + 4) = make_float4(acc[i][4], acc[i][5], acc[i][6], acc[i][7]);
    }
}

// ---------------- 3) per-channel BN stats (deterministic tree) -----------
template <bool FIRST>
__global__ __launch_bounds__(256) void stats_kernel(const float* __restrict__ yparam,
                                                    const float* __restrict__ gamma,
                                                    const float* __restrict__ beta) {
    const float* y = FIRST ? (const float*)g_y0 : yparam;
    float* ab = FIRST ? g_ab0 : g_ab1;
    const int o = blockIdx.x;
    const int tid = threadIdx.x;

    float s = 0.f, s2 = 0.f;
    for (int i4 = tid; i4 < (BB * NN_) / 4; i4 += 256) {
        const int bb = i4 >> 11;         // N/4 = 2048 vectors per batch
        const int n4 = i4 & 2047;
        const float4 v = *(const float4*)(y + ((size_t)(bb * CO + o)) * NN_ + n4 * 4);
        s  += (v.x + v.y) + (v.z + v.w);
        s2 += (v.x * v.x + v.y * v.y) + (v.z * v.z + v.w * v.w);
    }
    __shared__ float ss[256], sq[256];
    ss[tid] = s; sq[tid] = s2;
    __syncthreads();
    for (int st = 128; st > 0; st >>= 1) {
        if (tid < st) { ss[tid] += ss[tid + st]; sq[tid] += sq[tid + st]; }
        __syncthreads();
    }
    if (tid == 0) {
        const float inv = 1.f / (float)(BB * NN_);
        const float mu  = ss[0] * inv;
        const float var = sq[0] * inv - mu * mu;
        const float a   = gamma[o] * rsqrtf(var + 1e-5f);
        ab[o]      = a;
        ab[CO + o] = beta[o] - mu * a;
    }
}

// ---------------- 4) GEMM layer 1 (BN0+ReLU applied on load) -------------
__global__ __launch_bounds__(256) void gemm1_kernel(const float* __restrict__ w1,
                                                    float* __restrict__ out) {
    __shared__ float Ws[KT][128];
    __shared__ float Xs[KT][132];
    __shared__ float sA[CO], sB[CO];

    const int bx = blockIdx.x;
    const int b  = bx >> 6;
    const int n0 = (bx & 63) << 7;
    const int o0 = blockIdx.y << 7;
    const int tid = threadIdx.x;
    const int tx = tid & 15, ty = tid >> 4;

    sA[tid] = g_ab0[tid];
    sB[tid] = g_ab0[CO + tid];

    float acc[8][8] = {};
    const float* yb = g_y0 + (size_t)b * CO * NN_ + n0;

    for (int k0 = 0; k0 < CO; k0 += KT) {
        __syncthreads();
        {
            const int o = tid >> 1;
            const int c = (tid & 1) << 3;
            const float4* wp = (const float4*)(w1 + (size_t)(o0 + o) * CO + k0 + c);
            float4 v0 = wp[0], v1 = wp[1];
            Ws[c + 0][o] = v0.x; Ws[c + 1][o] = v0.y; Ws[c + 2][o] = v0.z; Ws[c + 3][o] = v0.w;
            Ws[c + 4][o] = v1.x; Ws[c + 5][o] = v1.y; Ws[c + 6][o] = v1.z; Ws[c + 7][o] = v1.w;
        }
        {
            const int kk = tid >> 4;
            const int nn = (tid & 15) << 3;
            const int c = k0 + kk;
            const float a = sA[c], bb2 = sB[c];
            const float4* p = (const float4*)(yb + (size_t)c * NN_ + nn);
            float4 v0 = p[0], v1 = p[1];
            Xs[kk][nn + 0] = fmaxf(fmaf(a, v0.x, bb2), 0.f);
            Xs[kk][nn + 1] = fmaxf(fmaf(a, v0.y, bb2), 0.f);
            Xs[kk][nn + 2] = fmaxf(fmaf(a, v0.z, bb2), 0.f);
            Xs[kk][nn + 3] = fmaxf(fmaf(a, v0.w, bb2), 0.f);
            Xs[kk][nn + 4] = fmaxf(fmaf(a, v1.x, bb2), 0.f);
            Xs[kk][nn + 5] = fmaxf(fmaf(a, v1.y, bb2), 0.f);
            Xs[kk][nn + 6] = fmaxf(fmaf(a, v1.z, bb2), 0.f);
            Xs[kk][nn + 7] = fmaxf(fmaf(a, v1.w, bb2), 0.f);
        }
        __syncthreads();
#pragma unroll
        for (int kk = 0; kk < KT; kk++) {
            float a[8], x[8];
            *(float4*)&a[0] = *(const float4*)&Ws[kk][ty * 8];
            *(float4*)&a[4] = *(const float4*)&Ws[kk][ty * 8 + 4];
            *(float4*)&x[0] = *(const float4*)&Xs[kk][tx * 8];
            *(float4*)&x[4] = *(const float4*)&Xs[kk][tx * 8 + 4];
#pragma unroll
            for (int i = 0; i < 8; i++)
#pragma unroll
                for (int j = 0; j < 8; j++) acc[i][j] = fmaf(a[i], x[j], acc[i][j]);
        }
    }
#pragma unroll
    for (int i = 0; i < 8; i++) {
        float* dst = out + ((size_t)(b * CO + o0 + ty * 8 + i)) * NN_ + n0 + tx * 8;
        *(float4*)dst       = make_float4(acc[i][0], acc[i][1], acc[i][2], acc[i][3]);
        *(float4*)(dst + 4) = make_float4(acc[i][4], acc[i][5], acc[i][6], acc[i][7]);
    }
}

// ---------------- 5) final BN1 + ReLU in place on d_out ------------------
__global__ __launch_bounds__(256) void bnrelu_kernel(float* __restrict__ y) {
    const size_t i = ((size_t)blockIdx.x * blockDim.x + threadIdx.x) * 4;
    const int c = (int)((i >> 13) & (CO - 1));
    const float a = g_ab1[c], bb = g_ab1[CO + c];
    float4 v = *(float4*)(y + i);
    v.x = fmaxf(fmaf(a, v.x, bb), 0.f);
    v.y = fmaxf(fmaf(a, v.y, bb), 0.f);
    v.z = fmaxf(fmaf(a, v.z, bb), 0.f);
    v.w = fmaxf(fmaf(a, v.w, bb), 0.f);
    *(float4*)(y + i) = v;
}

// ---------------- launcher ------------------------------------------------
extern "C" void kernel_launch(void* const* d_in, const int* in_sizes, int n_in,
                              void* d_out, int out_size) {
    const float* xyz1   = (const float*)d_in[0];
    const float* xyz2   = (const float*)d_in[1];
    const float* f1     = (const float*)d_in[2];
    const float* f2     = (const float*)d_in[3];
    const float* w0     = (const float*)d_in[4];
    const float* gamma0 = (const float*)d_in[5];
    const float* beta0  = (const float*)d_in[6];
    const float* w1     = (const float*)d_in[7];
    const float* gamma1 = (const float*)d_in[8];
    const float* beta1  = (const float*)d_in[9];
    float* out = (float*)d_out;

    nn_kernel<<<dim3(NN_ / 256, BB), 128>>>(xyz1, xyz2);
    gemm0_kernel<<<dim3(BB * (NN_ / 128), CO / 128), 256>>>(f1, f2, w0);
    stats_kernel<true><<<CO, 256>>>(nullptr, gamma0, beta0);
    gemm1_kernel<<<dim3(BB * (NN_ / 128), CO / 128), 256>>>(w1, out);
    stats_kernel<false><<<CO, 256>>>(out, gamma1, beta1);
    bnrelu_kernel<<<(BB * CO * NN_) / (4 * 256), 256>>>(out);
}

// round 5
// speedup vs baseline: 1.7083x; 1.7082x over previous
#include <cuda_runtime.h>
#include <cuda_bf16.h>
#include <cstdint>

#define BB 8
#define NN_ 8192
#define MM 2048
#define C1 128
#define C2 256
#define CIN 384
#define CO 256

typedef unsigned long long ull;
typedef __nv_bfloat16 bf16;

// ---------------- device scratch (no allocations allowed) ----------------
__device__ int   g_idx[BB * NN_];
__device__ float g_y0[(size_t)BB * CO * NN_];        // pre-BN output of layer 0 (64MB)
__device__ float g_ab0[2 * CO];
__device__ float g_ab1[2 * CO];
__device__ float g_f2t[(size_t)BB * MM * C2];        // f2 transposed [b][m][c2] (16MB)
__device__ bf16  g_w0hi[CO * CIN], g_w0lo[CO * CIN];
__device__ bf16  g_w1hi[CO * CO],  g_w1lo[CO * CO];
__device__ bf16  g_x0hi[(size_t)BB * NN_ * CIN];     // [b][n][384]
__device__ bf16  g_x0lo[(size_t)BB * NN_ * CIN];
__device__ bf16  g_x1hi[(size_t)BB * NN_ * CO];      // [b][n][256]
__device__ bf16  g_x1lo[(size_t)BB * NN_ * CO];

// ---------------- packed f32x2 helpers (exact per lane) ------------------
__device__ __forceinline__ ull f2_add(ull a, ull b) {
    ull r; asm("add.rn.f32x2 %0, %1, %2;" : "=l"(r) : "l"(a), "l"(b)); return r;
}
__device__ __forceinline__ ull f2_mul(ull a, ull b) {
    ull r; asm("mul.rn.f32x2 %0, %1, %2;" : "=l"(r) : "l"(a), "l"(b)); return r;
}
__device__ __forceinline__ ull f2_pack(float lo, float hi) {
    ull r; asm("mov.b64 %0, {%1, %2};" : "=l"(r) : "f"(lo), "f"(hi)); return r;
}
__device__ __forceinline__ void f2_unpack(float& lo, float& hi, ull v) {
    asm("mov.b64 {%0, %1}, %2;" : "=f"(lo), "=f"(hi) : "l"(v));
}
__device__ __forceinline__ uint32_t smem_u32(const void* p) {
    uint32_t a;
    asm("{ .reg .u64 t; cvta.to.shared.u64 t, %1; cvt.u32.u64 %0, t; }" : "=r"(a) : "l"(p));
    return a;
}
__device__ __forceinline__ void ldsm4(uint32_t& r0, uint32_t& r1, uint32_t& r2, uint32_t& r3,
                                      uint32_t addr) {
    asm volatile("ldmatrix.sync.aligned.m8n8.x4.shared.b16 {%0,%1,%2,%3}, [%4];"
                 : "=r"(r0), "=r"(r1), "=r"(r2), "=r"(r3) : "r"(addr));
}
__device__ __forceinline__ void mma16816(float* c, const uint32_t* a, const uint32_t* b) {
    asm volatile("mma.sync.aligned.m16n8k16.row.col.f32.bf16.bf16.f32 "
                 "{%0,%1,%2,%3}, {%4,%5,%6,%7}, {%8,%9}, {%0,%1,%2,%3};"
                 : "+f"(c[0]), "+f"(c[1]), "+f"(c[2]), "+f"(c[3])
                 : "r"(a[0]), "r"(a[1]), "r"(a[2]), "r"(a[3]), "r"(b[0]), "r"(b[1]));
}

// ---------------- 1) nearest neighbor (bitwise-matching argmin) ----------
__global__ __launch_bounds__(128) void nn_kernel(const float* __restrict__ xyz1,
                                                 const float* __restrict__ xyz2) {
    __shared__ __align__(16) float nq[3][MM];
    const int b  = blockIdx.y;
    const int n0 = blockIdx.x * 256;
    const int tid = threadIdx.x;

    const float* x2 = xyz2 + (size_t)b * MM * 3;
    for (int m = tid; m < MM; m += 128) {
        nq[0][m] = -x2[3 * m + 0];
        nq[1][m] = -x2[3 * m + 1];
        nq[2][m] = -x2[3 * m + 2];
    }
    __syncthreads();

    const ull* qx2 = (const ull*)nq[0];
    const ull* qy2 = (const ull*)nq[1];
    const ull* qz2 = (const ull*)nq[2];

    const int ng0 = n0 + tid;
    const int ng1 = n0 + tid + 128;
    const float* p0 = xyz1 + ((size_t)b * NN_ + ng0) * 3;
    const float* p1 = xyz1 + ((size_t)b * NN_ + ng1) * 3;

    const ull px0 = f2_pack(p0[0], p0[0]), py0 = f2_pack(p0[1], p0[1]), pz0 = f2_pack(p0[2], p0[2]);
    const ull px1 = f2_pack(p1[0], p1[0]), py1 = f2_pack(p1[1], p1[1]), pz1 = f2_pack(p1[2], p1[2]);

    float be0 = 3.0e38f, bo0 = 3.0e38f, be1 = 3.0e38f, bo1 = 3.0e38f;
    int   ie0 = 0, io0 = 1, ie1 = 0, io1 = 1;

#pragma unroll 4
    for (int m2 = 0; m2 < MM / 2; ++m2) {
        const ull qx = qx2[m2], qy = qy2[m2], qz = qz2[m2];
        {
            ull dx = f2_add(px0, qx), dy = f2_add(py0, qy), dz = f2_add(pz0, qz);
            ull d  = f2_add(f2_add(f2_mul(dx, dx), f2_mul(dy, dy)), f2_mul(dz, dz));
            float dl, dh; f2_unpack(dl, dh, d);
            if (dl < be0) { be0 = dl; ie0 = 2 * m2; }
            if (dh < bo0) { bo0 = dh; io0 = 2 * m2 + 1; }
        }
        {
            ull dx = f2_add(px1, qx), dy = f2_add(py1, qy), dz = f2_add(pz1, qz);
            ull d  = f2_add(f2_add(f2_mul(dx, dx), f2_mul(dy, dy)), f2_mul(dz, dz));
            float dl, dh; f2_unpack(dl, dh, d);
            if (dl < be1) { be1 = dl; ie1 = 2 * m2; }
            if (dh < bo1) { bo1 = dh; io1 = 2 * m2 + 1; }
        }
    }
    int bi0 = ie0;
    if (bo0 < be0 || (bo0 == be0 && io0 < ie0)) bi0 = io0;
    int bi1 = ie1;
    if (bo1 < be1 || (bo1 == be1 && io1 < ie1)) bi1 = io1;

    g_idx[b * NN_ + ng0] = bi0;
    g_idx[b * NN_ + ng1] = bi1;
}

// ---------------- hi/lo bf16 split helper ---------------------------------
__device__ __forceinline__ void split2(float v0, float v1, uint32_t& hi, uint32_t& lo) {
    bf16 h0 = __float2bfloat16(v0), h1 = __float2bfloat16(v1);
    bf16 l0 = __float2bfloat16(v0 - __bfloat162float(h0));
    bf16 l1 = __float2bfloat16(v1 - __bfloat162float(h1));
    __nv_bfloat162 hp(h0, h1), lp(l0, l1);
    hi = *(uint32_t*)&hp; lo = *(uint32_t*)&lp;
}

// ---------------- 2) weight split ----------------------------------------
__global__ __launch_bounds__(256) void prep_w(const float* __restrict__ w0,
                                              const float* __restrict__ w1) {
    const int i = blockIdx.x * 256 + threadIdx.x;
    if (i < CO * CIN) {
        float v = w0[i];
        bf16 h = __float2bfloat16(v);
        g_w0hi[i] = h;
        g_w0lo[i] = __float2bfloat16(v - __bfloat162float(h));
    }
    if (i < CO * CO) {
        float v = w1[i];
        bf16 h = __float2bfloat16(v);
        g_w1hi[i] = h;
        g_w1lo[i] = __float2bfloat16(v - __bfloat162float(h));
    }
}

// ---------------- 3) transpose f2 -> [b][m][c2] ---------------------------
__global__ void prep_f2t(const float* __restrict__ f2) {
    __shared__ float t[32][33];
    const int b = blockIdx.z, m0 = blockIdx.x * 32, c0 = blockIdx.y * 32;
    const int tx = threadIdx.x, ty = threadIdx.y;  // 32x8
#pragma unroll
    for (int k = 0; k < 4; k++)
        t[ty + 8 * k][tx] = f2[((size_t)(b * C2) + c0 + ty + 8 * k) * MM + m0 + tx];
    __syncthreads();
#pragma unroll
    for (int k = 0; k < 4; k++)
        g_f2t[((size_t)(b * MM) + m0 + ty + 8 * k) * C2 + c0 + tx] = t[tx][ty + 8 * k];
}

// ---------------- 4) build X0 hi/lo [b][n][384] (transpose + gather) ------
__global__ __launch_bounds__(256) void prep_x0(const float* __restrict__ f1) {
    __shared__ float sA[128][65];
    __shared__ int sidx[64];
    const int b = blockIdx.y, n0 = blockIdx.x * 64;
    const int tid = threadIdx.x, wid = tid >> 5, lane = tid & 31;

    if (tid < 64) sidx[tid] = g_idx[b * NN_ + n0 + tid];
    for (int i = tid; i < 128 * 64; i += 256) {
        const int c = i >> 6, j = i & 63;
        sA[c][j] = f1[((size_t)(b * C1 + c)) * NN_ + n0 + j];
    }
    __syncthreads();

    for (int jj = wid; jj < 64; jj += 8) {
        const size_t ob = ((size_t)(b * NN_) + n0 + jj) * CIN;
#pragma unroll
        for (int t = 0; t < 2; t++) {
            const int c = (t * 32 + lane) * 2;
            uint32_t hi, lo;
            split2(sA[c][jj], sA[c + 1][jj], hi, lo);
            *(uint32_t*)(g_x0hi + ob + c) = hi;
            *(uint32_t*)(g_x0lo + ob + c) = lo;
        }
        const float2* src = (const float2*)(g_f2t + ((size_t)(b * MM) + sidx[jj]) * C2);
#pragma unroll
        for (int t = 0; t < 4; t++) {
            const float2 v = src[t * 32 + lane];
            uint32_t hi, lo;
            split2(v.x, v.y, hi, lo);
            const int c = C1 + (t * 32 + lane) * 2;
            *(uint32_t*)(g_x0hi + ob + c) = hi;
            *(uint32_t*)(g_x0lo + ob + c) = lo;
        }
    }
}

// ---------------- 5) HMMA GEMM: Y[o][n] = W[o][:] . X[n][:] ---------------
// CTA tile 128(o) x 128(n), 8 warps (4 o-rows x 2 n-cols), warp tile 32x64.
// 3-MMA hi/lo split: Whi*Xhi + Whi*Xlo + Wlo*Xhi (fp32 accumulate).
// LAYER selects device-global scratch INSIDE device code (host cannot take
// the address of __device__ globals — that was the R3 bug). Layer-0 output
// also resolved in device code (Y arg used only for layer 1 = d_out).
#define PADK 72          // bf16 elements per smem row (64 + 8 pad), 144B stride
#define TILE_B (128 * PADK * 2)

template <int LAYER>
__global__ __launch_bounds__(256) void gemm_mma(float* __restrict__ Yarg) {
    constexpr int KDIM = (LAYER == 0) ? CIN : CO;
    const bf16* __restrict__ Xhi = (LAYER == 0) ? g_x0hi : g_x1hi;
    const bf16* __restrict__ Xlo = (LAYER == 0) ? g_x0lo : g_x1lo;
    const bf16* __restrict__ Whi = (LAYER == 0) ? g_w0hi : g_w1hi;
    const bf16* __restrict__ Wlo = (LAYER == 0) ? g_w0lo : g_w1lo;
    float* __restrict__ Y = (LAYER == 0) ? g_y0 : Yarg;

    extern __shared__ __align__(16) char smem[];
    bf16* sWhi = (bf16*)(smem);
    bf16* sWlo = (bf16*)(smem + TILE_B);
    bf16* sXhi = (bf16*)(smem + 2 * TILE_B);
    bf16* sXlo = (bf16*)(smem + 3 * TILE_B);

    const int tid = threadIdx.x, wid = tid >> 5, lane = tid & 31;
    const int b  = blockIdx.x >> 6;
    const int n0 = (blockIdx.x & 63) << 7;
    const int o0 = blockIdx.y << 7;
    const size_t xrow0 = (size_t)(b * NN_) + n0;

    const int warp_o = (wid & 3) * 32;   // o offset within tile
    const int warp_n = (wid >> 2) * 64;  // n offset within tile

    const int arow = warp_o + (lane & 15);
    const int acol = (lane >> 4) * 8;
    const int brow = warp_n + (lane & 7) + ((lane >> 4) << 3);
    const int bcol = ((lane >> 3) & 1) * 8;

    const uint32_t sb = smem_u32(smem);
    const uint32_t aWhi = sb + (arow * PADK + acol) * 2;
    const uint32_t aWlo = aWhi + TILE_B;
    const uint32_t aXhi = sb + 2 * TILE_B + (brow * PADK + bcol) * 2;
    const uint32_t aXlo = aXhi + TILE_B;

    float acc[2][8][4] = {};

    for (int k0 = 0; k0 < KDIM; k0 += 64) {
        __syncthreads();
#pragma unroll
        for (int it = 0; it < 4; ++it) {
            const int i = tid + it * 256;
            const int row = i >> 3, seg = i & 7;
            const int so = row * PADK + seg * 8;
            const size_t wk = (size_t)(o0 + row) * KDIM + k0 + seg * 8;
            const size_t xk = (xrow0 + row) * KDIM + k0 + seg * 8;
            *(uint4*)(sWhi + so) = *(const uint4*)(Whi + wk);
            *(uint4*)(sWlo + so) = *(const uint4*)(Wlo + wk);
            *(uint4*)(sXhi + so) = *(const uint4*)(Xhi + xk);
            *(uint4*)(sXlo + so) = *(const uint4*)(Xlo + xk);
        }
        __syncthreads();

#pragma unroll
        for (int kk = 0; kk < 4; ++kk) {
            const uint32_t koff = kk * 32;  // 16 bf16 = 32 bytes
            uint32_t ah[2][4], al[2][4];
#pragma unroll
            for (int t = 0; t < 2; ++t) {
                const uint32_t ro = t * 16 * PADK * 2 + koff;
                ldsm4(ah[t][0], ah[t][1], ah[t][2], ah[t][3], aWhi + ro);
                ldsm4(al[t][0], al[t][1], al[t][2], al[t][3], aWlo + ro);
            }
            uint32_t bh[4][4], bl[4][4];
#pragma unroll
            for (int u = 0; u < 4; ++u) {
                const uint32_t ro = u * 16 * PADK * 2 + koff;
                ldsm4(bh[u][0], bh[u][1], bh[u][2], bh[u][3], aXhi + ro);
                ldsm4(bl[u][0], bl[u][1], bl[u][2], bl[u][3], aXlo + ro);
            }
#pragma unroll
            for (int t = 0; t < 2; ++t)
#pragma unroll
                for (int j = 0; j < 8; ++j) {
                    const uint32_t* ph = &bh[j >> 1][(j & 1) * 2];
                    const uint32_t* pl = &bl[j >> 1][(j & 1) * 2];
                    mma16816(acc[t][j], ah[t], ph);
                    mma16816(acc[t][j], ah[t], pl);
                    mma16816(acc[t][j], al[t], ph);
                }
        }
    }

    const int orow = o0 + warp_o + (lane >> 2);
    const int ncol = n0 + warp_n + (lane & 3) * 2;
#pragma unroll
    for (int t = 0; t < 2; ++t) {
        float* d0 = Y + ((size_t)(b * CO) + orow + t * 16) * NN_ + ncol;
        float* d1 = d0 + 8 * NN_;
#pragma unroll
        for (int j = 0; j < 8; ++j) {
            *(float2*)(d0 + j * 8) = make_float2(acc[t][j][0], acc[t][j][1]);
            *(float2*)(d1 + j * 8) = make_float2(acc[t][j][2], acc[t][j][3]);
        }
    }
}

// ---------------- 6) per-channel BN stats (deterministic tree) -----------
template <bool FIRST>
__global__ __launch_bounds__(256) void stats_kernel(const float* __restrict__ yparam,
                                                    const float* __restrict__ gamma,
                                                    const float* __restrict__ beta) {
    const float* y = FIRST ? (const float*)g_y0 : yparam;
    float* ab = FIRST ? g_ab0 : g_ab1;
    const int o = blockIdx.x;
    const int tid = threadIdx.x;

    float s = 0.f, s2 = 0.f;
    for (int i4 = tid; i4 < (BB * NN_) / 4; i4 += 256) {
        const int bb = i4 >> 11;
        const int n4 = i4 & 2047;
        const float4 v = *(const float4*)(y + ((size_t)(bb * CO + o)) * NN_ + n4 * 4);
        s  += (v.x + v.y) + (v.z + v.w);
        s2 += (v.x * v.x + v.y * v.y) + (v.z * v.z + v.w * v.w);
    }
    __shared__ float ss[256], sq[256];
    ss[tid] = s; sq[tid] = s2;
    __syncthreads();
    for (int st = 128; st > 0; st >>= 1) {
        if (tid < st) { ss[tid] += ss[tid + st]; sq[tid] += sq[tid + st]; }
        __syncthreads();
    }
    if (tid == 0) {
        const float inv = 1.f / (float)(BB * NN_);
        const float mu  = ss[0] * inv;
        const float var = sq[0] * inv - mu * mu;
        const float a   = gamma[o] * rsqrtf(var + 1e-5f);
        ab[o]      = a;
        ab[CO + o] = beta[o] - mu * a;
    }
}

// ---------------- 7) build X1 hi/lo [b][n][256] = bn0+relu(y0)^T ----------
__global__ __launch_bounds__(256) void prep_x1() {
    __shared__ float sA[128][65];
    __shared__ float cA[CO], cB[CO];
    const int b = blockIdx.y, n0 = blockIdx.x * 64;
    const int tid = threadIdx.x, wid = tid >> 5, lane = tid & 31;

    cA[tid] = g_ab0[tid];
    cB[tid] = g_ab0[CO + tid];
    __syncthreads();

    for (int half = 0; half < 2; ++half) {
        for (int i = tid; i < 128 * 64; i += 256) {
            const int ol = i >> 6, j = i & 63;
            const int o = half * 128 + ol;
            const float v = g_y0[((size_t)(b * CO + o)) * NN_ + n0 + j];
            sA[ol][j] = fmaxf(fmaf(cA[o], v, cB[o]), 0.f);
        }
        __syncthreads();
        for (int jj = wid; jj < 64; jj += 8) {
            const size_t ob = ((size_t)(b * NN_) + n0 + jj) * CO + half * 128;
#pragma unroll
            for (int t = 0; t < 2; t++) {
                const int c = (t * 32 + lane) * 2;
                uint32_t hi, lo;
                split2(sA[c][jj], sA[c + 1][jj], hi, lo);
                *(uint32_t*)(g_x1hi + ob + c) = hi;
                *(uint32_t*)(g_x1lo + ob + c) = lo;
            }
        }
        __syncthreads();
    }
}

// ---------------- 8) final BN1 + ReLU in place on d_out ------------------
__global__ __launch_bounds__(256) void bnrelu_kernel(float* __restrict__ y) {
    const size_t i = ((size_t)blockIdx.x * blockDim.x + threadIdx.x) * 4;
    const int c = (int)((i >> 13) & (CO - 1));
    const float a = g_ab1[c], bb = g_ab1[CO + c];
    float4 v = *(float4*)(y + i);
    v.x = fmaxf(fmaf(a, v.x, bb), 0.f);
    v.y = fmaxf(fmaf(a, v.y, bb), 0.f);
    v.z = fmaxf(fmaf(a, v.z, bb), 0.f);
    v.w = fmaxf(fmaf(a, v.w, bb), 0.f);
    *(float4*)(y + i) = v;
}

// ---------------- launcher ------------------------------------------------
#define GEMM_SMEM (4 * TILE_B)   // 73728 B

extern "C" void kernel_launch(void* const* d_in, const int* in_sizes, int n_in,
                              void* d_out, int out_size) {
    const float* xyz1   = (const float*)d_in[0];
    const float* xyz2   = (const float*)d_in[1];
    const float* f1     = (const float*)d_in[2];
    const float* f2     = (const float*)d_in[3];
    const float* w0     = (const float*)d_in[4];
    const float* gamma0 = (const float*)d_in[5];
    const float* beta0  = (const float*)d_in[6];
    const float* w1     = (const float*)d_in[7];
    const float* gamma1 = (const float*)d_in[8];
    const float* beta1  = (const float*)d_in[9];
    float* out = (float*)d_out;

    cudaFuncSetAttribute(gemm_mma<0>, cudaFuncAttributeMaxDynamicSharedMemorySize, GEMM_SMEM);
    cudaFuncSetAttribute(gemm_mma<1>, cudaFuncAttributeMaxDynamicSharedMemorySize, GEMM_SMEM);

    nn_kernel<<<dim3(NN_ / 256, BB), 128>>>(xyz1, xyz2);
    prep_w<<<(CO * CIN + 255) / 256, 256>>>(w0, w1);
    prep_f2t<<<dim3(MM / 32, C2 / 32, BB), dim3(32, 8)>>>(f2);
    prep_x0<<<dim3(NN_ / 64, BB), 256>>>(f1);

    gemm_mma<0><<<dim3(BB * (NN_ / 128), CO / 128), 256, GEMM_SMEM>>>(nullptr);

    stats_kernel<true><<<CO, 256>>>(nullptr, gamma0, beta0);
    prep_x1<<<dim3(NN_ / 64, BB), 256>>>();

    gemm_mma<1><<<dim3(BB * (NN_ / 128), CO / 128), 256, GEMM_SMEM>>>(out);

    stats_kernel<false><<<CO, 256>>>(out, gamma1, beta1);
    bnrelu_kernel<<<(BB * CO * NN_) / (4 * 256), 256>>>(out);
}

// round 6
// speedup vs baseline: 1.8763x; 1.0983x over previous
#include <cuda_runtime.h>
#include <cuda_bf16.h>
#include <cstdint>

#define BB 8
#define NN_ 8192
#define MM 2048
#define C1 128
#define C2 256
#define CIN 384
#define CO 256
#define NBX 512            // BB * (NN_/128) gemm n-tiles

typedef unsigned long long ull;
typedef __nv_bfloat16 bf16;

// ---------------- device scratch (no allocations allowed) ----------------
__device__ int   g_idx[BB * NN_];
__device__ float g_y0[(size_t)BB * CO * NN_];        // pre-BN output of layer 0 (64MB)
__device__ float g_ab0[2 * CO];
__device__ float g_ab1[2 * CO];
__device__ float g_f2t[(size_t)BB * MM * C2];        // f2 transposed [b][m][c2]
__device__ bf16  g_w0hi[CO * CIN], g_w0lo[CO * CIN];
__device__ bf16  g_w1hi[CO * CO],  g_w1lo[CO * CO];
__device__ bf16  g_x0hi[(size_t)BB * NN_ * CIN];     // [b][n][384]
__device__ bf16  g_x0lo[(size_t)BB * NN_ * CIN];
__device__ float g_psum[CO * NBX];                   // per-(channel, CTA) partial sums
__device__ float g_psq[CO * NBX];

// ---------------- helpers -------------------------------------------------
__device__ __forceinline__ ull f2_add(ull a, ull b) {
    ull r; asm("add.rn.f32x2 %0, %1, %2;" : "=l"(r) : "l"(a), "l"(b)); return r;
}
__device__ __forceinline__ ull f2_mul(ull a, ull b) {
    ull r; asm("mul.rn.f32x2 %0, %1, %2;" : "=l"(r) : "l"(a), "l"(b)); return r;
}
__device__ __forceinline__ ull f2_pack(float lo, float hi) {
    ull r; asm("mov.b64 %0, {%1, %2};" : "=l"(r) : "f"(lo), "f"(hi)); return r;
}
__device__ __forceinline__ void f2_unpack(float& lo, float& hi, ull v) {
    asm("mov.b64 {%0, %1}, %2;" : "=f"(lo), "=f"(hi) : "l"(v));
}
__device__ __forceinline__ uint32_t smem_u32(const void* p) {
    uint32_t a;
    asm("{ .reg .u64 t; cvta.to.shared.u64 t, %1; cvt.u32.u64 %0, t; }" : "=r"(a) : "l"(p));
    return a;
}
__device__ __forceinline__ void ldsm4(uint32_t& r0, uint32_t& r1, uint32_t& r2, uint32_t& r3,
                                      uint32_t addr) {
    asm volatile("ldmatrix.sync.aligned.m8n8.x4.shared.b16 {%0,%1,%2,%3}, [%4];"
                 : "=r"(r0), "=r"(r1), "=r"(r2), "=r"(r3) : "r"(addr));
}
__device__ __forceinline__ void ldsm4t(uint32_t& r0, uint32_t& r1, uint32_t& r2, uint32_t& r3,
                                       uint32_t addr) {
    asm volatile("ldmatrix.sync.aligned.m8n8.x4.trans.shared.b16 {%0,%1,%2,%3}, [%4];"
                 : "=r"(r0), "=r"(r1), "=r"(r2), "=r"(r3) : "r"(addr));
}
__device__ __forceinline__ void mma16816(float* c, const uint32_t* a, const uint32_t* b) {
    asm volatile("mma.sync.aligned.m16n8k16.row.col.f32.bf16.bf16.f32 "
                 "{%0,%1,%2,%3}, {%4,%5,%6,%7}, {%8,%9}, {%0,%1,%2,%3};"
                 : "+f"(c[0]), "+f"(c[1]), "+f"(c[2]), "+f"(c[3])
                 : "r"(a[0]), "r"(a[1]), "r"(a[2]), "r"(a[3]), "r"(b[0]), "r"(b[1]));
}
__device__ __forceinline__ void split2(float v0, float v1, uint32_t& hi, uint32_t& lo) {
    bf16 h0 = __float2bfloat16(v0), h1 = __float2bfloat16(v1);
    bf16 l0 = __float2bfloat16(v0 - __bfloat162float(h0));
    bf16 l1 = __float2bfloat16(v1 - __bfloat162float(h1));
    __nv_bfloat162 hp(h0, h1), lp(l0, l1);
    hi = *(uint32_t*)&hp; lo = *(uint32_t*)&lp;
}

// ---------------- 1) nearest neighbor (bitwise-matching argmin) ----------
// Updates via ternaries -> FSETP + FSEL/SEL (pred-as-data, 4cyc) instead of
// @P guarded moves (13cyc). 256 threads, 1 point/thread, even/odd m streams.
__global__ __launch_bounds__(256) void nn_kernel(const float* __restrict__ xyz1,
                                                 const float* __restrict__ xyz2) {
    __shared__ __align__(16) float nq[3][MM];
    const int b  = blockIdx.y;
    const int n0 = blockIdx.x * 256;
    const int tid = threadIdx.x;

    const float* x2 = xyz2 + (size_t)b * MM * 3;
    for (int m = tid; m < MM; m += 256) {
        nq[0][m] = -x2[3 * m + 0];
        nq[1][m] = -x2[3 * m + 1];
        nq[2][m] = -x2[3 * m + 2];
    }
    __syncthreads();

    const ull* qx2 = (const ull*)nq[0];
    const ull* qy2 = (const ull*)nq[1];
    const ull* qz2 = (const ull*)nq[2];

    const int ng = n0 + tid;
    const float* p = xyz1 + ((size_t)b * NN_ + ng) * 3;
    const ull px = f2_pack(p[0], p[0]), py = f2_pack(p[1], p[1]), pz = f2_pack(p[2], p[2]);

    float be = 3.0e38f, bo = 3.0e38f;
    int   ie = 0, io = 1;

#pragma unroll 8
    for (int m2 = 0; m2 < MM / 2; ++m2) {
        const ull qx = qx2[m2], qy = qy2[m2], qz = qz2[m2];
        ull dx = f2_add(px, qx), dy = f2_add(py, qy), dz = f2_add(pz, qz);
        ull d  = f2_add(f2_add(f2_mul(dx, dx), f2_mul(dy, dy)), f2_mul(dz, dz));
        float dl, dh; f2_unpack(dl, dh, d);
        const bool pe = dl < be;
        const bool po = dh < bo;
        be = pe ? dl : be;
        ie = pe ? 2 * m2 : ie;
        bo = po ? dh : bo;
        io = po ? 2 * m2 + 1 : io;
    }
    int bi = ie;
    if (bo < be || (bo == be && io < ie)) bi = io;
    g_idx[b * NN_ + ng] = bi;
}

// ---------------- 2) weight split ----------------------------------------
__global__ __launch_bounds__(256) void prep_w(const float* __restrict__ w0,
                                              const float* __restrict__ w1) {
    const int i = blockIdx.x * 256 + threadIdx.x;
    if (i < CO * CIN) {
        float v = w0[i];
        bf16 h = __float2bfloat16(v);
        g_w0hi[i] = h;
        g_w0lo[i] = __float2bfloat16(v - __bfloat162float(h));
    }
    if (i < CO * CO) {
        float v = w1[i];
        bf16 h = __float2bfloat16(v);
        g_w1hi[i] = h;
        g_w1lo[i] = __float2bfloat16(v - __bfloat162float(h));
    }
}

// ---------------- 3) transpose f2 -> [b][m][c2] ---------------------------
__global__ void prep_f2t(const float* __restrict__ f2) {
    __shared__ float t[32][33];
    const int b = blockIdx.z, m0 = blockIdx.x * 32, c0 = blockIdx.y * 32;
    const int tx = threadIdx.x, ty = threadIdx.y;  // 32x8
#pragma unroll
    for (int k = 0; k < 4; k++)
        t[ty + 8 * k][tx] = f2[((size_t)(b * C2) + c0 + ty + 8 * k) * MM + m0 + tx];
    __syncthreads();
#pragma unroll
    for (int k = 0; k < 4; k++)
        g_f2t[((size_t)(b * MM) + m0 + ty + 8 * k) * C2 + c0 + tx] = t[tx][ty + 8 * k];
}

// ---------------- 4) build X0 hi/lo [b][n][384] (transpose + gather) ------
__global__ __launch_bounds__(256) void prep_x0(const float* __restrict__ f1) {
    __shared__ float sA[128][65];
    __shared__ int sidx[64];
    const int b = blockIdx.y, n0 = blockIdx.x * 64;
    const int tid = threadIdx.x, wid = tid >> 5, lane = tid & 31;

    if (tid < 64) sidx[tid] = g_idx[b * NN_ + n0 + tid];
    for (int i = tid; i < 128 * 64; i += 256) {
        const int c = i >> 6, j = i & 63;
        sA[c][j] = f1[((size_t)(b * C1 + c)) * NN_ + n0 + j];
    }
    __syncthreads();

    for (int jj = wid; jj < 64; jj += 8) {
        const size_t ob = ((size_t)(b * NN_) + n0 + jj) * CIN;
#pragma unroll
        for (int t = 0; t < 2; t++) {
            const int c = (t * 32 + lane) * 2;
            uint32_t hi, lo;
            split2(sA[c][jj], sA[c + 1][jj], hi, lo);
            *(uint32_t*)(g_x0hi + ob + c) = hi;
            *(uint32_t*)(g_x0lo + ob + c) = lo;
        }
        const float2* src = (const float2*)(g_f2t + ((size_t)(b * MM) + sidx[jj]) * C2);
#pragma unroll
        for (int t = 0; t < 4; t++) {
            const float2 v = src[t * 32 + lane];
            uint32_t hi, lo;
            split2(v.x, v.y, hi, lo);
            const int c = C1 + (t * 32 + lane) * 2;
            *(uint32_t*)(g_x0hi + ob + c) = hi;
            *(uint32_t*)(g_x0lo + ob + c) = lo;
        }
    }
}

// ---------------- 5) HMMA GEMM + fused stats partials ---------------------
// CTA 128(o) x 128(n), 8 warps (4 o x 2 n), warp tile 32x64.
// 3-MMA hi/lo split. LAYER 0: X from prep_x0 bf16 buffers ([n][k], non-trans
// ldmatrix). LAYER 1: X built on the fly from y0 (BN0 affine + ReLU + split,
// k-major smem, trans ldmatrix) — prep_x1 eliminated.
// Epilogue: deterministic per-CTA (sum, sumsq) partials per channel.
#define PADK 72
#define PADN 136
#define W_TILE_B  (128 * PADK * 2)          // 18432
#define XT_OFF    (2 * W_TILE_B)            // 36864
#define XT_TILE_B (64 * PADN * 2)           // 17408
#define AFF_OFF   (XT_OFF + 2 * XT_TILE_B)  // 71680
#define GEMM_SMEM (AFF_OFF + 2048)          // 73728 (layer0 uses 4*18432 = same)

template <int LAYER>
__global__ __launch_bounds__(256) void gemm_mma(float* __restrict__ Yarg) {
    constexpr int KDIM = (LAYER == 0) ? CIN : CO;
    const bf16* __restrict__ Whi = (LAYER == 0) ? g_w0hi : g_w1hi;
    const bf16* __restrict__ Wlo = (LAYER == 0) ? g_w0lo : g_w1lo;
    float* __restrict__ Y = (LAYER == 0) ? g_y0 : Yarg;

    extern __shared__ __align__(16) char smem[];
    bf16* sWhi = (bf16*)(smem);
    bf16* sWlo = (bf16*)(smem + W_TILE_B);
    // layer0 X tiles ([n][PADK]):
    bf16* sXhi = (bf16*)(smem + 2 * W_TILE_B);
    bf16* sXlo = (bf16*)(smem + 3 * W_TILE_B);
    // layer1 Xt tiles ([k][PADN]):
    bf16* sXthi = (bf16*)(smem + XT_OFF);
    bf16* sXtlo = (bf16*)(smem + XT_OFF + XT_TILE_B);
    float* sAff  = (float*)(smem + AFF_OFF);
    float* sBeta = sAff + 256;

    const int tid = threadIdx.x, wid = tid >> 5, lane = tid & 31;
    const int bx = blockIdx.x;
    const int b  = bx >> 6;
    const int n0 = (bx & 63) << 7;
    const int o0 = blockIdx.y << 7;
    const size_t xrow0 = (size_t)(b * NN_) + n0;

    const int warp_o = (wid & 3) * 32;
    const int warp_n = (wid >> 2) * 64;

    const uint32_t sb = smem_u32(smem);
    // A (W) fragment addresses (same both layers)
    const int arow = warp_o + (lane & 15);
    const int acol = (lane >> 4) * 8;
    const uint32_t aWhi = sb + (arow * PADK + acol) * 2;
    const uint32_t aWlo = aWhi + W_TILE_B;
    // B fragment addresses
    const int brow = warp_n + (lane & 7) + ((lane >> 4) << 3);   // layer0 (n-major)
    const int bcol = ((lane >> 3) & 1) * 8;
    const uint32_t aXhi = sb + 2 * W_TILE_B + (brow * PADK + bcol) * 2;
    const uint32_t aXlo = aXhi + W_TILE_B;
    const int krow = (lane & 7) + ((lane >> 3) & 1) * 8;          // layer1 (k-major, trans)
    const int noff = warp_n + ((lane >> 4) & 1) * 8;
    const uint32_t aXthi = sb + XT_OFF + (krow * PADN + noff) * 2;
    const uint32_t aXtlo = aXthi + XT_TILE_B;

    if (LAYER == 1) {
        sAff[tid]  = g_ab0[tid];
        sBeta[tid] = g_ab0[CO + tid];
    }

    float acc[2][8][4] = {};

    for (int k0 = 0; k0 < KDIM; k0 += 64) {
        __syncthreads();
        // W tiles
#pragma unroll
        for (int it = 0; it < 4; ++it) {
            const int i = tid + it * 256;
            const int row = i >> 3, seg = i & 7;
            const int so = row * PADK + seg * 8;
            const size_t wk = (size_t)(o0 + row) * KDIM + k0 + seg * 8;
            *(uint4*)(sWhi + so) = *(const uint4*)(Whi + wk);
            *(uint4*)(sWlo + so) = *(const uint4*)(Wlo + wk);
        }
        if (LAYER == 0) {
#pragma unroll
            for (int it = 0; it < 4; ++it) {
                const int i = tid + it * 256;
                const int row = i >> 3, seg = i & 7;
                const int so = row * PADK + seg * 8;
                const size_t xk = (xrow0 + row) * CIN + k0 + seg * 8;
                *(uint4*)(sXhi + so) = *(const uint4*)(g_x0hi + xk);
                *(uint4*)(sXlo + so) = *(const uint4*)(g_x0lo + xk);
            }
        } else {
            // Xt tile: rows o' in [k0,k0+64), cols n in [n0,n0+128)
            const int r  = tid >> 2;
            const int qn = (tid & 3) << 5;
            const float a  = sAff[k0 + r];
            const float b2 = sBeta[k0 + r];
            const float4* src = (const float4*)(g_y0 + ((size_t)(b * CO) + k0 + r) * NN_ + n0 + qn);
            bf16* dh = sXthi + r * PADN + qn;
            bf16* dl = sXtlo + r * PADN + qn;
#pragma unroll
            for (int v = 0; v < 4; ++v) {
                float4 fA = src[2 * v], fB = src[2 * v + 1];
                float x0 = fmaxf(fmaf(a, fA.x, b2), 0.f);
                float x1 = fmaxf(fmaf(a, fA.y, b2), 0.f);
                float x2 = fmaxf(fmaf(a, fA.z, b2), 0.f);
                float x3 = fmaxf(fmaf(a, fA.w, b2), 0.f);
                float x4 = fmaxf(fmaf(a, fB.x, b2), 0.f);
                float x5 = fmaxf(fmaf(a, fB.y, b2), 0.f);
                float x6 = fmaxf(fmaf(a, fB.z, b2), 0.f);
                float x7 = fmaxf(fmaf(a, fB.w, b2), 0.f);
                uint32_t h0, h1, h2, h3, l0, l1, l2, l3;
                split2(x0, x1, h0, l0); split2(x2, x3, h1, l1);
                split2(x4, x5, h2, l2); split2(x6, x7, h3, l3);
                *(uint4*)(dh + v * 8) = make_uint4(h0, h1, h2, h3);
                *(uint4*)(dl + v * 8) = make_uint4(l0, l1, l2, l3);
            }
        }
        __syncthreads();

#pragma unroll
        for (int kk = 0; kk < 4; ++kk) {
            uint32_t ah[2][4], al[2][4];
#pragma unroll
            for (int t = 0; t < 2; ++t) {
                const uint32_t ro = t * 16 * PADK * 2 + kk * 32;
                ldsm4(ah[t][0], ah[t][1], ah[t][2], ah[t][3], aWhi + ro);
                ldsm4(al[t][0], al[t][1], al[t][2], al[t][3], aWlo + ro);
            }
            uint32_t bh[4][4], bl[4][4];
#pragma unroll
            for (int u = 0; u < 4; ++u) {
                if (LAYER == 0) {
                    const uint32_t ro = u * 16 * PADK * 2 + kk * 32;
                    ldsm4(bh[u][0], bh[u][1], bh[u][2], bh[u][3], aXhi + ro);
                    ldsm4(bl[u][0], bl[u][1], bl[u][2], bl[u][3], aXlo + ro);
                } else {
                    const uint32_t ro = kk * 16 * PADN * 2 + u * 32;
                    ldsm4t(bh[u][0], bh[u][1], bh[u][2], bh[u][3], aXthi + ro);
                    ldsm4t(bl[u][0], bl[u][1], bl[u][2], bl[u][3], aXtlo + ro);
                }
            }
#pragma unroll
            for (int t = 0; t < 2; ++t)
#pragma unroll
                for (int j = 0; j < 8; ++j) {
                    const uint32_t* ph = &bh[j >> 1][(j & 1) * 2];
                    const uint32_t* pl = &bl[j >> 1][(j & 1) * 2];
                    mma16816(acc[t][j], ah[t], ph);
                    mma16816(acc[t][j], ah[t], pl);
                    mma16816(acc[t][j], al[t], ph);
                }
        }
    }

    // ---- Y store ----
    const int orow = o0 + warp_o + (lane >> 2);
    const int ncol = n0 + warp_n + (lane & 3) * 2;
#pragma unroll
    for (int t = 0; t < 2; ++t) {
        float* d0 = Y + ((size_t)(b * CO) + orow + t * 16) * NN_ + ncol;
        float* d1 = d0 + 8 * NN_;
#pragma unroll
        for (int j = 0; j < 8; ++j) {
            *(float2*)(d0 + j * 8) = make_float2(acc[t][j][0], acc[t][j][1]);
            *(float2*)(d1 + j * 8) = make_float2(acc[t][j][2], acc[t][j][3]);
        }
    }

    // ---- deterministic stats partials ----
    float rs[4] = {}, rq[4] = {};
#pragma unroll
    for (int t = 0; t < 2; ++t)
#pragma unroll
        for (int j = 0; j < 8; ++j) {
            rs[t * 2 + 0] += acc[t][j][0] + acc[t][j][1];
            rq[t * 2 + 0] += acc[t][j][0] * acc[t][j][0] + acc[t][j][1] * acc[t][j][1];
            rs[t * 2 + 1] += acc[t][j][2] + acc[t][j][3];
            rq[t * 2 + 1] += acc[t][j][2] * acc[t][j][2] + acc[t][j][3] * acc[t][j][3];
        }
#pragma unroll
    for (int v = 0; v < 4; ++v) {
        rs[v] += __shfl_xor_sync(0xffffffffu, rs[v], 1);
        rs[v] += __shfl_xor_sync(0xffffffffu, rs[v], 2);
        rq[v] += __shfl_xor_sync(0xffffffffu, rq[v], 1);
        rq[v] += __shfl_xor_sync(0xffffffffu, rq[v], 2);
    }
    __syncthreads();
    float* sSum = (float*)smem;        // [2][128]
    float* sSq  = sSum + 256;          // [2][128]
    if ((lane & 3) == 0) {
        const int h = (wid >> 2) * 128;
        const int g = warp_o + (lane >> 2);
        sSum[h + g]      = rs[0];
        sSum[h + g + 8]  = rs[1];
        sSum[h + g + 16] = rs[2];
        sSum[h + g + 24] = rs[3];
        sSq[h + g]       = rq[0];
        sSq[h + g + 8]   = rq[1];
        sSq[h + g + 16]  = rq[2];
        sSq[h + g + 24]  = rq[3];
    }
    __syncthreads();
    if (tid < 128) {
        g_psum[(size_t)(o0 + tid) * NBX + bx] = sSum[tid] + sSum[128 + tid];
        g_psq[(size_t)(o0 + tid) * NBX + bx]  = sSq[tid] + sSq[128 + tid];
    }
}

// ---------------- 6) stats reduce: partials -> BN affine ------------------
template <int LAYER>
__global__ __launch_bounds__(256) void stats_reduce(const float* __restrict__ gamma,
                                                    const float* __restrict__ beta) {
    const int o = blockIdx.x, tid = threadIdx.x;
    float s = g_psum[(size_t)o * NBX + tid] + g_psum[(size_t)o * NBX + 256 + tid];
    float q = g_psq[(size_t)o * NBX + tid] + g_psq[(size_t)o * NBX + 256 + tid];
    __shared__ float ss[256], sq[256];
    ss[tid] = s; sq[tid] = q;
    __syncthreads();
    for (int st = 128; st > 0; st >>= 1) {
        if (tid < st) { ss[tid] += ss[tid + st]; sq[tid] += sq[tid + st]; }
        __syncthreads();
    }
    if (tid == 0) {
        const float inv = 1.f / (float)(BB * NN_);
        const float mu  = ss[0] * inv;
        const float var = sq[0] * inv - mu * mu;
        const float a   = gamma[o] * rsqrtf(var + 1e-5f);
        float* ab = (LAYER == 0) ? g_ab0 : g_ab1;
        ab[o]      = a;
        ab[CO + o] = beta[o] - mu * a;
    }
}

// ---------------- 7) final BN1 + ReLU in place on d_out ------------------
__global__ __launch_bounds__(256) void bnrelu_kernel(float* __restrict__ y) {
    const size_t i = ((size_t)blockIdx.x * blockDim.x + threadIdx.x) * 4;
    const int c = (int)((i >> 13) & (CO - 1));
    const float a = g_ab1[c], bb = g_ab1[CO + c];
    float4 v = *(float4*)(y + i);
    v.x = fmaxf(fmaf(a, v.x, bb), 0.f);
    v.y = fmaxf(fmaf(a, v.y, bb), 0.f);
    v.z = fmaxf(fmaf(a, v.z, bb), 0.f);
    v.w = fmaxf(fmaf(a, v.w, bb), 0.f);
    *(float4*)(y + i) = v;
}

// ---------------- launcher ------------------------------------------------
extern "C" void kernel_launch(void* const* d_in, const int* in_sizes, int n_in,
                              void* d_out, int out_size) {
    const float* xyz1   = (const float*)d_in[0];
    const float* xyz2   = (const float*)d_in[1];
    const float* f1     = (const float*)d_in[2];
    const float* f2     = (const float*)d_in[3];
    const float* w0     = (const float*)d_in[4];
    const float* gamma0 = (const float*)d_in[5];
    const float* beta0  = (const float*)d_in[6];
    const float* w1     = (const float*)d_in[7];
    const float* gamma1 = (const float*)d_in[8];
    const float* beta1  = (const float*)d_in[9];
    float* out = (float*)d_out;

    cudaFuncSetAttribute(gemm_mma<0>, cudaFuncAttributeMaxDynamicSharedMemorySize, GEMM_SMEM);
    cudaFuncSetAttribute(gemm_mma<1>, cudaFuncAttributeMaxDynamicSharedMemorySize, GEMM_SMEM);

    nn_kernel<<<dim3(NN_ / 256, BB), 256>>>(xyz1, xyz2);
    prep_w<<<(CO * CIN + 255) / 256, 256>>>(w0, w1);
    prep_f2t<<<dim3(MM / 32, C2 / 32, BB), dim3(32, 8)>>>(f2);
    prep_x0<<<dim3(NN_ / 64, BB), 256>>>(f1);

    gemm_mma<0><<<dim3(NBX, CO / 128), 256, GEMM_SMEM>>>(nullptr);
    stats_reduce<0><<<CO, 256>>>(gamma0, beta0);

    gemm_mma<1><<<dim3(NBX, CO / 128), 256, GEMM_SMEM>>>(out);
    stats_reduce<1><<<CO, 256>>>(gamma1, beta1);

    bnrelu_kernel<<<(BB * CO * NN_) / (4 * 256), 256>>>(out);
}

// round 7
// speedup vs baseline: 1.9172x; 1.0218x over previous
#include <cuda_runtime.h>
#include <cuda_bf16.h>
#include <cstdint>

#define BB 8
#define NN_ 8192
#define MM 2048
#define C1 128
#define C2 256
#define CIN 384
#define CO 256
#define NBX 512            // BB * (NN_/128) gemm n-tiles

typedef unsigned long long ull;
typedef __nv_bfloat16 bf16;

// ---------------- device scratch (no allocations allowed) ----------------
__device__ int   g_idx[BB * NN_];
__device__ float g_y0[(size_t)BB * CO * NN_];        // pre-BN output of layer 0 (64MB)
__device__ float g_ab0[2 * CO];
__device__ float g_ab1[2 * CO];
__device__ float g_f2t[(size_t)BB * MM * C2];        // f2 transposed [b][m][c2]
__device__ bf16  g_w0hi[CO * CIN], g_w0lo[CO * CIN];
__device__ bf16  g_w1hi[CO * CO],  g_w1lo[CO * CO];
__device__ float g_psum[CO * NBX];                   // per-(channel, CTA) partials
__device__ float g_psq[CO * NBX];

// ---------------- helpers -------------------------------------------------
__device__ __forceinline__ ull f2_add(ull a, ull b) {
    ull r; asm("add.rn.f32x2 %0, %1, %2;" : "=l"(r) : "l"(a), "l"(b)); return r;
}
__device__ __forceinline__ ull f2_mul(ull a, ull b) {
    ull r; asm("mul.rn.f32x2 %0, %1, %2;" : "=l"(r) : "l"(a), "l"(b)); return r;
}
__device__ __forceinline__ ull f2_pack(float lo, float hi) {
    ull r; asm("mov.b64 %0, {%1, %2};" : "=l"(r) : "f"(lo), "f"(hi)); return r;
}
__device__ __forceinline__ void f2_unpack(float& lo, float& hi, ull v) {
    asm("mov.b64 {%0, %1}, %2;" : "=f"(lo), "=f"(hi) : "l"(v));
}
__device__ __forceinline__ uint32_t smem_u32(const void* p) {
    uint32_t a;
    asm("{ .reg .u64 t; cvta.to.shared.u64 t, %1; cvt.u32.u64 %0, t; }" : "=r"(a) : "l"(p));
    return a;
}
__device__ __forceinline__ void ldsm4(uint32_t& r0, uint32_t& r1, uint32_t& r2, uint32_t& r3,
                                      uint32_t addr) {
    asm volatile("ldmatrix.sync.aligned.m8n8.x4.shared.b16 {%0,%1,%2,%3}, [%4];"
                 : "=r"(r0), "=r"(r1), "=r"(r2), "=r"(r3) : "r"(addr));
}
__device__ __forceinline__ void ldsm4t(uint32_t& r0, uint32_t& r1, uint32_t& r2, uint32_t& r3,
                                       uint32_t addr) {
    asm volatile("ldmatrix.sync.aligned.m8n8.x4.trans.shared.b16 {%0,%1,%2,%3}, [%4];"
                 : "=r"(r0), "=r"(r1), "=r"(r2), "=r"(r3) : "r"(addr));
}
__device__ __forceinline__ void mma16816(float* c, const uint32_t* a, const uint32_t* b) {
    asm volatile("mma.sync.aligned.m16n8k16.row.col.f32.bf16.bf16.f32 "
                 "{%0,%1,%2,%3}, {%4,%5,%6,%7}, {%8,%9}, {%0,%1,%2,%3};"
                 : "+f"(c[0]), "+f"(c[1]), "+f"(c[2]), "+f"(c[3])
                 : "r"(a[0]), "r"(a[1]), "r"(a[2]), "r"(a[3]), "r"(b[0]), "r"(b[1]));
}
__device__ __forceinline__ void split2(float v0, float v1, uint32_t& hi, uint32_t& lo) {
    bf16 h0 = __float2bfloat16(v0), h1 = __float2bfloat16(v1);
    bf16 l0 = __float2bfloat16(v0 - __bfloat162float(h0));
    bf16 l1 = __float2bfloat16(v1 - __bfloat162float(h1));
    __nv_bfloat162 hp(h0, h1), lp(l0, l1);
    hi = *(uint32_t*)&hp; lo = *(uint32_t*)&lp;
}
__device__ __forceinline__ void split1(float v, bf16& h, bf16& l) {
    h = __float2bfloat16(v);
    l = __float2bfloat16(v - __bfloat162float(h));
}

// ---------------- 1) nearest neighbor (bitwise-matching argmin) ----------
// 2 points/thread: 3 LDS.64 per iter amortized over 2 points (LDS-bound loop).
__global__ __launch_bounds__(256) void nn_kernel(const float* __restrict__ xyz1,
                                                 const float* __restrict__ xyz2) {
    __shared__ __align__(16) float nq[3][MM];
    const int b  = blockIdx.y;
    const int n0 = blockIdx.x * 512;
    const int tid = threadIdx.x;

    const float* x2 = xyz2 + (size_t)b * MM * 3;
    for (int m = tid; m < MM; m += 256) {
        nq[0][m] = -x2[3 * m + 0];
        nq[1][m] = -x2[3 * m + 1];
        nq[2][m] = -x2[3 * m + 2];
    }
    __syncthreads();

    const ull* qx2 = (const ull*)nq[0];
    const ull* qy2 = (const ull*)nq[1];
    const ull* qz2 = (const ull*)nq[2];

    const int ng0 = n0 + tid;
    const int ng1 = n0 + tid + 256;
    const float* p0 = xyz1 + ((size_t)b * NN_ + ng0) * 3;
    const float* p1 = xyz1 + ((size_t)b * NN_ + ng1) * 3;

    const ull px0 = f2_pack(p0[0], p0[0]), py0 = f2_pack(p0[1], p0[1]), pz0 = f2_pack(p0[2], p0[2]);
    const ull px1 = f2_pack(p1[0], p1[0]), py1 = f2_pack(p1[1], p1[1]), pz1 = f2_pack(p1[2], p1[2]);

    float be0 = 3.0e38f, bo0 = 3.0e38f, be1 = 3.0e38f, bo1 = 3.0e38f;
    int   ie0 = 0, io0 = 1, ie1 = 0, io1 = 1;

#pragma unroll 8
    for (int m2 = 0; m2 < MM / 2; ++m2) {
        const ull qx = qx2[m2], qy = qy2[m2], qz = qz2[m2];
        {
            ull dx = f2_add(px0, qx), dy = f2_add(py0, qy), dz = f2_add(pz0, qz);
            ull d  = f2_add(f2_add(f2_mul(dx, dx), f2_mul(dy, dy)), f2_mul(dz, dz));
            float dl, dh; f2_unpack(dl, dh, d);
            const bool pe = dl < be0, po = dh < bo0;
            be0 = pe ? dl : be0; ie0 = pe ? 2 * m2 : ie0;
            bo0 = po ? dh : bo0; io0 = po ? 2 * m2 + 1 : io0;
        }
        {
            ull dx = f2_add(px1, qx), dy = f2_add(py1, qy), dz = f2_add(pz1, qz);
            ull d  = f2_add(f2_add(f2_mul(dx, dx), f2_mul(dy, dy)), f2_mul(dz, dz));
            float dl, dh; f2_unpack(dl, dh, d);
            const bool pe = dl < be1, po = dh < bo1;
            be1 = pe ? dl : be1; ie1 = pe ? 2 * m2 : ie1;
            bo1 = po ? dh : bo1; io1 = po ? 2 * m2 + 1 : io1;
        }
    }
    int bi0 = ie0;
    if (bo0 < be0 || (bo0 == be0 && io0 < ie0)) bi0 = io0;
    int bi1 = ie1;
    if (bo1 < be1 || (bo1 == be1 && io1 < ie1)) bi1 = io1;

    g_idx[b * NN_ + ng0] = bi0;
    g_idx[b * NN_ + ng1] = bi1;
}

// ---------------- 2) weight split ----------------------------------------
__global__ __launch_bounds__(256) void prep_w(const float* __restrict__ w0,
                                              const float* __restrict__ w1) {
    const int i = blockIdx.x * 256 + threadIdx.x;
    if (i < CO * CIN) {
        float v = w0[i];
        bf16 h = __float2bfloat16(v);
        g_w0hi[i] = h;
        g_w0lo[i] = __float2bfloat16(v - __bfloat162float(h));
    }
    if (i < CO * CO) {
        float v = w1[i];
        bf16 h = __float2bfloat16(v);
        g_w1hi[i] = h;
        g_w1lo[i] = __float2bfloat16(v - __bfloat162float(h));
    }
}

// ---------------- 3) transpose f2 -> [b][m][c2] ---------------------------
__global__ void prep_f2t(const float* __restrict__ f2) {
    __shared__ float t[32][33];
    const int b = blockIdx.z, m0 = blockIdx.x * 32, c0 = blockIdx.y * 32;
    const int tx = threadIdx.x, ty = threadIdx.y;  // 32x8
#pragma unroll
    for (int k = 0; k < 4; k++)
        t[ty + 8 * k][tx] = f2[((size_t)(b * C2) + c0 + ty + 8 * k) * MM + m0 + tx];
    __syncthreads();
#pragma unroll
    for (int k = 0; k < 4; k++)
        g_f2t[((size_t)(b * MM) + m0 + ty + 8 * k) * C2 + c0 + tx] = t[tx][ty + 8 * k];
}

// ---------------- 4) HMMA GEMM + fused X build + fused stats --------------
// CTA 128(o) x 128(n), 8 warps (4 o x 2 n), warp tile 32x64.
// 3-MMA hi/lo split. Both layers build k-major Xt tiles in the loader and
// consume via trans-ldmatrix:
//   LAYER 0, k<128 : rows from f1 (coalesced along n), split only.
//   LAYER 0, k>=128: per-point gather of f2t row segments (fused interp).
//   LAYER 1        : rows from y0 with BN0 affine + ReLU + split.
// Epilogue: deterministic per-CTA (sum, sumsq) partials per channel.
#define PADK 72
#define PADN 136
#define W_TILE_B  (128 * PADK * 2)          // 18432
#define XT_OFF    (2 * W_TILE_B)            // 36864
#define XT_TILE_B (64 * PADN * 2)           // 17408
#define AFF_OFF   (XT_OFF + 2 * XT_TILE_B)  // 71680
#define GEMM_SMEM (AFF_OFF + 2048)          // 73728

template <int LAYER>
__global__ __launch_bounds__(256) void gemm_mma(const float* __restrict__ f1arg,
                                                float* __restrict__ Yarg) {
    constexpr int KDIM = (LAYER == 0) ? CIN : CO;
    const bf16* __restrict__ Whi = (LAYER == 0) ? g_w0hi : g_w1hi;
    const bf16* __restrict__ Wlo = (LAYER == 0) ? g_w0lo : g_w1lo;
    float* __restrict__ Y = (LAYER == 0) ? g_y0 : Yarg;

    extern __shared__ __align__(16) char smem[];
    bf16* sWhi  = (bf16*)(smem);
    bf16* sWlo  = (bf16*)(smem + W_TILE_B);
    bf16* sXthi = (bf16*)(smem + XT_OFF);
    bf16* sXtlo = (bf16*)(smem + XT_OFF + XT_TILE_B);
    float* sAff  = (float*)(smem + AFF_OFF);   // layer1 only
    float* sBeta = sAff + 256;
    int*   sidx  = (int*)(smem + AFF_OFF);     // layer0 only (overlaps sAff)

    const int tid = threadIdx.x, wid = tid >> 5, lane = tid & 31;
    const int bx = blockIdx.x;
    const int b  = bx >> 6;
    const int n0 = (bx & 63) << 7;
    const int o0 = blockIdx.y << 7;

    const int warp_o = (wid & 3) * 32;
    const int warp_n = (wid >> 2) * 64;

    const uint32_t sb = smem_u32(smem);
    const int arow = warp_o + (lane & 15);
    const int acol = (lane >> 4) * 8;
    const uint32_t aWhi = sb + (arow * PADK + acol) * 2;
    const uint32_t aWlo = aWhi + W_TILE_B;
    const int krow = (lane & 7) + ((lane >> 3) & 1) * 8;   // k-major trans ldmatrix
    const int noff = warp_n + ((lane >> 4) & 1) * 8;
    const uint32_t aXthi = sb + XT_OFF + (krow * PADN + noff) * 2;
    const uint32_t aXtlo = aXthi + XT_TILE_B;

    if (LAYER == 1) {
        sAff[tid]  = g_ab0[tid];
        sBeta[tid] = g_ab0[CO + tid];
    } else {
        if (tid < 128) sidx[tid] = g_idx[b * NN_ + n0 + tid];
    }

    float acc[2][8][4] = {};

    for (int k0 = 0; k0 < KDIM; k0 += 64) {
        __syncthreads();
        // W tiles
#pragma unroll
        for (int it = 0; it < 4; ++it) {
            const int i = tid + it * 256;
            const int row = i >> 3, seg = i & 7;
            const int so = row * PADK + seg * 8;
            const size_t wk = (size_t)(o0 + row) * KDIM + k0 + seg * 8;
            *(uint4*)(sWhi + so) = *(const uint4*)(Whi + wk);
            *(uint4*)(sWlo + so) = *(const uint4*)(Wlo + wk);
        }
        // Xt tile (k-major, 64 k rows x 128 n cols)
        if (LAYER == 0 && k0 >= C1) {
            // fused gather: Xt[k][n] = f2t[idx[n]][k-128]
            const int n  = tid & 127;
            const int kh = tid >> 7;                 // 0/1 -> 32 k's each
            const float* row = g_f2t + ((size_t)(b * MM) + sidx[n]) * C2 + (k0 - C1) + kh * 32;
            float v[32];
#pragma unroll
            for (int q = 0; q < 8; ++q) {
                const float4 f = *(const float4*)(row + q * 4);
                v[q * 4 + 0] = f.x; v[q * 4 + 1] = f.y; v[q * 4 + 2] = f.z; v[q * 4 + 3] = f.w;
            }
#pragma unroll
            for (int q = 0; q < 32; ++q) {
                bf16 h, l;
                split1(v[q], h, l);
                const int kr = kh * 32 + q;
                sXthi[kr * PADN + n] = h;
                sXtlo[kr * PADN + n] = l;
            }
        } else {
            // row-streaming path: f1 (layer0 k<128) or y0+affine (layer1)
            const int r  = tid >> 2;
            const int qn = (tid & 3) << 5;
            const float* srcf = (LAYER == 0)
                ? (f1arg + ((size_t)(b * C1) + k0 + r) * NN_ + n0 + qn)
                : (g_y0 + ((size_t)(b * CO) + k0 + r) * NN_ + n0 + qn);
            const float a  = (LAYER == 0) ? 1.f : sAff[k0 + r];
            const float b2 = (LAYER == 0) ? 0.f : sBeta[k0 + r];
            const float4* src = (const float4*)srcf;
            bf16* dh = sXthi + r * PADN + qn;
            bf16* dl = sXtlo + r * PADN + qn;
#pragma unroll
            for (int v = 0; v < 4; ++v) {
                float4 fA = src[2 * v], fB = src[2 * v + 1];
                float x0, x1, x2, x3, x4, x5, x6, x7;
                if (LAYER == 0) {
                    x0 = fA.x; x1 = fA.y; x2 = fA.z; x3 = fA.w;
                    x4 = fB.x; x5 = fB.y; x6 = fB.z; x7 = fB.w;
                } else {
                    x0 = fmaxf(fmaf(a, fA.x, b2), 0.f);
                    x1 = fmaxf(fmaf(a, fA.y, b2), 0.f);
                    x2 = fmaxf(fmaf(a, fA.z, b2), 0.f);
                    x3 = fmaxf(fmaf(a, fA.w, b2), 0.f);
                    x4 = fmaxf(fmaf(a, fB.x, b2), 0.f);
                    x5 = fmaxf(fmaf(a, fB.y, b2), 0.f);
                    x6 = fmaxf(fmaf(a, fB.z, b2), 0.f);
                    x7 = fmaxf(fmaf(a, fB.w, b2), 0.f);
                }
                uint32_t h0, h1, h2, h3, l0, l1, l2, l3;
                split2(x0, x1, h0, l0); split2(x2, x3, h1, l1);
                split2(x4, x5, h2, l2); split2(x6, x7, h3, l3);
                *(uint4*)(dh + v * 8) = make_uint4(h0, h1, h2, h3);
                *(uint4*)(dl + v * 8) = make_uint4(l0, l1, l2, l3);
            }
        }
        __syncthreads();

#pragma unroll
        for (int kk = 0; kk < 4; ++kk) {
            uint32_t ah[2][4], al[2][4];
#pragma unroll
            for (int t = 0; t < 2; ++t) {
                const uint32_t ro = t * 16 * PADK * 2 + kk * 32;
                ldsm4(ah[t][0], ah[t][1], ah[t][2], ah[t][3], aWhi + ro);
                ldsm4(al[t][0], al[t][1], al[t][2], al[t][3], aWlo + ro);
            }
            uint32_t bh[4][4], bl[4][4];
#pragma unroll
            for (int u = 0; u < 4; ++u) {
                const uint32_t ro = kk * 16 * PADN * 2 + u * 32;
                ldsm4t(bh[u][0], bh[u][1], bh[u][2], bh[u][3], aXthi + ro);
                ldsm4t(bl[u][0], bl[u][1], bl[u][2], bl[u][3], aXtlo + ro);
            }
#pragma unroll
            for (int t = 0; t < 2; ++t)
#pragma unroll
                for (int j = 0; j < 8; ++j) {
                    const uint32_t* ph = &bh[j >> 1][(j & 1) * 2];
                    const uint32_t* pl = &bl[j >> 1][(j & 1) * 2];
                    mma16816(acc[t][j], ah[t], ph);
                    mma16816(acc[t][j], ah[t], pl);
                    mma16816(acc[t][j], al[t], ph);
                }
        }
    }

    // ---- Y store ----
    const int orow = o0 + warp_o + (lane >> 2);
    const int ncol = n0 + warp_n + (lane & 3) * 2;
#pragma unroll
    for (int t = 0; t < 2; ++t) {
        float* d0 = Y + ((size_t)(b * CO) + orow + t * 16) * NN_ + ncol;
        float* d1 = d0 + 8 * NN_;
#pragma unroll
        for (int j = 0; j < 8; ++j) {
            *(float2*)(d0 + j * 8) = make_float2(acc[t][j][0], acc[t][j][1]);
            *(float2*)(d1 + j * 8) = make_float2(acc[t][j][2], acc[t][j][3]);
        }
    }

    // ---- deterministic stats partials ----
    float rs[4] = {}, rq[4] = {};
#pragma unroll
    for (int t = 0; t < 2; ++t)
#pragma unroll
        for (int j = 0; j < 8; ++j) {
            rs[t * 2 + 0] += acc[t][j][0] + acc[t][j][1];
            rq[t * 2 + 0] += acc[t][j][0] * acc[t][j][0] + acc[t][j][1] * acc[t][j][1];
            rs[t * 2 + 1] += acc[t][j][2] + acc[t][j][3];
            rq[t * 2 + 1] += acc[t][j][2] * acc[t][j][2] + acc[t][j][3] * acc[t][j][3];
        }
#pragma unroll
    for (int v = 0; v < 4; ++v) {
        rs[v] += __shfl_xor_sync(0xffffffffu, rs[v], 1);
        rs[v] += __shfl_xor_sync(0xffffffffu, rs[v], 2);
        rq[v] += __shfl_xor_sync(0xffffffffu, rq[v], 1);
        rq[v] += __shfl_xor_sync(0xffffffffu, rq[v], 2);
    }
    __syncthreads();
    float* sSum = (float*)smem;        // [2][128]
    float* sSq  = sSum + 256;
    if ((lane & 3) == 0) {
        const int h = (wid >> 2) * 128;
        const int g = warp_o + (lane >> 2);
        sSum[h + g]      = rs[0];
        sSum[h + g + 8]  = rs[1];
        sSum[h + g + 16] = rs[2];
        sSum[h + g + 24] = rs[3];
        sSq[h + g]       = rq[0];
        sSq[h + g + 8]   = rq[1];
        sSq[h + g + 16]  = rq[2];
        sSq[h + g + 24]  = rq[3];
    }
    __syncthreads();
    if (tid < 128) {
        g_psum[(size_t)(o0 + tid) * NBX + bx] = sSum[tid] + sSum[128 + tid];
        g_psq[(size_t)(o0 + tid) * NBX + bx]  = sSq[tid] + sSq[128 + tid];
    }
}

// ---------------- 5) stats reduce: partials -> BN affine ------------------
template <int LAYER>
__global__ __launch_bounds__(256) void stats_reduce(const float* __restrict__ gamma,
                                                    const float* __restrict__ beta) {
    const int o = blockIdx.x, tid = threadIdx.x;
    float s = g_psum[(size_t)o * NBX + tid] + g_psum[(size_t)o * NBX + 256 + tid];
    float q = g_psq[(size_t)o * NBX + tid] + g_psq[(size_t)o * NBX + 256 + tid];
    __shared__ float ss[256], sq[256];
    ss[tid] = s; sq[tid] = q;
    __syncthreads();
    for (int st = 128; st > 0; st >>= 1) {
        if (tid < st) { ss[tid] += ss[tid + st]; sq[tid] += sq[tid + st]; }
        __syncthreads();
    }
    if (tid == 0) {
        const float inv = 1.f / (float)(BB * NN_);
        const float mu  = ss[0] * inv;
        const float var = sq[0] * inv - mu * mu;
        const float a   = gamma[o] * rsqrtf(var + 1e-5f);
        float* ab = (LAYER == 0) ? g_ab0 : g_ab1;
        ab[o]      = a;
        ab[CO + o] = beta[o] - mu * a;
    }
}

// ---------------- 6) final BN1 + ReLU in place on d_out ------------------
__global__ __launch_bounds__(256) void bnrelu_kernel(float* __restrict__ y) {
    const size_t i = ((size_t)blockIdx.x * blockDim.x + threadIdx.x) * 4;
    const int c = (int)((i >> 13) & (CO - 1));
    const float a = g_ab1[c], bb = g_ab1[CO + c];
    float4 v = *(float4*)(y + i);
    v.x = fmaxf(fmaf(a, v.x, bb), 0.f);
    v.y = fmaxf(fmaf(a, v.y, bb), 0.f);
    v.z = fmaxf(fmaf(a, v.z, bb), 0.f);
    v.w = fmaxf(fmaf(a, v.w, bb), 0.f);
    *(float4*)(y + i) = v;
}

// ---------------- launcher ------------------------------------------------
extern "C" void kernel_launch(void* const* d_in, const int* in_sizes, int n_in,
                              void* d_out, int out_size) {
    const float* xyz1   = (const float*)d_in[0];
    const float* xyz2   = (const float*)d_in[1];
    const float* f1     = (const float*)d_in[2];
    const float* f2     = (const float*)d_in[3];
    const float* w0     = (const float*)d_in[4];
    const float* gamma0 = (const float*)d_in[5];
    const float* beta0  = (const float*)d_in[6];
    const float* w1     = (const float*)d_in[7];
    const float* gamma1 = (const float*)d_in[8];
    const float* beta1  = (const float*)d_in[9];
    float* out = (float*)d_out;

    cudaFuncSetAttribute(gemm_mma<0>, cudaFuncAttributeMaxDynamicSharedMemorySize, GEMM_SMEM);
    cudaFuncSetAttribute(gemm_mma<1>, cudaFuncAttributeMaxDynamicSharedMemorySize, GEMM_SMEM);

    nn_kernel<<<dim3(NN_ / 512, BB), 256>>>(xyz1, xyz2);
    prep_w<<<(CO * CIN + 255) / 256, 256>>>(w0, w1);
    prep_f2t<<<dim3(MM / 32, C2 / 32, BB), dim3(32, 8)>>>(f2);

    gemm_mma<0><<<dim3(NBX, CO / 128), 256, GEMM_SMEM>>>(f1, nullptr);
    stats_reduce<0><<<CO, 256>>>(gamma0, beta0);

    gemm_mma<1><<<dim3(NBX, CO / 128), 256, GEMM_SMEM>>>(nullptr, out);
    stats_reduce<1><<<CO, 256>>>(gamma1, beta1);

    bnrelu_kernel<<<(BB * CO * NN_) / (4 * 256), 256>>>(out);
}

// round 8
// speedup vs baseline: 2.1344x; 1.1133x over previous
#include <cuda_runtime.h>
#include <cuda_bf16.h>
#include <cstdint>

#define BB 8
#define NN_ 8192
#define MM 2048
#define C1 128
#define C2 256
#define CIN 384
#define CO 256
#define NBX 512            // BB * (NN_/128) gemm n-tiles

typedef unsigned long long ull;
typedef __nv_bfloat16 bf16;

// ---------------- device scratch (no allocations allowed) ----------------
__device__ int   g_idx[BB * NN_];
__device__ float g_y0[(size_t)BB * CO * NN_];        // pre-BN output of layer 0 (64MB)
__device__ float g_ab0[2 * CO];
__device__ float g_ab1[2 * CO];
__device__ float g_f2t[(size_t)BB * MM * C2];        // f2 transposed [b][m][c2]
__device__ bf16  g_w0hi[CO * CIN], g_w0lo[CO * CIN];
__device__ bf16  g_w1hi[CO * CO],  g_w1lo[CO * CO];
__device__ float g_psum[CO * NBX];                   // per-(channel, CTA) partials
__device__ float g_psq[CO * NBX];

// ---------------- helpers -------------------------------------------------
__device__ __forceinline__ ull f2_add(ull a, ull b) {
    ull r; asm("add.rn.f32x2 %0, %1, %2;" : "=l"(r) : "l"(a), "l"(b)); return r;
}
__device__ __forceinline__ ull f2_mul(ull a, ull b) {
    ull r; asm("mul.rn.f32x2 %0, %1, %2;" : "=l"(r) : "l"(a), "l"(b)); return r;
}
__device__ __forceinline__ ull f2_pack(float lo, float hi) {
    ull r; asm("mov.b64 %0, {%1, %2};" : "=l"(r) : "f"(lo), "f"(hi)); return r;
}
__device__ __forceinline__ void f2_unpack(float& lo, float& hi, ull v) {
    asm("mov.b64 {%0, %1}, %2;" : "=f"(lo), "=f"(hi) : "l"(v));
}
__device__ __forceinline__ uint32_t smem_u32(const void* p) {
    uint32_t a;
    asm("{ .reg .u64 t; cvta.to.shared.u64 t, %1; cvt.u32.u64 %0, t; }" : "=r"(a) : "l"(p));
    return a;
}
__device__ __forceinline__ void ldsm4(uint32_t& r0, uint32_t& r1, uint32_t& r2, uint32_t& r3,
                                      uint32_t addr) {
    asm volatile("ldmatrix.sync.aligned.m8n8.x4.shared.b16 {%0,%1,%2,%3}, [%4];"
                 : "=r"(r0), "=r"(r1), "=r"(r2), "=r"(r3) : "r"(addr));
}
__device__ __forceinline__ void ldsm4t(uint32_t& r0, uint32_t& r1, uint32_t& r2, uint32_t& r3,
                                       uint32_t addr) {
    asm volatile("ldmatrix.sync.aligned.m8n8.x4.trans.shared.b16 {%0,%1,%2,%3}, [%4];"
                 : "=r"(r0), "=r"(r1), "=r"(r2), "=r"(r3) : "r"(addr));
}
__device__ __forceinline__ void mma16816(float* c, const uint32_t* a, const uint32_t* b) {
    asm volatile("mma.sync.aligned.m16n8k16.row.col.f32.bf16.bf16.f32 "
                 "{%0,%1,%2,%3}, {%4,%5,%6,%7}, {%8,%9}, {%0,%1,%2,%3};"
                 : "+f"(c[0]), "+f"(c[1]), "+f"(c[2]), "+f"(c[3])
                 : "r"(a[0]), "r"(a[1]), "r"(a[2]), "r"(a[3]), "r"(b[0]), "r"(b[1]));
}
__device__ __forceinline__ void split2(float v0, float v1, uint32_t& hi, uint32_t& lo) {
    bf16 h0 = __float2bfloat16(v0), h1 = __float2bfloat16(v1);
    bf16 l0 = __float2bfloat16(v0 - __bfloat162float(h0));
    bf16 l1 = __float2bfloat16(v1 - __bfloat162float(h1));
    __nv_bfloat162 hp(h0, h1), lp(l0, l1);
    hi = *(uint32_t*)&hp; lo = *(uint32_t*)&lp;
}
__device__ __forceinline__ void split1(float v, bf16& h, bf16& l) {
    h = __float2bfloat16(v);
    l = __float2bfloat16(v - __bfloat162float(h));
}
#define CP_ASYNC16(saddr, gptr) \
    asm volatile("cp.async.cg.shared.global [%0], [%1], 16;" :: "r"(saddr), "l"(gptr))
#define CP_COMMIT() asm volatile("cp.async.commit_group;" ::: "memory")
#define CP_WAIT0()  asm volatile("cp.async.wait_group 0;" ::: "memory")
#define CP_WAIT1()  asm volatile("cp.async.wait_group 1;" ::: "memory")

// ---------------- 1) nearest neighbor (bitwise-matching argmin) ----------
__global__ __launch_bounds__(256) void nn_kernel(const float* __restrict__ xyz1,
                                                 const float* __restrict__ xyz2) {
    __shared__ __align__(16) float nq[3][MM];
    const int b  = blockIdx.y;
    const int n0 = blockIdx.x * 512;
    const int tid = threadIdx.x;

    const float* x2 = xyz2 + (size_t)b * MM * 3;
    for (int m = tid; m < MM; m += 256) {
        nq[0][m] = -x2[3 * m + 0];
        nq[1][m] = -x2[3 * m + 1];
        nq[2][m] = -x2[3 * m + 2];
    }
    __syncthreads();

    const ull* qx2 = (const ull*)nq[0];
    const ull* qy2 = (const ull*)nq[1];
    const ull* qz2 = (const ull*)nq[2];

    const int ng0 = n0 + tid;
    const int ng1 = n0 + tid + 256;
    const float* p0 = xyz1 + ((size_t)b * NN_ + ng0) * 3;
    const float* p1 = xyz1 + ((size_t)b * NN_ + ng1) * 3;

    const ull px0 = f2_pack(p0[0], p0[0]), py0 = f2_pack(p0[1], p0[1]), pz0 = f2_pack(p0[2], p0[2]);
    const ull px1 = f2_pack(p1[0], p1[0]), py1 = f2_pack(p1[1], p1[1]), pz1 = f2_pack(p1[2], p1[2]);

    float be0 = 3.0e38f, bo0 = 3.0e38f, be1 = 3.0e38f, bo1 = 3.0e38f;
    int   ie0 = 0, io0 = 1, ie1 = 0, io1 = 1;

#pragma unroll 8
    for (int m2 = 0; m2 < MM / 2; ++m2) {
        const ull qx = qx2[m2], qy = qy2[m2], qz = qz2[m2];
        {
            ull dx = f2_add(px0, qx), dy = f2_add(py0, qy), dz = f2_add(pz0, qz);
            ull d  = f2_add(f2_add(f2_mul(dx, dx), f2_mul(dy, dy)), f2_mul(dz, dz));
            float dl, dh; f2_unpack(dl, dh, d);
            const bool pe = dl < be0, po = dh < bo0;
            be0 = pe ? dl : be0; ie0 = pe ? 2 * m2 : ie0;
            bo0 = po ? dh : bo0; io0 = po ? 2 * m2 + 1 : io0;
        }
        {
            ull dx = f2_add(px1, qx), dy = f2_add(py1, qy), dz = f2_add(pz1, qz);
            ull d  = f2_add(f2_add(f2_mul(dx, dx), f2_mul(dy, dy)), f2_mul(dz, dz));
            float dl, dh; f2_unpack(dl, dh, d);
            const bool pe = dl < be1, po = dh < bo1;
            be1 = pe ? dl : be1; ie1 = pe ? 2 * m2 : ie1;
            bo1 = po ? dh : bo1; io1 = po ? 2 * m2 + 1 : io1;
        }
    }
    int bi0 = ie0;
    if (bo0 < be0 || (bo0 == be0 && io0 < ie0)) bi0 = io0;
    int bi1 = ie1;
    if (bo1 < be1 || (bo1 == be1 && io1 < ie1)) bi1 = io1;

    g_idx[b * NN_ + ng0] = bi0;
    g_idx[b * NN_ + ng1] = bi1;
}

// ---------------- 2) weight split ----------------------------------------
__global__ __launch_bounds__(256) void prep_w(const float* __restrict__ w0,
                                              const float* __restrict__ w1) {
    const int i = blockIdx.x * 256 + threadIdx.x;
    if (i < CO * CIN) {
        float v = w0[i];
        bf16 h = __float2bfloat16(v);
        g_w0hi[i] = h;
        g_w0lo[i] = __float2bfloat16(v - __bfloat162float(h));
    }
    if (i < CO * CO) {
        float v = w1[i];
        bf16 h = __float2bfloat16(v);
        g_w1hi[i] = h;
        g_w1lo[i] = __float2bfloat16(v - __bfloat162float(h));
    }
}

// ---------------- 3) transpose f2 -> [b][m][c2] ---------------------------
__global__ void prep_f2t(const float* __restrict__ f2) {
    __shared__ float t[32][33];
    const int b = blockIdx.z, m0 = blockIdx.x * 32, c0 = blockIdx.y * 32;
    const int tx = threadIdx.x, ty = threadIdx.y;  // 32x8
#pragma unroll
    for (int k = 0; k < 4; k++)
        t[ty + 8 * k][tx] = f2[((size_t)(b * C2) + c0 + ty + 8 * k) * MM + m0 + tx];
    __syncthreads();
#pragma unroll
    for (int k = 0; k < 4; k++)
        g_f2t[((size_t)(b * MM) + m0 + ty + 8 * k) * C2 + c0 + tx] = t[tx][ty + 8 * k];
}

// ---------------- 4) pipelined HMMA GEMM + fused X build + fused stats ----
// Double-buffered smem. W tiles: cp.async (no reg staging). X tiles: register
// prefetch (k+2 issued after MMA(k)), convert+store after MMA(k+1). Each LDG
// hides behind a full MMA block. 3-MMA hi/lo split, trans-ldmatrix B.
#define PADK 72
#define PADN 136
#define W_TILE_B    (128 * PADK * 2)        // 18432
#define WBUF_STRIDE (2 * W_TILE_B)          // 36864
#define XBUF_OFF    (2 * WBUF_STRIDE)       // 73728
#define XT_TILE_B   (64 * PADN * 2)         // 17408
#define XBUF_STRIDE (2 * XT_TILE_B)         // 34816
#define SIDX_OFF    (XBUF_OFF + 2 * XBUF_STRIDE)  // 143360
#define GEMM_SMEM   (SIDX_OFF + 512)        // 143872

template <int LAYER>
__global__ __launch_bounds__(256, 1) void gemm_mma(const float* __restrict__ f1arg,
                                                   float* __restrict__ Yarg) {
    constexpr int KDIM = (LAYER == 0) ? CIN : CO;
    constexpr int NKB  = KDIM / 64;
    const bf16* __restrict__ Whi = (LAYER == 0) ? g_w0hi : g_w1hi;
    const bf16* __restrict__ Wlo = (LAYER == 0) ? g_w0lo : g_w1lo;
    float* __restrict__ Y = (LAYER == 0) ? g_y0 : Yarg;

    extern __shared__ __align__(16) char smem[];
    int* sidx = (int*)(smem + SIDX_OFF);

    const int tid = threadIdx.x, wid = tid >> 5, lane = tid & 31;
    const int bx = blockIdx.x;
    const int b  = bx >> 6;
    const int n0 = (bx & 63) << 7;
    const int o0 = blockIdx.y << 7;

    const int warp_o = (wid & 3) * 32;
    const int warp_n = (wid >> 2) * 64;

    const uint32_t sb = smem_u32(smem);
    const int arow = warp_o + (lane & 15);
    const int acol = (lane >> 4) * 8;
    const uint32_t aW_off = (uint32_t)(arow * PADK + acol) * 2;
    const int krow = (lane & 7) + ((lane >> 3) & 1) * 8;
    const int noff = warp_n + ((lane >> 4) & 1) * 8;
    const uint32_t aXt_off = (uint32_t)(krow * PADN + noff) * 2;

    if (LAYER == 0 && tid < 128) sidx[tid] = g_idx[b * NN_ + n0 + tid];

    float acc[2][8][4] = {};
    float4 v[8];

    // ---- pipeline stage helpers ----
    auto cp_w = [&](int buf, int k0) {
        const uint32_t wb = sb + buf * WBUF_STRIDE;
#pragma unroll
        for (int it = 0; it < 4; ++it) {
            const int i = tid + it * 256;
            const int row = i >> 3, seg = i & 7;
            const uint32_t so = (uint32_t)(row * PADK + seg * 8) * 2;
            const size_t wk = (size_t)(o0 + row) * KDIM + k0 + seg * 8;
            CP_ASYNC16(wb + so, Whi + wk);
            CP_ASYNC16(wb + W_TILE_B + so, Wlo + wk);
        }
    };
    auto loadX = [&](int k0) {
        if (LAYER == 0 && k0 >= C1) {
            const int n = tid & 127, kh = tid >> 7;
            const float* row = g_f2t + ((size_t)(b * MM) + sidx[n]) * C2 + (k0 - C1) + kh * 32;
#pragma unroll
            for (int q = 0; q < 8; ++q) v[q] = *(const float4*)(row + q * 4);
        } else {
            const int r = tid >> 2, qn = (tid & 3) << 5;
            const float* src = (LAYER == 0)
                ? f1arg + ((size_t)(b * C1) + k0 + r) * NN_ + n0 + qn
                : g_y0 + ((size_t)(b * CO) + k0 + r) * NN_ + n0 + qn;
#pragma unroll
            for (int q = 0; q < 8; ++q) v[q] = *(const float4*)(src + q * 4);
        }
    };
    auto storeX = [&](int k0, int buf) {
        bf16* xh = (bf16*)(smem + XBUF_OFF + buf * XBUF_STRIDE);
        bf16* xl = (bf16*)((char*)xh + XT_TILE_B);
        if (LAYER == 0 && k0 >= C1) {
            const int n = tid & 127, kh = tid >> 7;
            const float* f = (const float*)v;
#pragma unroll
            for (int q = 0; q < 32; ++q) {
                bf16 h, l;
                split1(f[q], h, l);
                const int kr = kh * 32 + q;
                xh[kr * PADN + n] = h;
                xl[kr * PADN + n] = l;
            }
        } else {
            const int r = tid >> 2, qn = (tid & 3) << 5;
            float a = 1.f, b2 = 0.f;
            if (LAYER == 1) { a = g_ab0[k0 + r]; b2 = g_ab0[CO + k0 + r]; }
            bf16* dh = xh + r * PADN + qn;
            bf16* dl = xl + r * PADN + qn;
#pragma unroll
            for (int q = 0; q < 4; ++q) {
                float4 fA = v[2 * q], fB = v[2 * q + 1];
                float x0, x1, x2, x3, x4, x5, x6, x7;
                if (LAYER == 0) {
                    x0 = fA.x; x1 = fA.y; x2 = fA.z; x3 = fA.w;
                    x4 = fB.x; x5 = fB.y; x6 = fB.z; x7 = fB.w;
                } else {
                    x0 = fmaxf(fmaf(a, fA.x, b2), 0.f);
                    x1 = fmaxf(fmaf(a, fA.y, b2), 0.f);
                    x2 = fmaxf(fmaf(a, fA.z, b2), 0.f);
                    x3 = fmaxf(fmaf(a, fA.w, b2), 0.f);
                    x4 = fmaxf(fmaf(a, fB.x, b2), 0.f);
                    x5 = fmaxf(fmaf(a, fB.y, b2), 0.f);
                    x6 = fmaxf(fmaf(a, fB.z, b2), 0.f);
                    x7 = fmaxf(fmaf(a, fB.w, b2), 0.f);
                }
                uint32_t h0, h1, h2, h3, l0, l1, l2, l3;
                split2(x0, x1, h0, l0); split2(x2, x3, h1, l1);
                split2(x4, x5, h2, l2); split2(x6, x7, h3, l3);
                *(uint4*)(dh + q * 8) = make_uint4(h0, h1, h2, h3);
                *(uint4*)(dl + q * 8) = make_uint4(l0, l1, l2, l3);
            }
        }
    };
    auto mma_blk = [&](int buf) {
        const uint32_t aWhi = sb + buf * WBUF_STRIDE + aW_off;
        const uint32_t aWlo = aWhi + W_TILE_B;
        const uint32_t aXthi = sb + XBUF_OFF + buf * XBUF_STRIDE + aXt_off;
        const uint32_t aXtlo = aXthi + XT_TILE_B;
#pragma unroll
        for (int kk = 0; kk < 4; ++kk) {
            uint32_t ah[2][4], al[2][4];
#pragma unroll
            for (int t = 0; t < 2; ++t) {
                const uint32_t ro = t * 16 * PADK * 2 + kk * 32;
                ldsm4(ah[t][0], ah[t][1], ah[t][2], ah[t][3], aWhi + ro);
                ldsm4(al[t][0], al[t][1], al[t][2], al[t][3], aWlo + ro);
            }
            uint32_t bh[4][4], bl[4][4];
#pragma unroll
            for (int u = 0; u < 4; ++u) {
                const uint32_t ro = kk * 16 * PADN * 2 + u * 32;
                ldsm4t(bh[u][0], bh[u][1], bh[u][2], bh[u][3], aXthi + ro);
                ldsm4t(bl[u][0], bl[u][1], bl[u][2], bl[u][3], aXtlo + ro);
            }
#pragma unroll
            for (int t = 0; t < 2; ++t)
#pragma unroll
                for (int j = 0; j < 8; ++j) {
                    const uint32_t* ph = &bh[j >> 1][(j & 1) * 2];
                    const uint32_t* pl = &bl[j >> 1][(j & 1) * 2];
                    mma16816(acc[t][j], ah[t], ph);
                    mma16816(acc[t][j], ah[t], pl);
                    mma16816(acc[t][j], al[t], ph);
                }
        }
    };

    // ---- prologue ----
    cp_w(0, 0);  CP_COMMIT();
    loadX(0);
    storeX(0, 0);
    cp_w(1, 64); CP_COMMIT();
    loadX(64);
    CP_WAIT1();          // W block 0 complete
    __syncthreads();     // X block 0 + sidx visible

    // ---- main pipeline ----
    for (int kb = 0; kb < NKB; ++kb) {
        mma_blk(kb & 1);
        if (kb + 1 < NKB) {
            __syncthreads();                       // all reads of buf kb&1 done
            storeX((kb + 1) * 64, (kb + 1) & 1);   // convert prefetched regs
            if (kb + 2 < NKB) {
                cp_w(kb & 1, (kb + 2) * 64); CP_COMMIT();
                loadX((kb + 2) * 64);
                CP_WAIT1();                        // W block kb+1 complete
            } else {
                CP_WAIT0();
            }
            __syncthreads();                       // X block kb+1 visible
        }
    }

    // ---- Y store ----
    const int orow = o0 + warp_o + (lane >> 2);
    const int ncol = n0 + warp_n + (lane & 3) * 2;
#pragma unroll
    for (int t = 0; t < 2; ++t) {
        float* d0 = Y + ((size_t)(b * CO) + orow + t * 16) * NN_ + ncol;
        float* d1 = d0 + 8 * NN_;
#pragma unroll
        for (int j = 0; j < 8; ++j) {
            *(float2*)(d0 + j * 8) = make_float2(acc[t][j][0], acc[t][j][1]);
            *(float2*)(d1 + j * 8) = make_float2(acc[t][j][2], acc[t][j][3]);
        }
    }

    // ---- deterministic stats partials ----
    float rs[4] = {}, rq[4] = {};
#pragma unroll
    for (int t = 0; t < 2; ++t)
#pragma unroll
        for (int j = 0; j < 8; ++j) {
            rs[t * 2 + 0] += acc[t][j][0] + acc[t][j][1];
            rq[t * 2 + 0] += acc[t][j][0] * acc[t][j][0] + acc[t][j][1] * acc[t][j][1];
            rs[t * 2 + 1] += acc[t][j][2] + acc[t][j][3];
            rq[t * 2 + 1] += acc[t][j][2] * acc[t][j][2] + acc[t][j][3] * acc[t][j][3];
        }
#pragma unroll
    for (int w = 0; w < 4; ++w) {
        rs[w] += __shfl_xor_sync(0xffffffffu, rs[w], 1);
        rs[w] += __shfl_xor_sync(0xffffffffu, rs[w], 2);
        rq[w] += __shfl_xor_sync(0xffffffffu, rq[w], 1);
        rq[w] += __shfl_xor_sync(0xffffffffu, rq[w], 2);
    }
    __syncthreads();
    float* sSum = (float*)smem;        // [2][128]
    float* sSq  = sSum + 256;
    if ((lane & 3) == 0) {
        const int h = (wid >> 2) * 128;
        const int g = warp_o + (lane >> 2);
        sSum[h + g]      = rs[0];
        sSum[h + g + 8]  = rs[1];
        sSum[h + g + 16] = rs[2];
        sSum[h + g + 24] = rs[3];
        sSq[h + g]       = rq[0];
        sSq[h + g + 8]   = rq[1];
        sSq[h + g + 16]  = rq[2];
        sSq[h + g + 24]  = rq[3];
    }
    __syncthreads();
    if (tid < 128) {
        g_psum[(size_t)(o0 + tid) * NBX + bx] = sSum[tid] + sSum[128 + tid];
        g_psq[(size_t)(o0 + tid) * NBX + bx]  = sSq[tid] + sSq[128 + tid];
    }
}

// ---------------- 5) stats reduce: partials -> BN affine ------------------
template <int LAYER>
__global__ __launch_bounds__(256) void stats_reduce(const float* __restrict__ gamma,
                                                    const float* __restrict__ beta) {
    const int o = blockIdx.x, tid = threadIdx.x;
    float s = g_psum[(size_t)o * NBX + tid] + g_psum[(size_t)o * NBX + 256 + tid];
    float q = g_psq[(size_t)o * NBX + tid] + g_psq[(size_t)o * NBX + 256 + tid];
    __shared__ float ss[256], sq[256];
    ss[tid] = s; sq[tid] = q;
    __syncthreads();
    for (int st = 128; st > 0; st >>= 1) {
        if (tid < st) { ss[tid] += ss[tid + st]; sq[tid] += sq[tid + st]; }
        __syncthreads();
    }
    if (tid == 0) {
        const float inv = 1.f / (float)(BB * NN_);
        const float mu  = ss[0] * inv;
        const float var = sq[0] * inv - mu * mu;
        const float a   = gamma[o] * rsqrtf(var + 1e-5f);
        float* ab = (LAYER == 0) ? g_ab0 : g_ab1;
        ab[o]      = a;
        ab[CO + o] = beta[o] - mu * a;
    }
}

// ---------------- 6) final BN1 + ReLU in place on d_out ------------------
__global__ __launch_bounds__(256) void bnrelu_kernel(float* __restrict__ y) {
    const size_t i = ((size_t)blockIdx.x * blockDim.x + threadIdx.x) * 4;
    const int c = (int)((i >> 13) & (CO - 1));
    const float a = g_ab1[c], bb = g_ab1[CO + c];
    float4 v = *(float4*)(y + i);
    v.x = fmaxf(fmaf(a, v.x, bb), 0.f);
    v.y = fmaxf(fmaf(a, v.y, bb), 0.f);
    v.z = fmaxf(fmaf(a, v.z, bb), 0.f);
    v.w = fmaxf(fmaf(a, v.w, bb), 0.f);
    *(float4*)(y + i) = v;
}

// ---------------- launcher ------------------------------------------------
extern "C" void kernel_launch(void* const* d_in, const int* in_sizes, int n_in,
                              void* d_out, int out_size) {
    const float* xyz1   = (const float*)d_in[0];
    const float* xyz2   = (const float*)d_in[1];
    const float* f1     = (const float*)d_in[2];
    const float* f2     = (const float*)d_in[3];
    const float* w0     = (const float*)d_in[4];
    const float* gamma0 = (const float*)d_in[5];
    const float* beta0  = (const float*)d_in[6];
    const float* w1     = (const float*)d_in[7];
    const float* gamma1 = (const float*)d_in[8];
    const float* beta1  = (const float*)d_in[9];
    float* out = (float*)d_out;

    cudaFuncSetAttribute(gemm_mma<0>, cudaFuncAttributeMaxDynamicSharedMemorySize, GEMM_SMEM);
    cudaFuncSetAttribute(gemm_mma<1>, cudaFuncAttributeMaxDynamicSharedMemorySize, GEMM_SMEM);

    nn_kernel<<<dim3(NN_ / 512, BB), 256>>>(xyz1, xyz2);
    prep_w<<<(CO * CIN + 255) / 256, 256>>>(w0, w1);
    prep_f2t<<<dim3(MM / 32, C2 / 32, BB), dim3(32, 8)>>>(f2);

    gemm_mma<0><<<dim3(NBX, CO / 128), 256, GEMM_SMEM>>>(f1, nullptr);
    stats_reduce<0><<<CO, 256>>>(gamma0, beta0);

    gemm_mma<1><<<dim3(NBX, CO / 128), 256, GEMM_SMEM>>>(nullptr, out);
    stats_reduce<1><<<CO, 256>>>(gamma1, beta1);

    bnrelu_kernel<<<(BB * CO * NN_) / (4 * 256), 256>>>(out);
}

// round 9
// speedup vs baseline: 2.5140x; 1.1778x over previous
#include <cuda_runtime.h>
#include <cuda_fp16.h>
#include <cstdint>

#define BB 8
#define NN_ 8192
#define MM 2048
#define C1 128
#define C2 256
#define CIN 384
#define CO 256
#define NBX 512            // BB * (NN_/128) gemm n-tiles

typedef unsigned long long ull;

// ---------------- device scratch (no allocations allowed) ----------------
__device__ int    g_idx[BB * NN_];
__device__ float  g_y0[(size_t)BB * CO * NN_];       // pre-BN output of layer 0
__device__ float  g_ab0[2 * CO];
__device__ float  g_ab1[2 * CO];
__device__ float  g_f2t[(size_t)BB * MM * C2];       // f2 transposed [b][m][c2]
__device__ __half g_w0hi[CO * CIN], g_w0lo[CO * CIN];
__device__ __half g_w1hi[CO * CO],  g_w1lo[CO * CO];
__device__ float  g_psum[CO * NBX];
__device__ float  g_psq[CO * NBX];

// ---------------- helpers -------------------------------------------------
__device__ __forceinline__ ull f2_add(ull a, ull b) {
    ull r; asm("add.rn.f32x2 %0, %1, %2;" : "=l"(r) : "l"(a), "l"(b)); return r;
}
__device__ __forceinline__ ull f2_mul(ull a, ull b) {
    ull r; asm("mul.rn.f32x2 %0, %1, %2;" : "=l"(r) : "l"(a), "l"(b)); return r;
}
__device__ __forceinline__ ull f2_pack(float lo, float hi) {
    ull r; asm("mov.b64 %0, {%1, %2};" : "=l"(r) : "f"(lo), "f"(hi)); return r;
}
__device__ __forceinline__ void f2_unpack(float& lo, float& hi, ull v) {
    asm("mov.b64 {%0, %1}, %2;" : "=f"(lo), "=f"(hi) : "l"(v));
}
__device__ __forceinline__ uint32_t smem_u32(const void* p) {
    uint32_t a;
    asm("{ .reg .u64 t; cvta.to.shared.u64 t, %1; cvt.u32.u64 %0, t; }" : "=r"(a) : "l"(p));
    return a;
}
__device__ __forceinline__ void ldsm4(uint32_t& r0, uint32_t& r1, uint32_t& r2, uint32_t& r3,
                                      uint32_t addr) {
    asm volatile("ldmatrix.sync.aligned.m8n8.x4.shared.b16 {%0,%1,%2,%3}, [%4];"
                 : "=r"(r0), "=r"(r1), "=r"(r2), "=r"(r3) : "r"(addr));
}
__device__ __forceinline__ void ldsm4t(uint32_t& r0, uint32_t& r1, uint32_t& r2, uint32_t& r3,
                                       uint32_t addr) {
    asm volatile("ldmatrix.sync.aligned.m8n8.x4.trans.shared.b16 {%0,%1,%2,%3}, [%4];"
                 : "=r"(r0), "=r"(r1), "=r"(r2), "=r"(r3) : "r"(addr));
}
__device__ __forceinline__ void mma16816(float* c, const uint32_t* a, const uint32_t* b) {
    asm volatile("mma.sync.aligned.m16n8k16.row.col.f32.f16.f16.f32 "
                 "{%0,%1,%2,%3}, {%4,%5,%6,%7}, {%8,%9}, {%0,%1,%2,%3};"
                 : "+f"(c[0]), "+f"(c[1]), "+f"(c[2]), "+f"(c[3])
                 : "r"(a[0]), "r"(a[1]), "r"(a[2]), "r"(a[3]), "r"(b[0]), "r"(b[1]));
}
__device__ __forceinline__ uint32_t h2u(float a, float b) {
    __half2 h = __halves2half2(__float2half_rn(a), __float2half_rn(b));
    return *(uint32_t*)&h;
}
#define CP_ASYNC16(saddr, gptr) \
    asm volatile("cp.async.cg.shared.global [%0], [%1], 16;" :: "r"(saddr), "l"(gptr))
#define CP_COMMIT() asm volatile("cp.async.commit_group;" ::: "memory")
#define CP_WAIT0()  asm volatile("cp.async.wait_group 0;" ::: "memory")
#define CP_WAIT1()  asm volatile("cp.async.wait_group 1;" ::: "memory")

// ---------------- 1) nearest neighbor (bitwise-matching argmin) ----------
__global__ __launch_bounds__(256) void nn_kernel(const float* __restrict__ xyz1,
                                                 const float* __restrict__ xyz2) {
    __shared__ __align__(16) float nq[3][MM];
    const int b  = blockIdx.y;
    const int n0 = blockIdx.x * 512;
    const int tid = threadIdx.x;

    const float* x2 = xyz2 + (size_t)b * MM * 3;
    for (int m = tid; m < MM; m += 256) {
        nq[0][m] = -x2[3 * m + 0];
        nq[1][m] = -x2[3 * m + 1];
        nq[2][m] = -x2[3 * m + 2];
    }
    __syncthreads();

    const ull* qx2 = (const ull*)nq[0];
    const ull* qy2 = (const ull*)nq[1];
    const ull* qz2 = (const ull*)nq[2];

    const int ng0 = n0 + tid;
    const int ng1 = n0 + tid + 256;
    const float* p0 = xyz1 + ((size_t)b * NN_ + ng0) * 3;
    const float* p1 = xyz1 + ((size_t)b * NN_ + ng1) * 3;

    const ull px0 = f2_pack(p0[0], p0[0]), py0 = f2_pack(p0[1], p0[1]), pz0 = f2_pack(p0[2], p0[2]);
    const ull px1 = f2_pack(p1[0], p1[0]), py1 = f2_pack(p1[1], p1[1]), pz1 = f2_pack(p1[2], p1[2]);

    float be0 = 3.0e38f, bo0 = 3.0e38f, be1 = 3.0e38f, bo1 = 3.0e38f;
    int   ie0 = 0, io0 = 1, ie1 = 0, io1 = 1;

#pragma unroll 8
    for (int m2 = 0; m2 < MM / 2; ++m2) {
        const ull qx = qx2[m2], qy = qy2[m2], qz = qz2[m2];
        {
            ull dx = f2_add(px0, qx), dy = f2_add(py0, qy), dz = f2_add(pz0, qz);
            ull d  = f2_add(f2_add(f2_mul(dx, dx), f2_mul(dy, dy)), f2_mul(dz, dz));
            float dl, dh; f2_unpack(dl, dh, d);
            const bool pe = dl < be0, po = dh < bo0;
            be0 = pe ? dl : be0; ie0 = pe ? 2 * m2 : ie0;
            bo0 = po ? dh : bo0; io0 = po ? 2 * m2 + 1 : io0;
        }
        {
            ull dx = f2_add(px1, qx), dy = f2_add(py1, qy), dz = f2_add(pz1, qz);
            ull d  = f2_add(f2_add(f2_mul(dx, dx), f2_mul(dy, dy)), f2_mul(dz, dz));
            float dl, dh; f2_unpack(dl, dh, d);
            const bool pe = dl < be1, po = dh < bo1;
            be1 = pe ? dl : be1; ie1 = pe ? 2 * m2 : ie1;
            bo1 = po ? dh : bo1; io1 = po ? 2 * m2 + 1 : io1;
        }
    }
    int bi0 = ie0;
    if (bo0 < be0 || (bo0 == be0 && io0 < ie0)) bi0 = io0;
    int bi1 = ie1;
    if (bo1 < be1 || (bo1 == be1 && io1 < ie1)) bi1 = io1;

    g_idx[b * NN_ + ng0] = bi0;
    g_idx[b * NN_ + ng1] = bi1;
}

// ---------------- 2) weight split (fp16 hi/lo) ----------------------------
__global__ __launch_bounds__(256) void prep_w(const float* __restrict__ w0,
                                              const float* __restrict__ w1) {
    const int i = blockIdx.x * 256 + threadIdx.x;
    if (i < CO * CIN) {
        float v = w0[i];
        __half h = __float2half_rn(v);
        g_w0hi[i] = h;
        g_w0lo[i] = __float2half_rn(v - __half2float(h));
    }
    if (i < CO * CO) {
        float v = w1[i];
        __half h = __float2half_rn(v);
        g_w1hi[i] = h;
        g_w1lo[i] = __float2half_rn(v - __half2float(h));
    }
}

// ---------------- 3) transpose f2 -> [b][m][c2] ---------------------------
__global__ void prep_f2t(const float* __restrict__ f2) {
    __shared__ float t[32][33];
    const int b = blockIdx.z, m0 = blockIdx.x * 32, c0 = blockIdx.y * 32;
    const int tx = threadIdx.x, ty = threadIdx.y;  // 32x8
#pragma unroll
    for (int k = 0; k < 4; k++)
        t[ty + 8 * k][tx] = f2[((size_t)(b * C2) + c0 + ty + 8 * k) * MM + m0 + tx];
    __syncthreads();
#pragma unroll
    for (int k = 0; k < 4; k++)
        g_f2t[((size_t)(b * MM) + m0 + ty + 8 * k) * C2 + c0 + tx] = t[tx][ty + 8 * k];
}

// ---------------- 4) pipelined HMMA GEMM (fp16, W-split, X-single) --------
// 512 threads, 16 warps (8 o x 2 n), warp tile 16(o) x 64(n), CTA 128x128.
// 2 MMAs per k16: Whi*X + Wlo*X, fp32 accumulate. X single fp16 tile.
// W: cp.async double-buffered. X: register prefetch k+2, trans-ldmatrix.
#define PADK 72
#define PADN 136
#define W_TILE_B    (128 * PADK * 2)        // 18432 (hi or lo)
#define WBUF_STRIDE (2 * W_TILE_B)          // 36864
#define XBUF_OFF    (2 * WBUF_STRIDE)       // 73728
#define XT_TILE_B   (64 * PADN * 2)         // 17408 (hi only)
#define SIDX_OFF    (XBUF_OFF + 2 * XT_TILE_B)  // 108544
#define GEMM_SMEM   (SIDX_OFF + 512)        // 109056

template <int LAYER>
__global__ __launch_bounds__(512, 1) void gemm_mma(const float* __restrict__ f1arg,
                                                   float* __restrict__ Yarg) {
    constexpr int KDIM = (LAYER == 0) ? CIN : CO;
    constexpr int NKB  = KDIM / 64;
    const __half* __restrict__ Whi = (LAYER == 0) ? g_w0hi : g_w1hi;
    const __half* __restrict__ Wlo = (LAYER == 0) ? g_w0lo : g_w1lo;
    float* __restrict__ Y = (LAYER == 0) ? g_y0 : Yarg;

    extern __shared__ __align__(16) char smem[];
    int* sidx = (int*)(smem + SIDX_OFF);

    const int tid = threadIdx.x, wid = tid >> 5, lane = tid & 31;
    const int bx = blockIdx.x;
    const int b  = bx >> 6;
    const int n0 = (bx & 63) << 7;
    const int o0 = blockIdx.y << 7;

    const int warp_o = (wid & 7) * 16;
    const int warp_n = (wid >> 3) * 64;

    const uint32_t sb = smem_u32(smem);
    const int arow = warp_o + (lane & 15);
    const int acol = (lane >> 4) * 8;
    const uint32_t aW_off = (uint32_t)(arow * PADK + acol) * 2;
    const int krow = (lane & 7) + ((lane >> 3) & 1) * 8;
    const int noff = warp_n + ((lane >> 4) & 1) * 8;
    const uint32_t aXt_off = (uint32_t)(krow * PADN + noff) * 2;

    if (LAYER == 0 && tid < 128) sidx[tid] = g_idx[b * NN_ + n0 + tid];

    float acc[8][4] = {};
    float4 v[4];

    auto cp_w = [&](int buf, int k0) {
        const uint32_t wb = sb + buf * WBUF_STRIDE;
#pragma unroll
        for (int it = 0; it < 2; ++it) {
            const int i = tid + it * 512;
            const int row = i >> 3, seg = i & 7;
            const uint32_t so = (uint32_t)(row * PADK + seg * 8) * 2;
            const size_t wk = (size_t)(o0 + row) * KDIM + k0 + seg * 8;
            CP_ASYNC16(wb + so, Whi + wk);
            CP_ASYNC16(wb + W_TILE_B + so, Wlo + wk);
        }
    };
    auto loadX = [&](int k0) {
        if (LAYER == 0 && k0 >= C1) {
            const int n = tid & 127, kq = tid >> 7;   // kq: 0..3, 16 k's each
            const float* row = g_f2t + ((size_t)(b * MM) + sidx[n]) * C2 + (k0 - C1) + kq * 16;
#pragma unroll
            for (int q = 0; q < 4; ++q) v[q] = *(const float4*)(row + q * 4);
        } else {
            const int r = tid >> 3, qn = (tid & 7) << 4;
            const float* src = (LAYER == 0)
                ? f1arg + ((size_t)(b * C1) + k0 + r) * NN_ + n0 + qn
                : g_y0 + ((size_t)(b * CO) + k0 + r) * NN_ + n0 + qn;
#pragma unroll
            for (int q = 0; q < 4; ++q) v[q] = *(const float4*)(src + q * 4);
        }
    };
    auto storeX = [&](int k0, int buf) {
        __half* xh = (__half*)(smem + XBUF_OFF + buf * XT_TILE_B);
        if (LAYER == 0 && k0 >= C1) {
            const int n = tid & 127, kq = tid >> 7;
            const float* f = (const float*)v;
#pragma unroll
            for (int q = 0; q < 16; ++q)
                xh[(kq * 16 + q) * PADN + n] = __float2half_rn(f[q]);
        } else {
            const int r = tid >> 3, qn = (tid & 7) << 4;
            float a = 1.f, b2 = 0.f;
            if (LAYER == 1) { a = g_ab0[k0 + r]; b2 = g_ab0[CO + k0 + r]; }
            const float* f = (const float*)v;
            float x[16];
#pragma unroll
            for (int q = 0; q < 16; ++q)
                x[q] = (LAYER == 0) ? f[q] : fmaxf(fmaf(a, f[q], b2), 0.f);
            uint32_t u[8];
#pragma unroll
            for (int q = 0; q < 8; ++q) u[q] = h2u(x[2 * q], x[2 * q + 1]);
            __half* dh = xh + r * PADN + qn;
            *(uint4*)dh       = make_uint4(u[0], u[1], u[2], u[3]);
            *(uint4*)(dh + 8) = make_uint4(u[4], u[5], u[6], u[7]);
        }
    };
    auto mma_blk = [&](int buf) {
        const uint32_t aWhi = sb + buf * WBUF_STRIDE + aW_off;
        const uint32_t aWlo = aWhi + W_TILE_B;
        const uint32_t aXt  = sb + XBUF_OFF + buf * XT_TILE_B + aXt_off;
#pragma unroll
        for (int kk = 0; kk < 4; ++kk) {
            uint32_t ah[4], al[4];
            ldsm4(ah[0], ah[1], ah[2], ah[3], aWhi + kk * 32);
            ldsm4(al[0], al[1], al[2], al[3], aWlo + kk * 32);
            uint32_t bh[4][4];
#pragma unroll
            for (int u = 0; u < 4; ++u)
                ldsm4t(bh[u][0], bh[u][1], bh[u][2], bh[u][3],
                       aXt + kk * 16 * PADN * 2 + u * 32);
#pragma unroll
            for (int j = 0; j < 8; ++j) {
                const uint32_t* pb = &bh[j >> 1][(j & 1) * 2];
                mma16816(acc[j], ah, pb);
                mma16816(acc[j], al, pb);
            }
        }
    };

    // ---- prologue ----
    cp_w(0, 0);  CP_COMMIT();
    loadX(0);
    storeX(0, 0);
    cp_w(1, 64); CP_COMMIT();
    loadX(64);
    CP_WAIT1();
    __syncthreads();

    // ---- main pipeline ----
    for (int kb = 0; kb < NKB; ++kb) {
        mma_blk(kb & 1);
        if (kb + 1 < NKB) {
            __syncthreads();
            storeX((kb + 1) * 64, (kb + 1) & 1);
            if (kb + 2 < NKB) {
                cp_w(kb & 1, (kb + 2) * 64); CP_COMMIT();
                loadX((kb + 2) * 64);
                CP_WAIT1();
            } else {
                CP_WAIT0();
            }
            __syncthreads();
        }
    }

    // ---- Y store ----
    const int orow = o0 + warp_o + (lane >> 2);
    const int ncol = n0 + warp_n + (lane & 3) * 2;
    float* d0 = Y + ((size_t)(b * CO) + orow) * NN_ + ncol;
    float* d1 = d0 + 8 * NN_;
#pragma unroll
    for (int j = 0; j < 8; ++j) {
        *(float2*)(d0 + j * 8) = make_float2(acc[j][0], acc[j][1]);
        *(float2*)(d1 + j * 8) = make_float2(acc[j][2], acc[j][3]);
    }

    // ---- deterministic stats partials ----
    float rs[2] = {}, rq[2] = {};
#pragma unroll
    for (int j = 0; j < 8; ++j) {
        rs[0] += acc[j][0] + acc[j][1];
        rq[0] += acc[j][0] * acc[j][0] + acc[j][1] * acc[j][1];
        rs[1] += acc[j][2] + acc[j][3];
        rq[1] += acc[j][2] * acc[j][2] + acc[j][3] * acc[j][3];
    }
#pragma unroll
    for (int w = 0; w < 2; ++w) {
        rs[w] += __shfl_xor_sync(0xffffffffu, rs[w], 1);
        rs[w] += __shfl_xor_sync(0xffffffffu, rs[w], 2);
        rq[w] += __shfl_xor_sync(0xffffffffu, rq[w], 1);
        rq[w] += __shfl_xor_sync(0xffffffffu, rq[w], 2);
    }
    __syncthreads();
    float* sSum = (float*)smem;        // [2 n-halves][128 rows]
    float* sSq  = sSum + 256;
    if ((lane & 3) == 0) {
        const int h = (wid >> 3) * 128;
        const int g = warp_o + (lane >> 2);
        sSum[h + g]     = rs[0];
        sSum[h + g + 8] = rs[1];
        sSq[h + g]      = rq[0];
        sSq[h + g + 8]  = rq[1];
    }
    __syncthreads();
    if (tid < 128) {
        g_psum[(size_t)(o0 + tid) * NBX + bx] = sSum[tid] + sSum[128 + tid];
        g_psq[(size_t)(o0 + tid) * NBX + bx]  = sSq[tid] + sSq[128 + tid];
    }
}

// ---------------- 5) stats reduce: partials -> BN affine ------------------
template <int LAYER>
__global__ __launch_bounds__(256) void stats_reduce(const float* __restrict__ gamma,
                                                    const float* __restrict__ beta) {
    const int o = blockIdx.x, tid = threadIdx.x;
    float s = g_psum[(size_t)o * NBX + tid] + g_psum[(size_t)o * NBX + 256 + tid];
    float q = g_psq[(size_t)o * NBX + tid] + g_psq[(size_t)o * NBX + 256 + tid];
    __shared__ float ss[256], sq[256];
    ss[tid] = s; sq[tid] = q;
    __syncthreads();
    for (int st = 128; st > 0; st >>= 1) {
        if (tid < st) { ss[tid] += ss[tid + st]; sq[tid] += sq[tid + st]; }
        __syncthreads();
    }
    if (tid == 0) {
        const float inv = 1.f / (float)(BB * NN_);
        const float mu  = ss[0] * inv;
        const float var = sq[0] * inv - mu * mu;
        const float a   = gamma[o] * rsqrtf(var + 1e-5f);
        float* ab = (LAYER == 0) ? g_ab0 : g_ab1;
        ab[o]      = a;
        ab[CO + o] = beta[o] - mu * a;
    }
}

// ---------------- 6) final BN1 + ReLU in place on d_out ------------------
__global__ __launch_bounds__(256) void bnrelu_kernel(float* __restrict__ y) {
    const size_t i = ((size_t)blockIdx.x * blockDim.x + threadIdx.x) * 4;
    const int c = (int)((i >> 13) & (CO - 1));
    const float a = g_ab1[c], bb = g_ab1[CO + c];
    float4 v = *(float4*)(y + i);
    v.x = fmaxf(fmaf(a, v.x, bb), 0.f);
    v.y = fmaxf(fmaf(a, v.y, bb), 0.f);
    v.z = fmaxf(fmaf(a, v.z, bb), 0.f);
    v.w = fmaxf(fmaf(a, v.w, bb), 0.f);
    *(float4*)(y + i) = v;
}

// ---------------- launcher ------------------------------------------------
extern "C" void kernel_launch(void* const* d_in, const int* in_sizes, int n_in,
                              void* d_out, int out_size) {
    const float* xyz1   = (const float*)d_in[0];
    const float* xyz2   = (const float*)d_in[1];
    const float* f1     = (const float*)d_in[2];
    const float* f2     = (const float*)d_in[3];
    const float* w0     = (const float*)d_in[4];
    const float* gamma0 = (const float*)d_in[5];
    const float* beta0  = (const float*)d_in[6];
    const float* w1     = (const float*)d_in[7];
    const float* gamma1 = (const float*)d_in[8];
    const float* beta1  = (const float*)d_in[9];
    float* out = (float*)d_out;

    cudaFuncSetAttribute(gemm_mma<0>, cudaFuncAttributeMaxDynamicSharedMemorySize, GEMM_SMEM);
    cudaFuncSetAttribute(gemm_mma<1>, cudaFuncAttributeMaxDynamicSharedMemorySize, GEMM_SMEM);

    nn_kernel<<<dim3(NN_ / 512, BB), 256>>>(xyz1, xyz2);
    prep_w<<<(CO * CIN + 255) / 256, 256>>>(w0, w1);
    prep_f2t<<<dim3(MM / 32, C2 / 32, BB), dim3(32, 8)>>>(f2);

    gemm_mma<0><<<dim3(NBX, CO / 128), 512, GEMM_SMEM>>>(f1, nullptr);
    stats_reduce<0><<<CO, 256>>>(gamma0, beta0);

    gemm_mma<1><<<dim3(NBX, CO / 128), 512, GEMM_SMEM>>>(nullptr, out);
    stats_reduce<1><<<CO, 256>>>(gamma1, beta1);

    bnrelu_kernel<<<(BB * CO * NN_) / (4 * 256), 256>>>(out);
}

// round 10
// speedup vs baseline: 2.7121x; 1.0788x over previous
#include <cuda_runtime.h>
#include <cuda_fp16.h>
#include <cstdint>

#define BB 8
#define NN_ 8192
#define MM 2048
#define C1 128
#define C2 256
#define CIN 384
#define CO 256
#define NBX 512            // BB * (NN_/128) gemm n-tiles

typedef unsigned long long ull;

// ---------------- device scratch (no allocations allowed) ----------------
__device__ int    g_idx[BB * NN_];
__device__ float  g_y0[(size_t)BB * CO * NN_];       // pre-BN output of layer 0
__device__ float  g_ab0[2 * CO];
__device__ float  g_ab1[2 * CO];
__device__ float  g_f2t[(size_t)BB * MM * C2];       // f2 transposed [b][m][c2]
__device__ __half g_w0hi[CO * CIN], g_w0lo[CO * CIN];
__device__ __half g_w1hi[CO * CO],  g_w1lo[CO * CO];
__device__ float  g_psum[CO * NBX];
__device__ float  g_psq[CO * NBX];

// ---------------- helpers -------------------------------------------------
__device__ __forceinline__ ull f2_add(ull a, ull b) {
    ull r; asm("add.rn.f32x2 %0, %1, %2;" : "=l"(r) : "l"(a), "l"(b)); return r;
}
__device__ __forceinline__ ull f2_mul(ull a, ull b) {
    ull r; asm("mul.rn.f32x2 %0, %1, %2;" : "=l"(r) : "l"(a), "l"(b)); return r;
}
__device__ __forceinline__ ull f2_pack(float lo, float hi) {
    ull r; asm("mov.b64 %0, {%1, %2};" : "=l"(r) : "f"(lo), "f"(hi)); return r;
}
__device__ __forceinline__ void f2_unpack(float& lo, float& hi, ull v) {
    asm("mov.b64 {%0, %1}, %2;" : "=f"(lo), "=f"(hi) : "l"(v));
}
__device__ __forceinline__ uint32_t smem_u32(const void* p) {
    uint32_t a;
    asm("{ .reg .u64 t; cvta.to.shared.u64 t, %1; cvt.u32.u64 %0, t; }" : "=r"(a) : "l"(p));
    return a;
}
__device__ __forceinline__ void ldsm4(uint32_t& r0, uint32_t& r1, uint32_t& r2, uint32_t& r3,
                                      uint32_t addr) {
    asm volatile("ldmatrix.sync.aligned.m8n8.x4.shared.b16 {%0,%1,%2,%3}, [%4];"
                 : "=r"(r0), "=r"(r1), "=r"(r2), "=r"(r3) : "r"(addr));
}
__device__ __forceinline__ void ldsm4t(uint32_t& r0, uint32_t& r1, uint32_t& r2, uint32_t& r3,
                                       uint32_t addr) {
    asm volatile("ldmatrix.sync.aligned.m8n8.x4.trans.shared.b16 {%0,%1,%2,%3}, [%4];"
                 : "=r"(r0), "=r"(r1), "=r"(r2), "=r"(r3) : "r"(addr));
}
__device__ __forceinline__ void mma16816(float* c, const uint32_t* a, const uint32_t* b) {
    asm volatile("mma.sync.aligned.m16n8k16.row.col.f32.f16.f16.f32 "
                 "{%0,%1,%2,%3}, {%4,%5,%6,%7}, {%8,%9}, {%0,%1,%2,%3};"
                 : "+f"(c[0]), "+f"(c[1]), "+f"(c[2]), "+f"(c[3])
                 : "r"(a[0]), "r"(a[1]), "r"(a[2]), "r"(a[3]), "r"(b[0]), "r"(b[1]));
}
__device__ __forceinline__ uint32_t h2u(float a, float b) {
    __half2 h = __halves2half2(__float2half_rn(a), __float2half_rn(b));
    return *(uint32_t*)&h;
}
#define CP_ASYNC16(saddr, gptr) \
    asm volatile("cp.async.cg.shared.global [%0], [%1], 16;" :: "r"(saddr), "l"(gptr))
#define CP_COMMIT() asm volatile("cp.async.commit_group;" ::: "memory")
#define CP_WAIT0()  asm volatile("cp.async.wait_group 0;" ::: "memory")

// ---------------- 1) nearest neighbor (bitwise-matching argmin) ----------
__global__ __launch_bounds__(256) void nn_kernel(const float* __restrict__ xyz1,
                                                 const float* __restrict__ xyz2) {
    __shared__ __align__(16) float nq[3][MM];
    const int b  = blockIdx.y;
    const int n0 = blockIdx.x * 512;
    const int tid = threadIdx.x;

    const float* x2 = xyz2 + (size_t)b * MM * 3;
    for (int m = tid; m < MM; m += 256) {
        nq[0][m] = -x2[3 * m + 0];
        nq[1][m] = -x2[3 * m + 1];
        nq[2][m] = -x2[3 * m + 2];
    }
    __syncthreads();

    const ull* qx2 = (const ull*)nq[0];
    const ull* qy2 = (const ull*)nq[1];
    const ull* qz2 = (const ull*)nq[2];

    const int ng0 = n0 + tid;
    const int ng1 = n0 + tid + 256;
    const float* p0 = xyz1 + ((size_t)b * NN_ + ng0) * 3;
    const float* p1 = xyz1 + ((size_t)b * NN_ + ng1) * 3;

    const ull px0 = f2_pack(p0[0], p0[0]), py0 = f2_pack(p0[1], p0[1]), pz0 = f2_pack(p0[2], p0[2]);
    const ull px1 = f2_pack(p1[0], p1[0]), py1 = f2_pack(p1[1], p1[1]), pz1 = f2_pack(p1[2], p1[2]);

    float be0 = 3.0e38f, bo0 = 3.0e38f, be1 = 3.0e38f, bo1 = 3.0e38f;
    int   ie0 = 0, io0 = 1, ie1 = 0, io1 = 1;

#pragma unroll 8
    for (int m2 = 0; m2 < MM / 2; ++m2) {
        const ull qx = qx2[m2], qy = qy2[m2], qz = qz2[m2];
        {
            ull dx = f2_add(px0, qx), dy = f2_add(py0, qy), dz = f2_add(pz0, qz);
            ull d  = f2_add(f2_add(f2_mul(dx, dx), f2_mul(dy, dy)), f2_mul(dz, dz));
            float dl, dh; f2_unpack(dl, dh, d);
            const bool pe = dl < be0, po = dh < bo0;
            be0 = pe ? dl : be0; ie0 = pe ? 2 * m2 : ie0;
            bo0 = po ? dh : bo0; io0 = po ? 2 * m2 + 1 : io0;
        }
        {
            ull dx = f2_add(px1, qx), dy = f2_add(py1, qy), dz = f2_add(pz1, qz);
            ull d  = f2_add(f2_add(f2_mul(dx, dx), f2_mul(dy, dy)), f2_mul(dz, dz));
            float dl, dh; f2_unpack(dl, dh, d);
            const bool pe = dl < be1, po = dh < bo1;
            be1 = pe ? dl : be1; ie1 = pe ? 2 * m2 : ie1;
            bo1 = po ? dh : bo1; io1 = po ? 2 * m2 + 1 : io1;
        }
    }
    int bi0 = ie0;
    if (bo0 < be0 || (bo0 == be0 && io0 < ie0)) bi0 = io0;
    int bi1 = ie1;
    if (bo1 < be1 || (bo1 == be1 && io1 < ie1)) bi1 = io1;

    g_idx[b * NN_ + ng0] = bi0;
    g_idx[b * NN_ + ng1] = bi1;
}

// ---------------- 2) weight split (fp16 hi/lo) ----------------------------
__global__ __launch_bounds__(256) void prep_w(const float* __restrict__ w0,
                                              const float* __restrict__ w1) {
    const int i = blockIdx.x * 256 + threadIdx.x;
    if (i < CO * CIN) {
        float v = w0[i];
        __half h = __float2half_rn(v);
        g_w0hi[i] = h;
        g_w0lo[i] = __float2half_rn(v - __half2float(h));
    }
    if (i < CO * CO) {
        float v = w1[i];
        __half h = __float2half_rn(v);
        g_w1hi[i] = h;
        g_w1lo[i] = __float2half_rn(v - __half2float(h));
    }
}

// ---------------- 3) transpose f2 -> [b][m][c2] ---------------------------
__global__ void prep_f2t(const float* __restrict__ f2) {
    __shared__ float t[32][33];
    const int b = blockIdx.z, m0 = blockIdx.x * 32, c0 = blockIdx.y * 32;
    const int tx = threadIdx.x, ty = threadIdx.y;  // 32x8
#pragma unroll
    for (int k = 0; k < 4; k++)
        t[ty + 8 * k][tx] = f2[((size_t)(b * C2) + c0 + ty + 8 * k) * MM + m0 + tx];
    __syncthreads();
#pragma unroll
    for (int k = 0; k < 4; k++)
        g_f2t[((size_t)(b * MM) + m0 + ty + 8 * k) * C2 + c0 + tx] = t[tx][ty + 8 * k];
}

// ---------------- 4) pipelined HMMA GEMM (fp16, W-split, X-single) --------
// 512 threads, 16 warps (8 o x 2 n), warp tile 16(o) x 64(n), CTA 128x128.
// Single barrier per k-block; feed phase (cp.async W, X convert+STS, LDG
// prefetch) issues between MMA(kk=0) and MMA(kk=1..3) so it lands in the
// tensor pipe's shadow. Buffers: MMA(kb) reads buf kb&1; writers fill
// (kb+1)&1 whose readers finished before the PREVIOUS barrier.
#define PADK 72
#define PADN 136
#define W_TILE_B    (128 * PADK * 2)        // 18432 (hi or lo)
#define WBUF_STRIDE (2 * W_TILE_B)          // 36864
#define XBUF_OFF    (2 * WBUF_STRIDE)       // 73728
#define XT_TILE_B   (64 * PADN * 2)         // 17408 (hi only)
#define SIDX_OFF    (XBUF_OFF + 2 * XT_TILE_B)  // 108544
#define GEMM_SMEM   (SIDX_OFF + 512)        // 109056

template <int LAYER>
__global__ __launch_bounds__(512, 1) void gemm_mma(const float* __restrict__ f1arg,
                                                   float* __restrict__ Yarg) {
    constexpr int KDIM = (LAYER == 0) ? CIN : CO;
    constexpr int NKB  = KDIM / 64;
    const __half* __restrict__ Whi = (LAYER == 0) ? g_w0hi : g_w1hi;
    const __half* __restrict__ Wlo = (LAYER == 0) ? g_w0lo : g_w1lo;
    float* __restrict__ Y = (LAYER == 0) ? g_y0 : Yarg;

    extern __shared__ __align__(16) char smem[];
    int* sidx = (int*)(smem + SIDX_OFF);

    const int tid = threadIdx.x, wid = tid >> 5, lane = tid & 31;
    const int bx = blockIdx.x;
    const int b  = bx >> 6;
    const int n0 = (bx & 63) << 7;
    const int o0 = blockIdx.y << 7;

    const int warp_o = (wid & 7) * 16;
    const int warp_n = (wid >> 3) * 64;

    const uint32_t sb = smem_u32(smem);
    const int arow = warp_o + (lane & 15);
    const int acol = (lane >> 4) * 8;
    const uint32_t aW_off = (uint32_t)(arow * PADK + acol) * 2;
    const int krow = (lane & 7) + ((lane >> 3) & 1) * 8;
    const int noff = warp_n + ((lane >> 4) & 1) * 8;
    const uint32_t aXt_off = (uint32_t)(krow * PADN + noff) * 2;

    if (LAYER == 0 && tid < 128) sidx[tid] = g_idx[b * NN_ + n0 + tid];

    float acc[8][4] = {};
    float4 v[4];

    auto cp_w = [&](int buf, int k0) {
        const uint32_t wb = sb + buf * WBUF_STRIDE;
#pragma unroll
        for (int it = 0; it < 2; ++it) {
            const int i = tid + it * 512;
            const int row = i >> 3, seg = i & 7;
            const uint32_t so = (uint32_t)(row * PADK + seg * 8) * 2;
            const size_t wk = (size_t)(o0 + row) * KDIM + k0 + seg * 8;
            CP_ASYNC16(wb + so, Whi + wk);
            CP_ASYNC16(wb + W_TILE_B + so, Wlo + wk);
        }
    };
    auto loadX = [&](int k0) {
        if (LAYER == 0 && k0 >= C1) {
            const int n = tid & 127, kq = tid >> 7;   // kq: 0..3, 16 k's each
            const float* row = g_f2t + ((size_t)(b * MM) + sidx[n]) * C2 + (k0 - C1) + kq * 16;
#pragma unroll
            for (int q = 0; q < 4; ++q) v[q] = *(const float4*)(row + q * 4);
        } else {
            const int r = tid >> 3, qn = (tid & 7) << 4;
            const float* src = (LAYER == 0)
                ? f1arg + ((size_t)(b * C1) + k0 + r) * NN_ + n0 + qn
                : g_y0 + ((size_t)(b * CO) + k0 + r) * NN_ + n0 + qn;
#pragma unroll
            for (int q = 0; q < 4; ++q) v[q] = *(const float4*)(src + q * 4);
        }
    };
    auto storeX = [&](int k0, int buf) {
        __half* xh = (__half*)(smem + XBUF_OFF + buf * XT_TILE_B);
        if (LAYER == 0 && k0 >= C1) {
            const int n = tid & 127, kq = tid >> 7;
            const float* f = (const float*)v;
#pragma unroll
            for (int q = 0; q < 16; ++q)
                xh[(kq * 16 + q) * PADN + n] = __float2half_rn(f[q]);
        } else {
            const int r = tid >> 3, qn = (tid & 7) << 4;
            float a = 1.f, b2 = 0.f;
            if (LAYER == 1) { a = g_ab0[k0 + r]; b2 = g_ab0[CO + k0 + r]; }
            const float* f = (const float*)v;
            float x[16];
#pragma unroll
            for (int q = 0; q < 16; ++q)
                x[q] = (LAYER == 0) ? f[q] : fmaxf(fmaf(a, f[q], b2), 0.f);
            uint32_t u[8];
#pragma unroll
            for (int q = 0; q < 8; ++q) u[q] = h2u(x[2 * q], x[2 * q + 1]);
            __half* dh = xh + r * PADN + qn;
            *(uint4*)dh       = make_uint4(u[0], u[1], u[2], u[3]);
            *(uint4*)(dh + 8) = make_uint4(u[4], u[5], u[6], u[7]);
        }
    };
    auto mma_kk = [&](int buf, int kk) {
        const uint32_t aWhi = sb + buf * WBUF_STRIDE + aW_off;
        const uint32_t aWlo = aWhi + W_TILE_B;
        const uint32_t aXt  = sb + XBUF_OFF + buf * XT_TILE_B + aXt_off;
        uint32_t ah[4], al[4];
        ldsm4(ah[0], ah[1], ah[2], ah[3], aWhi + kk * 32);
        ldsm4(al[0], al[1], al[2], al[3], aWlo + kk * 32);
        uint32_t bh[4][4];
#pragma unroll
        for (int u = 0; u < 4; ++u)
            ldsm4t(bh[u][0], bh[u][1], bh[u][2], bh[u][3],
                   aXt + kk * 16 * PADN * 2 + u * 32);
#pragma unroll
        for (int j = 0; j < 8; ++j) {
            const uint32_t* pb = &bh[j >> 1][(j & 1) * 2];
            mma16816(acc[j], ah, pb);
            mma16816(acc[j], al, pb);
        }
    };

    // ---- prologue: block 0 in smem, X(1) in regs ----
    cp_w(0, 0); CP_COMMIT();
    loadX(0);
    storeX(0, 0);
    if (NKB > 1) loadX(64);
    CP_WAIT0();
    __syncthreads();

    // ---- main pipeline: one barrier per k-block ----
    for (int kb = 0; kb < NKB; ++kb) {
        const int cur = kb & 1;
        mma_kk(cur, 0);                       // tensor pipe primed first
        if (kb + 1 < NKB) {
            cp_w(cur ^ 1, (kb + 1) * 64); CP_COMMIT();
            storeX((kb + 1) * 64, cur ^ 1);   // consumes v (loaded last iter)
            if (kb + 2 < NKB) loadX((kb + 2) * 64);
        }
        mma_kk(cur, 1);
        mma_kk(cur, 2);
        mma_kk(cur, 3);
        if (kb + 1 < NKB) {
            CP_WAIT0();
            __syncthreads();
        }
    }

    // ---- Y store ----
    const int orow = o0 + warp_o + (lane >> 2);
    const int ncol = n0 + warp_n + (lane & 3) * 2;
    float* d0 = Y + ((size_t)(b * CO) + orow) * NN_ + ncol;
    float* d1 = d0 + 8 * NN_;
#pragma unroll
    for (int j = 0; j < 8; ++j) {
        *(float2*)(d0 + j * 8) = make_float2(acc[j][0], acc[j][1]);
        *(float2*)(d1 + j * 8) = make_float2(acc[j][2], acc[j][3]);
    }

    // ---- deterministic stats partials ----
    float rs[2] = {}, rq[2] = {};
#pragma unroll
    for (int j = 0; j < 8; ++j) {
        rs[0] += acc[j][0] + acc[j][1];
        rq[0] += acc[j][0] * acc[j][0] + acc[j][1] * acc[j][1];
        rs[1] += acc[j][2] + acc[j][3];
        rq[1] += acc[j][2] * acc[j][2] + acc[j][3] * acc[j][3];
    }
#pragma unroll
    for (int w = 0; w < 2; ++w) {
        rs[w] += __shfl_xor_sync(0xffffffffu, rs[w], 1);
        rs[w] += __shfl_xor_sync(0xffffffffu, rs[w], 2);
        rq[w] += __shfl_xor_sync(0xffffffffu, rq[w], 1);
        rq[w] += __shfl_xor_sync(0xffffffffu, rq[w], 2);
    }
    __syncthreads();
    float* sSum = (float*)smem;        // [2 n-halves][128 rows]
    float* sSq  = sSum + 256;
    if ((lane & 3) == 0) {
        const int h = (wid >> 3) * 128;
        const int g = warp_o + (lane >> 2);
        sSum[h + g]     = rs[0];
        sSum[h + g + 8] = rs[1];
        sSq[h + g]      = rq[0];
        sSq[h + g + 8]  = rq[1];
    }
    __syncthreads();
    if (tid < 128) {
        g_psum[(size_t)(o0 + tid) * NBX + bx] = sSum[tid] + sSum[128 + tid];
        g_psq[(size_t)(o0 + tid) * NBX + bx]  = sSq[tid] + sSq[128 + tid];
    }
}

// ---------------- 5) stats reduce: partials -> BN affine ------------------
template <int LAYER>
__global__ __launch_bounds__(256) void stats_reduce(const float* __restrict__ gamma,
                                                    const float* __restrict__ beta) {
    const int o = blockIdx.x, tid = threadIdx.x;
    float s = g_psum[(size_t)o * NBX + tid] + g_psum[(size_t)o * NBX + 256 + tid];
    float q = g_psq[(size_t)o * NBX + tid] + g_psq[(size_t)o * NBX + 256 + tid];
    __shared__ float ss[256], sq[256];
    ss[tid] = s; sq[tid] = q;
    __syncthreads();
    for (int st = 128; st > 0; st >>= 1) {
        if (tid < st) { ss[tid] += ss[tid + st]; sq[tid] += sq[tid + st]; }
        __syncthreads();
    }
    if (tid == 0) {
        const float inv = 1.f / (float)(BB * NN_);
        const float mu  = ss[0] * inv;
        const float var = sq[0] * inv - mu * mu;
        const float a   = gamma[o] * rsqrtf(var + 1e-5f);
        float* ab = (LAYER == 0) ? g_ab0 : g_ab1;
        ab[o]      = a;
        ab[CO + o] = beta[o] - mu * a;
    }
}

// ---------------- 6) final BN1 + ReLU in place on d_out ------------------
__global__ __launch_bounds__(256) void bnrelu_kernel(float* __restrict__ y) {
    const size_t i = ((size_t)blockIdx.x * blockDim.x + threadIdx.x) * 4;
    const int c = (int)((i >> 13) & (CO - 1));
    const float a = g_ab1[c], bb = g_ab1[CO + c];
    float4 v = *(float4*)(y + i);
    v.x = fmaxf(fmaf(a, v.x, bb), 0.f);
    v.y = fmaxf(fmaf(a, v.y, bb), 0.f);
    v.z = fmaxf(fmaf(a, v.z, bb), 0.f);
    v.w = fmaxf(fmaf(a, v.w, bb), 0.f);
    *(float4*)(y + i) = v;
}

// ---------------- launcher ------------------------------------------------
extern "C" void kernel_launch(void* const* d_in, const int* in_sizes, int n_in,
                              void* d_out, int out_size) {
    const float* xyz1   = (const float*)d_in[0];
    const float* xyz2   = (const float*)d_in[1];
    const float* f1     = (const float*)d_in[2];
    const float* f2     = (const float*)d_in[3];
    const float* w0     = (const float*)d_in[4];
    const float* gamma0 = (const float*)d_in[5];
    const float* beta0  = (const float*)d_in[6];
    const float* w1     = (const float*)d_in[7];
    const float* gamma1 = (const float*)d_in[8];
    const float* beta1  = (const float*)d_in[9];
    float* out = (float*)d_out;

    cudaFuncSetAttribute(gemm_mma<0>, cudaFuncAttributeMaxDynamicSharedMemorySize, GEMM_SMEM);
    cudaFuncSetAttribute(gemm_mma<1>, cudaFuncAttributeMaxDynamicSharedMemorySize, GEMM_SMEM);

    nn_kernel<<<dim3(NN_ / 512, BB), 256>>>(xyz1, xyz2);
    prep_w<<<(CO * CIN + 255) / 256, 256>>>(w0, w1);
    prep_f2t<<<dim3(MM / 32, C2 / 32, BB), dim3(32, 8)>>>(f2);

    gemm_mma<0><<<dim3(NBX, CO / 128), 512, GEMM_SMEM>>>(f1, nullptr);
    stats_reduce<0><<<CO, 256>>>(gamma0, beta0);

    gemm_mma<1><<<dim3(NBX, CO / 128), 512, GEMM_SMEM>>>(nullptr, out);
    stats_reduce<1><<<CO, 256>>>(gamma1, beta1);

    bnrelu_kernel<<<(BB * CO * NN_) / (4 * 256), 256>>>(out);
}

// round 11
// speedup vs baseline: 3.0277x; 1.1163x over previous
#include <cuda_runtime.h>
#include <cuda_fp16.h>
#include <cstdint>

#define BB 8
#define NN_ 8192
#define MM 2048
#define C1 128
#define C2 256
#define CIN 384
#define CO 256
#define NBX 512            // BB * (NN_/128) gemm n-tiles

typedef unsigned long long ull;

// ---------------- device scratch (no allocations allowed) ----------------
__device__ int    g_idx[BB * NN_];
__device__ float  g_y0[(size_t)BB * CO * NN_];       // pre-BN output of layer 0
__device__ float  g_ab0[2 * CO];
__device__ float  g_ab1[2 * CO];
__device__ float  g_f2t[(size_t)BB * MM * C2];       // f2 transposed [b][m][c2]
__device__ __half g_w0h[CO * CIN];
__device__ __half g_w1h[CO * CO];
__device__ float  g_psum[CO * NBX];
__device__ float  g_psq[CO * NBX];

// ---------------- helpers -------------------------------------------------
__device__ __forceinline__ ull f2_add(ull a, ull b) {
    ull r; asm("add.rn.f32x2 %0, %1, %2;" : "=l"(r) : "l"(a), "l"(b)); return r;
}
__device__ __forceinline__ ull f2_mul(ull a, ull b) {
    ull r; asm("mul.rn.f32x2 %0, %1, %2;" : "=l"(r) : "l"(a), "l"(b)); return r;
}
__device__ __forceinline__ ull f2_pack(float lo, float hi) {
    ull r; asm("mov.b64 %0, {%1, %2};" : "=l"(r) : "f"(lo), "f"(hi)); return r;
}
__device__ __forceinline__ void f2_unpack(float& lo, float& hi, ull v) {
    asm("mov.b64 {%0, %1}, %2;" : "=f"(lo), "=f"(hi) : "l"(v));
}
__device__ __forceinline__ uint32_t smem_u32(const void* p) {
    uint32_t a;
    asm("{ .reg .u64 t; cvta.to.shared.u64 t, %1; cvt.u32.u64 %0, t; }" : "=r"(a) : "l"(p));
    return a;
}
__device__ __forceinline__ void ldsm4(uint32_t& r0, uint32_t& r1, uint32_t& r2, uint32_t& r3,
                                      uint32_t addr) {
    asm volatile("ldmatrix.sync.aligned.m8n8.x4.shared.b16 {%0,%1,%2,%3}, [%4];"
                 : "=r"(r0), "=r"(r1), "=r"(r2), "=r"(r3) : "r"(addr));
}
__device__ __forceinline__ void ldsm4t(uint32_t& r0, uint32_t& r1, uint32_t& r2, uint32_t& r3,
                                       uint32_t addr) {
    asm volatile("ldmatrix.sync.aligned.m8n8.x4.trans.shared.b16 {%0,%1,%2,%3}, [%4];"
                 : "=r"(r0), "=r"(r1), "=r"(r2), "=r"(r3) : "r"(addr));
}
__device__ __forceinline__ void mma16816(float* c, const uint32_t* a, const uint32_t* b) {
    asm volatile("mma.sync.aligned.m16n8k16.row.col.f32.f16.f16.f32 "
                 "{%0,%1,%2,%3}, {%4,%5,%6,%7}, {%8,%9}, {%0,%1,%2,%3};"
                 : "+f"(c[0]), "+f"(c[1]), "+f"(c[2]), "+f"(c[3])
                 : "r"(a[0]), "r"(a[1]), "r"(a[2]), "r"(a[3]), "r"(b[0]), "r"(b[1]));
}
__device__ __forceinline__ uint32_t h2u(float a, float b) {
    __half2 h = __halves2half2(__float2half_rn(a), __float2half_rn(b));
    return *(uint32_t*)&h;
}
#define CP_ASYNC16(saddr, gptr) \
    asm volatile("cp.async.cg.shared.global [%0], [%1], 16;" :: "r"(saddr), "l"(gptr))
#define CP_COMMIT() asm volatile("cp.async.commit_group;" ::: "memory")
#define CP_WAIT0()  asm volatile("cp.async.wait_group 0;" ::: "memory")

// ---------------- 1) nearest neighbor (bitwise-matching argmin) ----------
__global__ __launch_bounds__(256) void nn_kernel(const float* __restrict__ xyz1,
                                                 const float* __restrict__ xyz2) {
    __shared__ __align__(16) float nq[3][MM];
    const int b  = blockIdx.y;
    const int n0 = blockIdx.x * 512;
    const int tid = threadIdx.x;

    const float* x2 = xyz2 + (size_t)b * MM * 3;
    for (int m = tid; m < MM; m += 256) {
        nq[0][m] = -x2[3 * m + 0];
        nq[1][m] = -x2[3 * m + 1];
        nq[2][m] = -x2[3 * m + 2];
    }
    __syncthreads();

    const ull* qx2 = (const ull*)nq[0];
    const ull* qy2 = (const ull*)nq[1];
    const ull* qz2 = (const ull*)nq[2];

    const int ng0 = n0 + tid;
    const int ng1 = n0 + tid + 256;
    const float* p0 = xyz1 + ((size_t)b * NN_ + ng0) * 3;
    const float* p1 = xyz1 + ((size_t)b * NN_ + ng1) * 3;

    const ull px0 = f2_pack(p0[0], p0[0]), py0 = f2_pack(p0[1], p0[1]), pz0 = f2_pack(p0[2], p0[2]);
    const ull px1 = f2_pack(p1[0], p1[0]), py1 = f2_pack(p1[1], p1[1]), pz1 = f2_pack(p1[2], p1[2]);

    float be0 = 3.0e38f, bo0 = 3.0e38f, be1 = 3.0e38f, bo1 = 3.0e38f;
    int   ie0 = 0, io0 = 1, ie1 = 0, io1 = 1;

#pragma unroll 8
    for (int m2 = 0; m2 < MM / 2; ++m2) {
        const ull qx = qx2[m2], qy = qy2[m2], qz = qz2[m2];
        {
            ull dx = f2_add(px0, qx), dy = f2_add(py0, qy), dz = f2_add(pz0, qz);
            ull d  = f2_add(f2_add(f2_mul(dx, dx), f2_mul(dy, dy)), f2_mul(dz, dz));
            float dl, dh; f2_unpack(dl, dh, d);
            const bool pe = dl < be0, po = dh < bo0;
            be0 = pe ? dl : be0; ie0 = pe ? 2 * m2 : ie0;
            bo0 = po ? dh : bo0; io0 = po ? 2 * m2 + 1 : io0;
        }
        {
            ull dx = f2_add(px1, qx), dy = f2_add(py1, qy), dz = f2_add(pz1, qz);
            ull d  = f2_add(f2_add(f2_mul(dx, dx), f2_mul(dy, dy)), f2_mul(dz, dz));
            float dl, dh; f2_unpack(dl, dh, d);
            const bool pe = dl < be1, po = dh < bo1;
            be1 = pe ? dl : be1; ie1 = pe ? 2 * m2 : ie1;
            bo1 = po ? dh : bo1; io1 = po ? 2 * m2 + 1 : io1;
        }
    }
    int bi0 = ie0;
    if (bo0 < be0 || (bo0 == be0 && io0 < ie0)) bi0 = io0;
    int bi1 = ie1;
    if (bo1 < be1 || (bo1 == be1 && io1 < ie1)) bi1 = io1;

    g_idx[b * NN_ + ng0] = bi0;
    g_idx[b * NN_ + ng1] = bi1;
}

// ---------------- 2) weight convert (single fp16) --------------------------
__global__ __launch_bounds__(256) void prep_w(const float* __restrict__ w0,
                                              const float* __restrict__ w1) {
    const int i = blockIdx.x * 256 + threadIdx.x;
    if (i < CO * CIN) g_w0h[i] = __float2half_rn(w0[i]);
    if (i < CO * CO)  g_w1h[i] = __float2half_rn(w1[i]);
}

// ---------------- 3) transpose f2 -> [b][m][c2] ---------------------------
__global__ void prep_f2t(const float* __restrict__ f2) {
    __shared__ float t[32][33];
    const int b = blockIdx.z, m0 = blockIdx.x * 32, c0 = blockIdx.y * 32;
    const int tx = threadIdx.x, ty = threadIdx.y;  // 32x8
#pragma unroll
    for (int k = 0; k < 4; k++)
        t[ty + 8 * k][tx] = f2[((size_t)(b * C2) + c0 + ty + 8 * k) * MM + m0 + tx];
    __syncthreads();
#pragma unroll
    for (int k = 0; k < 4; k++)
        g_f2t[((size_t)(b * MM) + m0 + ty + 8 * k) * C2 + c0 + tx] = t[tx][ty + 8 * k];
}

// ---------------- 4) pipelined HMMA GEMM (fp16 W single, X single) --------
// 512 threads, 16 warps in 4(o) x 4(n), warp tile 32(o) x 32(n), CTA 128x128.
// 1 MMA per k16 per (o16,n8) frag. LDSM traffic per k-block: W dup4 x 16KB
// + X dup4 x 16KB = 128KB (was 192KB). Single barrier per k-block; feed
// phase in the MMA shadow (R9 structure).
#define PADK 72
#define PADN 136
#define W_TILE_B    (128 * PADK * 2)        // 18432
#define XBUF_OFF    (2 * W_TILE_B)          // 36864
#define XT_TILE_B   (64 * PADN * 2)         // 17408
#define SIDX_OFF    (XBUF_OFF + 2 * XT_TILE_B)  // 71680
#define GEMM_SMEM   (SIDX_OFF + 512)        // 72192

template <int LAYER>
__global__ __launch_bounds__(512, 1) void gemm_mma(const float* __restrict__ f1arg,
                                                   float* __restrict__ Yarg) {
    constexpr int KDIM = (LAYER == 0) ? CIN : CO;
    constexpr int NKB  = KDIM / 64;
    const __half* __restrict__ Wh = (LAYER == 0) ? g_w0h : g_w1h;
    float* __restrict__ Y = (LAYER == 0) ? g_y0 : Yarg;

    extern __shared__ __align__(16) char smem[];
    int* sidx = (int*)(smem + SIDX_OFF);

    const int tid = threadIdx.x, wid = tid >> 5, lane = tid & 31;
    const int bx = blockIdx.x;
    const int b  = bx >> 6;
    const int n0 = (bx & 63) << 7;
    const int o0 = blockIdx.y << 7;

    const int warp_o = (wid & 3) * 32;
    const int warp_n = (wid >> 2) * 32;

    const uint32_t sb = smem_u32(smem);
    const int arow = warp_o + (lane & 15);
    const int acol = (lane >> 4) * 8;
    const uint32_t aW_off = (uint32_t)(arow * PADK + acol) * 2;
    const int krow = (lane & 7) + ((lane >> 3) & 1) * 8;
    const int noff = warp_n + ((lane >> 4) & 1) * 8;
    const uint32_t aXt_off = (uint32_t)(krow * PADN + noff) * 2;

    if (LAYER == 0 && tid < 128) sidx[tid] = g_idx[b * NN_ + n0 + tid];

    float acc[2][4][4] = {};
    float4 v[4];

    auto cp_w = [&](int buf, int k0) {
        const uint32_t wb = sb + buf * W_TILE_B;
        // 128 rows x 8 segs of 16B = 1024 cp.async; 2 per thread
#pragma unroll
        for (int it = 0; it < 2; ++it) {
            const int i = tid + it * 512;
            const int row = i >> 3, seg = i & 7;
            const uint32_t so = (uint32_t)(row * PADK + seg * 8) * 2;
            const size_t wk = (size_t)(o0 + row) * KDIM + k0 + seg * 8;
            CP_ASYNC16(wb + so, Wh + wk);
        }
    };
    auto loadX = [&](int k0) {
        if (LAYER == 0 && k0 >= C1) {
            const int n = tid & 127, kq = tid >> 7;   // kq: 0..3, 16 k's each
            const float* row = g_f2t + ((size_t)(b * MM) + sidx[n]) * C2 + (k0 - C1) + kq * 16;
#pragma unroll
            for (int q = 0; q < 4; ++q) v[q] = *(const float4*)(row + q * 4);
        } else {
            const int r = tid >> 3, qn = (tid & 7) << 4;
            const float* src = (LAYER == 0)
                ? f1arg + ((size_t)(b * C1) + k0 + r) * NN_ + n0 + qn
                : g_y0 + ((size_t)(b * CO) + k0 + r) * NN_ + n0 + qn;
#pragma unroll
            for (int q = 0; q < 4; ++q) v[q] = *(const float4*)(src + q * 4);
        }
    };
    auto storeX = [&](int k0, int buf) {
        __half* xh = (__half*)(smem + XBUF_OFF + buf * XT_TILE_B);
        if (LAYER == 0 && k0 >= C1) {
            const int n = tid & 127, kq = tid >> 7;
            const float* f = (const float*)v;
#pragma unroll
            for (int q = 0; q < 16; ++q)
                xh[(kq * 16 + q) * PADN + n] = __float2half_rn(f[q]);
        } else {
            const int r = tid >> 3, qn = (tid & 7) << 4;
            float a = 1.f, b2 = 0.f;
            if (LAYER == 1) { a = g_ab0[k0 + r]; b2 = g_ab0[CO + k0 + r]; }
            const float* f = (const float*)v;
            float x[16];
#pragma unroll
            for (int q = 0; q < 16; ++q)
                x[q] = (LAYER == 0) ? f[q] : fmaxf(fmaf(a, f[q], b2), 0.f);
            uint32_t u[8];
#pragma unroll
            for (int q = 0; q < 8; ++q) u[q] = h2u(x[2 * q], x[2 * q + 1]);
            __half* dh = xh + r * PADN + qn;
            *(uint4*)dh       = make_uint4(u[0], u[1], u[2], u[3]);
            *(uint4*)(dh + 8) = make_uint4(u[4], u[5], u[6], u[7]);
        }
    };
    auto mma_kk = [&](int buf, int kk) {
        const uint32_t aW  = sb + buf * W_TILE_B + aW_off;
        const uint32_t aXt = sb + XBUF_OFF + buf * XT_TILE_B + aXt_off;
        uint32_t a[2][4];
        ldsm4(a[0][0], a[0][1], a[0][2], a[0][3], aW + kk * 32);
        ldsm4(a[1][0], a[1][1], a[1][2], a[1][3], aW + 16 * PADK * 2 + kk * 32);
        uint32_t bh[2][4];
#pragma unroll
        for (int u = 0; u < 2; ++u)
            ldsm4t(bh[u][0], bh[u][1], bh[u][2], bh[u][3],
                   aXt + kk * 16 * PADN * 2 + u * 32);
#pragma unroll
        for (int j = 0; j < 4; ++j) {
            const uint32_t* pb = &bh[j >> 1][(j & 1) * 2];
            mma16816(acc[0][j], a[0], pb);
            mma16816(acc[1][j], a[1], pb);
        }
    };

    // ---- prologue: block 0 in smem, X(1) in regs ----
    cp_w(0, 0); CP_COMMIT();
    loadX(0);
    storeX(0, 0);
    if (NKB > 1) loadX(64);
    CP_WAIT0();
    __syncthreads();

    // ---- main pipeline: one barrier per k-block ----
    for (int kb = 0; kb < NKB; ++kb) {
        const int cur = kb & 1;
        mma_kk(cur, 0);                       // tensor pipe primed first
        if (kb + 1 < NKB) {
            cp_w(cur ^ 1, (kb + 1) * 64); CP_COMMIT();
            storeX((kb + 1) * 64, cur ^ 1);   // consumes v (loaded last iter)
            if (kb + 2 < NKB) loadX((kb + 2) * 64);
        }
        mma_kk(cur, 1);
        mma_kk(cur, 2);
        mma_kk(cur, 3);
        if (kb + 1 < NKB) {
            CP_WAIT0();
            __syncthreads();
        }
    }

    // ---- Y store ----
    const int ncol = n0 + warp_n + (lane & 3) * 2;
#pragma unroll
    for (int t = 0; t < 2; ++t) {
        const int orow = o0 + warp_o + t * 16 + (lane >> 2);
        float* d0 = Y + ((size_t)(b * CO) + orow) * NN_ + ncol;
        float* d1 = d0 + 8 * NN_;
#pragma unroll
        for (int j = 0; j < 4; ++j) {
            *(float2*)(d0 + j * 8) = make_float2(acc[t][j][0], acc[t][j][1]);
            *(float2*)(d1 + j * 8) = make_float2(acc[t][j][2], acc[t][j][3]);
        }
    }

    // ---- deterministic stats partials ----
    float rs[4] = {}, rq[4] = {};
#pragma unroll
    for (int t = 0; t < 2; ++t)
#pragma unroll
        for (int j = 0; j < 4; ++j) {
            rs[t * 2 + 0] += acc[t][j][0] + acc[t][j][1];
            rq[t * 2 + 0] += acc[t][j][0] * acc[t][j][0] + acc[t][j][1] * acc[t][j][1];
            rs[t * 2 + 1] += acc[t][j][2] + acc[t][j][3];
            rq[t * 2 + 1] += acc[t][j][2] * acc[t][j][2] + acc[t][j][3] * acc[t][j][3];
        }
#pragma unroll
    for (int w = 0; w < 4; ++w) {
        rs[w] += __shfl_xor_sync(0xffffffffu, rs[w], 1);
        rs[w] += __shfl_xor_sync(0xffffffffu, rs[w], 2);
        rq[w] += __shfl_xor_sync(0xffffffffu, rq[w], 1);
        rq[w] += __shfl_xor_sync(0xffffffffu, rq[w], 2);
    }
    __syncthreads();
    float* sSum = (float*)smem;        // [4 n-groups][128 rows]
    float* sSq  = sSum + 512;
    if ((lane & 3) == 0) {
        const int h = (wid >> 2) * 128;
        const int g = warp_o + (lane >> 2);
        // rs[0]: row g, rs[1]: g+8, rs[2]: g+16, rs[3]: g+24
        sSum[h + g]      = rs[0];
        sSum[h + g + 8]  = rs[1];
        sSum[h + g + 16] = rs[2];
        sSum[h + g + 24] = rs[3];
        sSq[h + g]       = rq[0];
        sSq[h + g + 8]   = rq[1];
        sSq[h + g + 16]  = rq[2];
        sSq[h + g + 24]  = rq[3];
    }
    __syncthreads();
    if (tid < 128) {
        g_psum[(size_t)(o0 + tid) * NBX + bx] =
            (sSum[tid] + sSum[128 + tid]) + (sSum[256 + tid] + sSum[384 + tid]);
        g_psq[(size_t)(o0 + tid) * NBX + bx]  =
            (sSq[tid] + sSq[128 + tid]) + (sSq[256 + tid] + sSq[384 + tid]);
    }
}

// ---------------- 5) stats reduce: partials -> BN affine ------------------
template <int LAYER>
__global__ __launch_bounds__(256) void stats_reduce(const float* __restrict__ gamma,
                                                    const float* __restrict__ beta) {
    const int o = blockIdx.x, tid = threadIdx.x;
    float s = g_psum[(size_t)o * NBX + tid] + g_psum[(size_t)o * NBX + 256 + tid];
    float q = g_psq[(size_t)o * NBX + tid] + g_psq[(size_t)o * NBX + 256 + tid];
    __shared__ float ss[256], sq[256];
    ss[tid] = s; sq[tid] = q;
    __syncthreads();
    for (int st = 128; st > 0; st >>= 1) {
        if (tid < st) { ss[tid] += ss[tid + st]; sq[tid] += sq[tid + st]; }
        __syncthreads();
    }
    if (tid == 0) {
        const float inv = 1.f / (float)(BB * NN_);
        const float mu  = ss[0] * inv;
        const float var = sq[0] * inv - mu * mu;
        const float a   = gamma[o] * rsqrtf(var + 1e-5f);
        float* ab = (LAYER == 0) ? g_ab0 : g_ab1;
        ab[o]      = a;
        ab[CO + o] = beta[o] - mu * a;
    }
}

// ---------------- 6) final BN1 + ReLU in place on d_out ------------------
__global__ __launch_bounds__(256) void bnrelu_kernel(float* __restrict__ y) {
    const size_t i = ((size_t)blockIdx.x * blockDim.x + threadIdx.x) * 4;
    const int c = (int)((i >> 13) & (CO - 1));
    const float a = g_ab1[c], bb = g_ab1[CO + c];
    float4 v = *(float4*)(y + i);
    v.x = fmaxf(fmaf(a, v.x, bb), 0.f);
    v.y = fmaxf(fmaf(a, v.y, bb), 0.f);
    v.z = fmaxf(fmaf(a, v.z, bb), 0.f);
    v.w = fmaxf(fmaf(a, v.w, bb), 0.f);
    *(float4*)(y + i) = v;
}

// ---------------- launcher ------------------------------------------------
extern "C" void kernel_launch(void* const* d_in, const int* in_sizes, int n_in,
                              void* d_out, int out_size) {
    const float* xyz1   = (const float*)d_in[0];
    const float* xyz2   = (const float*)d_in[1];
    const float* f1     = (const float*)d_in[2];
    const float* f2     = (const float*)d_in[3];
    const float* w0     = (const float*)d_in[4];
    const float* gamma0 = (const float*)d_in[5];
    const float* beta0  = (const float*)d_in[6];
    const float* w1     = (const float*)d_in[7];
    const float* gamma1 = (const float*)d_in[8];
    const float* beta1  = (const float*)d_in[9];
    float* out = (float*)d_out;

    cudaFuncSetAttribute(gemm_mma<0>, cudaFuncAttributeMaxDynamicSharedMemorySize, GEMM_SMEM);
    cudaFuncSetAttribute(gemm_mma<1>, cudaFuncAttributeMaxDynamicSharedMemorySize, GEMM_SMEM);

    nn_kernel<<<dim3(NN_ / 512, BB), 256>>>(xyz1, xyz2);
    prep_w<<<(CO * CIN + 255) / 256, 256>>>(w0, w1);
    prep_f2t<<<dim3(MM / 32, C2 / 32, BB), dim3(32, 8)>>>(f2);

    gemm_mma<0><<<dim3(NBX, CO / 128), 512, GEMM_SMEM>>>(f1, nullptr);
    stats_reduce<0><<<CO, 256>>>(gamma0, beta0);

    gemm_mma<1><<<dim3(NBX, CO / 128), 512, GEMM_SMEM>>>(nullptr, out);
    stats_reduce<1><<<CO, 256>>>(gamma1, beta1);

    bnrelu_kernel<<<(BB * CO * NN_) / (4 * 256), 256>>>(out);
}

// round 12
// speedup vs baseline: 3.0562x; 1.0094x over previous
#include <cuda_runtime.h>
#include <cuda_fp16.h>
#include <cstdint>

#define BB 8
#define NN_ 8192
#define MM 2048
#define C1 128
#define C2 256
#define CIN 384
#define CO 256
#define NBX 512            // BB * (NN_/128) gemm n-tiles

typedef unsigned long long ull;

// ---------------- device scratch (no allocations allowed) ----------------
__device__ int    g_idx[BB * NN_];
__device__ float  g_y0[(size_t)BB * CO * NN_];       // pre-BN output of layer 0
__device__ float  g_ab0[2 * CO];
__device__ float  g_ab1[2 * CO];
__device__ float  g_f2t[(size_t)BB * MM * C2];       // f2 transposed [b][m][c2]
__device__ __half g_w0h[CO * CIN];
__device__ __half g_w1h[CO * CO];
__device__ float  g_psum[CO * NBX];
__device__ float  g_psq[CO * NBX];

// ---------------- helpers -------------------------------------------------
__device__ __forceinline__ ull f2_add(ull a, ull b) {
    ull r; asm("add.rn.f32x2 %0, %1, %2;" : "=l"(r) : "l"(a), "l"(b)); return r;
}
__device__ __forceinline__ ull f2_mul(ull a, ull b) {
    ull r; asm("mul.rn.f32x2 %0, %1, %2;" : "=l"(r) : "l"(a), "l"(b)); return r;
}
__device__ __forceinline__ ull f2_pack(float lo, float hi) {
    ull r; asm("mov.b64 %0, {%1, %2};" : "=l"(r) : "f"(lo), "f"(hi)); return r;
}
__device__ __forceinline__ void f2_unpack(float& lo, float& hi, ull v) {
    asm("mov.b64 {%0, %1}, %2;" : "=f"(lo), "=f"(hi) : "l"(v));
}
__device__ __forceinline__ uint32_t smem_u32(const void* p) {
    uint32_t a;
    asm("{ .reg .u64 t; cvta.to.shared.u64 t, %1; cvt.u32.u64 %0, t; }" : "=r"(a) : "l"(p));
    return a;
}
__device__ __forceinline__ void ldsm4(uint32_t& r0, uint32_t& r1, uint32_t& r2, uint32_t& r3,
                                      uint32_t addr) {
    asm volatile("ldmatrix.sync.aligned.m8n8.x4.shared.b16 {%0,%1,%2,%3}, [%4];"
                 : "=r"(r0), "=r"(r1), "=r"(r2), "=r"(r3) : "r"(addr));
}
__device__ __forceinline__ void ldsm4t(uint32_t& r0, uint32_t& r1, uint32_t& r2, uint32_t& r3,
                                       uint32_t addr) {
    asm volatile("ldmatrix.sync.aligned.m8n8.x4.trans.shared.b16 {%0,%1,%2,%3}, [%4];"
                 : "=r"(r0), "=r"(r1), "=r"(r2), "=r"(r3) : "r"(addr));
}
__device__ __forceinline__ void mma16816(float* c, const uint32_t* a, const uint32_t* b) {
    asm volatile("mma.sync.aligned.m16n8k16.row.col.f32.f16.f16.f32 "
                 "{%0,%1,%2,%3}, {%4,%5,%6,%7}, {%8,%9}, {%0,%1,%2,%3};"
                 : "+f"(c[0]), "+f"(c[1]), "+f"(c[2]), "+f"(c[3])
                 : "r"(a[0]), "r"(a[1]), "r"(a[2]), "r"(a[3]), "r"(b[0]), "r"(b[1]));
}
__device__ __forceinline__ uint32_t h2u(float a, float b) {
    __half2 h = __halves2half2(__float2half_rn(a), __float2half_rn(b));
    return *(uint32_t*)&h;
}
#define CP_ASYNC16(saddr, gptr) \
    asm volatile("cp.async.cg.shared.global [%0], [%1], 16;" :: "r"(saddr), "l"(gptr))
#define CP_COMMIT() asm volatile("cp.async.commit_group;" ::: "memory")
#define CP_WAIT0()  asm volatile("cp.async.wait_group 0;" ::: "memory")

// ---------------- 1) nearest neighbor (bitwise-matching argmin) ----------
__global__ __launch_bounds__(256) void nn_kernel(const float* __restrict__ xyz1,
                                                 const float* __restrict__ xyz2) {
    __shared__ __align__(16) float nq[3][MM];
    const int b  = blockIdx.y;
    const int n0 = blockIdx.x * 512;
    const int tid = threadIdx.x;

    const float* x2 = xyz2 + (size_t)b * MM * 3;
    for (int m = tid; m < MM; m += 256) {
        nq[0][m] = -x2[3 * m + 0];
        nq[1][m] = -x2[3 * m + 1];
        nq[2][m] = -x2[3 * m + 2];
    }
    __syncthreads();

    const ull* qx2 = (const ull*)nq[0];
    const ull* qy2 = (const ull*)nq[1];
    const ull* qz2 = (const ull*)nq[2];

    const int ng0 = n0 + tid;
    const int ng1 = n0 + tid + 256;
    const float* p0 = xyz1 + ((size_t)b * NN_ + ng0) * 3;
    const float* p1 = xyz1 + ((size_t)b * NN_ + ng1) * 3;

    const ull px0 = f2_pack(p0[0], p0[0]), py0 = f2_pack(p0[1], p0[1]), pz0 = f2_pack(p0[2], p0[2]);
    const ull px1 = f2_pack(p1[0], p1[0]), py1 = f2_pack(p1[1], p1[1]), pz1 = f2_pack(p1[2], p1[2]);

    float be0 = 3.0e38f, bo0 = 3.0e38f, be1 = 3.0e38f, bo1 = 3.0e38f;
    int   ie0 = 0, io0 = 1, ie1 = 0, io1 = 1;

#pragma unroll 8
    for (int m2 = 0; m2 < MM / 2; ++m2) {
        const ull qx = qx2[m2], qy = qy2[m2], qz = qz2[m2];
        {
            ull dx = f2_add(px0, qx), dy = f2_add(py0, qy), dz = f2_add(pz0, qz);
            ull d  = f2_add(f2_add(f2_mul(dx, dx), f2_mul(dy, dy)), f2_mul(dz, dz));
            float dl, dh; f2_unpack(dl, dh, d);
            const bool pe = dl < be0, po = dh < bo0;
            be0 = pe ? dl : be0; ie0 = pe ? 2 * m2 : ie0;
            bo0 = po ? dh : bo0; io0 = po ? 2 * m2 + 1 : io0;
        }
        {
            ull dx = f2_add(px1, qx), dy = f2_add(py1, qy), dz = f2_add(pz1, qz);
            ull d  = f2_add(f2_add(f2_mul(dx, dx), f2_mul(dy, dy)), f2_mul(dz, dz));
            float dl, dh; f2_unpack(dl, dh, d);
            const bool pe = dl < be1, po = dh < bo1;
            be1 = pe ? dl : be1; ie1 = pe ? 2 * m2 : ie1;
            bo1 = po ? dh : bo1; io1 = po ? 2 * m2 + 1 : io1;
        }
    }
    int bi0 = ie0;
    if (bo0 < be0 || (bo0 == be0 && io0 < ie0)) bi0 = io0;
    int bi1 = ie1;
    if (bo1 < be1 || (bo1 == be1 && io1 < ie1)) bi1 = io1;

    g_idx[b * NN_ + ng0] = bi0;
    g_idx[b * NN_ + ng1] = bi1;
}

// ---------------- 2) weight convert (single fp16) --------------------------
__global__ __launch_bounds__(256) void prep_w(const float* __restrict__ w0,
                                              const float* __restrict__ w1) {
    const int i = blockIdx.x * 256 + threadIdx.x;
    if (i < CO * CIN) g_w0h[i] = __float2half_rn(w0[i]);
    if (i < CO * CO)  g_w1h[i] = __float2half_rn(w1[i]);
}

// ---------------- 3) transpose f2 -> [b][m][c2] ---------------------------
__global__ void prep_f2t(const float* __restrict__ f2) {
    __shared__ float t[32][33];
    const int b = blockIdx.z, m0 = blockIdx.x * 32, c0 = blockIdx.y * 32;
    const int tx = threadIdx.x, ty = threadIdx.y;  // 32x8
#pragma unroll
    for (int k = 0; k < 4; k++)
        t[ty + 8 * k][tx] = f2[((size_t)(b * C2) + c0 + ty + 8 * k) * MM + m0 + tx];
    __syncthreads();
#pragma unroll
    for (int k = 0; k < 4; k++)
        g_f2t[((size_t)(b * MM) + m0 + ty + 8 * k) * C2 + c0 + tx] = t[tx][ty + 8 * k];
}

// ---------------- 4) pipelined HMMA GEMM (fp16 W+X, 2 CTAs/SM) ------------
// 256 threads, 8 warps in 4(o) x 2(n), warp tile 32(o) x 64(n), CTA 128x128.
// LDSM per k-block: W dup2 x 16KB + X dup4 x 16KB = 96KB (was 128KB).
// __launch_bounds__(256,2): two CTAs co-resident per SM so one CTA's MMAs
// cover the other's feed phase. Single barrier per k-block (R9 structure).
#define PADK 72
#define PADN 136
#define W_TILE_B    (128 * PADK * 2)        // 18432
#define XBUF_OFF    (2 * W_TILE_B)          // 36864
#define XT_TILE_B   (64 * PADN * 2)         // 17408
#define SIDX_OFF    (XBUF_OFF + 2 * XT_TILE_B)  // 71680
#define GEMM_SMEM   (SIDX_OFF + 512)        // 72192

template <int LAYER>
__global__ __launch_bounds__(256, 2) void gemm_mma(const float* __restrict__ f1arg,
                                                   float* __restrict__ Yarg) {
    constexpr int KDIM = (LAYER == 0) ? CIN : CO;
    constexpr int NKB  = KDIM / 64;
    const __half* __restrict__ Wh = (LAYER == 0) ? g_w0h : g_w1h;
    float* __restrict__ Y = (LAYER == 0) ? g_y0 : Yarg;

    extern __shared__ __align__(16) char smem[];
    int* sidx = (int*)(smem + SIDX_OFF);

    const int tid = threadIdx.x, wid = tid >> 5, lane = tid & 31;
    const int bx = blockIdx.x;
    const int b  = bx >> 6;
    const int n0 = (bx & 63) << 7;
    const int o0 = blockIdx.y << 7;

    const int warp_o = (wid & 3) * 32;
    const int warp_n = (wid >> 2) * 64;

    const uint32_t sb = smem_u32(smem);
    const int arow = warp_o + (lane & 15);
    const int acol = (lane >> 4) * 8;
    const uint32_t aW_off = (uint32_t)(arow * PADK + acol) * 2;
    const int krow = (lane & 7) + ((lane >> 3) & 1) * 8;
    const int noff = warp_n + ((lane >> 4) & 1) * 8;
    const uint32_t aXt_off = (uint32_t)(krow * PADN + noff) * 2;

    if (LAYER == 0 && tid < 128) sidx[tid] = g_idx[b * NN_ + n0 + tid];

    float acc[2][8][4] = {};
    float4 v[8];

    auto cp_w = [&](int buf, int k0) {
        const uint32_t wb = sb + buf * W_TILE_B;
#pragma unroll
        for (int it = 0; it < 4; ++it) {
            const int i = tid + it * 256;
            const int row = i >> 3, seg = i & 7;
            const uint32_t so = (uint32_t)(row * PADK + seg * 8) * 2;
            const size_t wk = (size_t)(o0 + row) * KDIM + k0 + seg * 8;
            CP_ASYNC16(wb + so, Wh + wk);
        }
    };
    auto loadX = [&](int k0) {
        if (LAYER == 0 && k0 >= C1) {
            const int n = tid & 127, kh = tid >> 7;   // kh: 0/1, 32 k's each
            const float* row = g_f2t + ((size_t)(b * MM) + sidx[n]) * C2 + (k0 - C1) + kh * 32;
#pragma unroll
            for (int q = 0; q < 8; ++q) v[q] = *(const float4*)(row + q * 4);
        } else {
            const int r = tid >> 2, qn = (tid & 3) << 5;
            const float* src = (LAYER == 0)
                ? f1arg + ((size_t)(b * C1) + k0 + r) * NN_ + n0 + qn
                : g_y0 + ((size_t)(b * CO) + k0 + r) * NN_ + n0 + qn;
#pragma unroll
            for (int q = 0; q < 8; ++q) v[q] = *(const float4*)(src + q * 4);
        }
    };
    auto storeX = [&](int k0, int buf) {
        __half* xh = (__half*)(smem + XBUF_OFF + buf * XT_TILE_B);
        if (LAYER == 0 && k0 >= C1) {
            const int n = tid & 127, kh = tid >> 7;
            const float* f = (const float*)v;
#pragma unroll
            for (int q = 0; q < 32; ++q)
                xh[(kh * 32 + q) * PADN + n] = __float2half_rn(f[q]);
        } else {
            const int r = tid >> 2, qn = (tid & 3) << 5;
            float a = 1.f, b2 = 0.f;
            if (LAYER == 1) { a = g_ab0[k0 + r]; b2 = g_ab0[CO + k0 + r]; }
            const float* f = (const float*)v;
            float x[32];
#pragma unroll
            for (int q = 0; q < 32; ++q)
                x[q] = (LAYER == 0) ? f[q] : fmaxf(fmaf(a, f[q], b2), 0.f);
            uint32_t u[16];
#pragma unroll
            for (int q = 0; q < 16; ++q) u[q] = h2u(x[2 * q], x[2 * q + 1]);
            __half* dh = xh + r * PADN + qn;
            *(uint4*)dh        = make_uint4(u[0],  u[1],  u[2],  u[3]);
            *(uint4*)(dh + 8)  = make_uint4(u[4],  u[5],  u[6],  u[7]);
            *(uint4*)(dh + 16) = make_uint4(u[8],  u[9],  u[10], u[11]);
            *(uint4*)(dh + 24) = make_uint4(u[12], u[13], u[14], u[15]);
        }
    };
    auto mma_kk = [&](int buf, int kk) {
        const uint32_t aW  = sb + buf * W_TILE_B + aW_off;
        const uint32_t aXt = sb + XBUF_OFF + buf * XT_TILE_B + aXt_off;
        uint32_t a[2][4];
        ldsm4(a[0][0], a[0][1], a[0][2], a[0][3], aW + kk * 32);
        ldsm4(a[1][0], a[1][1], a[1][2], a[1][3], aW + 16 * PADK * 2 + kk * 32);
        uint32_t bh[4][4];
#pragma unroll
        for (int u = 0; u < 4; ++u)
            ldsm4t(bh[u][0], bh[u][1], bh[u][2], bh[u][3],
                   aXt + kk * 16 * PADN * 2 + u * 32);
#pragma unroll
        for (int j = 0; j < 8; ++j) {
            const uint32_t* pb = &bh[j >> 1][(j & 1) * 2];
            mma16816(acc[0][j], a[0], pb);
            mma16816(acc[1][j], a[1], pb);
        }
    };

    // ---- prologue: block 0 in smem, X(1) in regs ----
    cp_w(0, 0); CP_COMMIT();
    loadX(0);
    storeX(0, 0);
    if (NKB > 1) loadX(64);
    CP_WAIT0();
    __syncthreads();

    // ---- main pipeline: one barrier per k-block ----
    for (int kb = 0; kb < NKB; ++kb) {
        const int cur = kb & 1;
        mma_kk(cur, 0);                       // tensor pipe primed first
        if (kb + 1 < NKB) {
            cp_w(cur ^ 1, (kb + 1) * 64); CP_COMMIT();
            storeX((kb + 1) * 64, cur ^ 1);   // consumes v (loaded last iter)
            if (kb + 2 < NKB) loadX((kb + 2) * 64);
        }
        mma_kk(cur, 1);
        mma_kk(cur, 2);
        mma_kk(cur, 3);
        if (kb + 1 < NKB) {
            CP_WAIT0();
            __syncthreads();
        }
    }

    // ---- Y store ----
    const int orow = o0 + warp_o + (lane >> 2);
    const int ncol = n0 + warp_n + (lane & 3) * 2;
#pragma unroll
    for (int t = 0; t < 2; ++t) {
        float* d0 = Y + ((size_t)(b * CO) + orow + t * 16) * NN_ + ncol;
        float* d1 = d0 + 8 * NN_;
#pragma unroll
        for (int j = 0; j < 8; ++j) {
            *(float2*)(d0 + j * 8) = make_float2(acc[t][j][0], acc[t][j][1]);
            *(float2*)(d1 + j * 8) = make_float2(acc[t][j][2], acc[t][j][3]);
        }
    }

    // ---- deterministic stats partials ----
    float rs[4] = {}, rq[4] = {};
#pragma unroll
    for (int t = 0; t < 2; ++t)
#pragma unroll
        for (int j = 0; j < 8; ++j) {
            rs[t * 2 + 0] += acc[t][j][0] + acc[t][j][1];
            rq[t * 2 + 0] += acc[t][j][0] * acc[t][j][0] + acc[t][j][1] * acc[t][j][1];
            rs[t * 2 + 1] += acc[t][j][2] + acc[t][j][3];
            rq[t * 2 + 1] += acc[t][j][2] * acc[t][j][2] + acc[t][j][3] * acc[t][j][3];
        }
#pragma unroll
    for (int w = 0; w < 4; ++w) {
        rs[w] += __shfl_xor_sync(0xffffffffu, rs[w], 1);
        rs[w] += __shfl_xor_sync(0xffffffffu, rs[w], 2);
        rq[w] += __shfl_xor_sync(0xffffffffu, rq[w], 1);
        rq[w] += __shfl_xor_sync(0xffffffffu, rq[w], 2);
    }
    __syncthreads();
    float* sSum = (float*)smem;        // [2 n-groups][128 rows]
    float* sSq  = sSum + 256;
    if ((lane & 3) == 0) {
        const int h = (wid >> 2) * 128;
        const int g = warp_o + (lane >> 2);
        sSum[h + g]      = rs[0];
        sSum[h + g + 8]  = rs[1];
        sSum[h + g + 16] = rs[2];
        sSum[h + g + 24] = rs[3];
        sSq[h + g]       = rq[0];
        sSq[h + g + 8]   = rq[1];
        sSq[h + g + 16]  = rq[2];
        sSq[h + g + 24]  = rq[3];
    }
    __syncthreads();
    if (tid < 128) {
        g_psum[(size_t)(o0 + tid) * NBX + bx] = sSum[tid] + sSum[128 + tid];
        g_psq[(size_t)(o0 + tid) * NBX + bx]  = sSq[tid] + sSq[128 + tid];
    }
}

// ---------------- 5) stats reduce: partials -> BN affine ------------------
template <int LAYER>
__global__ __launch_bounds__(256) void stats_reduce(const float* __restrict__ gamma,
                                                    const float* __restrict__ beta) {
    const int o = blockIdx.x, tid = threadIdx.x;
    float s = g_psum[(size_t)o * NBX + tid] + g_psum[(size_t)o * NBX + 256 + tid];
    float q = g_psq[(size_t)o * NBX + tid] + g_psq[(size_t)o * NBX + 256 + tid];
    __shared__ float ss[256], sq[256];
    ss[tid] = s; sq[tid] = q;
    __syncthreads();
    for (int st = 128; st > 0; st >>= 1) {
        if (tid < st) { ss[tid] += ss[tid + st]; sq[tid] += sq[tid + st]; }
        __syncthreads();
    }
    if (tid == 0) {
        const float inv = 1.f / (float)(BB * NN_);
        const float mu  = ss[0] * inv;
        const float var = sq[0] * inv - mu * mu;
        const float a   = gamma[o] * rsqrtf(var + 1e-5f);
        float* ab = (LAYER == 0) ? g_ab0 : g_ab1;
        ab[o]      = a;
        ab[CO + o] = beta[o] - mu * a;
    }
}

// ---------------- 6) final BN1 + ReLU in place on d_out ------------------
__global__ __launch_bounds__(256) void bnrelu_kernel(float* __restrict__ y) {
    const size_t i = ((size_t)blockIdx.x * blockDim.x + threadIdx.x) * 4;
    const int c = (int)((i >> 13) & (CO - 1));
    const float a = g_ab1[c], bb = g_ab1[CO + c];
    float4 v = *(float4*)(y + i);
    v.x = fmaxf(fmaf(a, v.x, bb), 0.f);
    v.y = fmaxf(fmaf(a, v.y, bb), 0.f);
    v.z = fmaxf(fmaf(a, v.z, bb), 0.f);
    v.w = fmaxf(fmaf(a, v.w, bb), 0.f);
    *(float4*)(y + i) = v;
}

// ---------------- launcher ------------------------------------------------
extern "C" void kernel_launch(void* const* d_in, const int* in_sizes, int n_in,
                              void* d_out, int out_size) {
    const float* xyz1   = (const float*)d_in[0];
    const float* xyz2   = (const float*)d_in[1];
    const float* f1     = (const float*)d_in[2];
    const float* f2     = (const float*)d_in[3];
    const float* w0     = (const float*)d_in[4];
    const float* gamma0 = (const float*)d_in[5];
    const float* beta0  = (const float*)d_in[6];
    const float* w1     = (const float*)d_in[7];
    const float* gamma1 = (const float*)d_in[8];
    const float* beta1  = (const float*)d_in[9];
    float* out = (float*)d_out;

    cudaFuncSetAttribute(gemm_mma<0>, cudaFuncAttributeMaxDynamicSharedMemorySize, GEMM_SMEM);
    cudaFuncSetAttribute(gemm_mma<1>, cudaFuncAttributeMaxDynamicSharedMemorySize, GEMM_SMEM);

    nn_kernel<<<dim3(NN_ / 512, BB), 256>>>(xyz1, xyz2);
    prep_w<<<(CO * CIN + 255) / 256, 256>>>(w0, w1);
    prep_f2t<<<dim3(MM / 32, C2 / 32, BB), dim3(32, 8)>>>(f2);

    gemm_mma<0><<<dim3(NBX, CO / 128), 256, GEMM_SMEM>>>(f1, nullptr);
    stats_reduce<0><<<CO, 256>>>(gamma0, beta0);

    gemm_mma<1><<<dim3(NBX, CO / 128), 256, GEMM_SMEM>>>(nullptr, out);
    stats_reduce<1><<<CO, 256>>>(gamma1, beta1);

    bnrelu_kernel<<<(BB * CO * NN_) / (4 * 256), 256>>>(out);
}

// round 13
// speedup vs baseline: 3.4761x; 1.1374x over previous
#include <cuda_runtime.h>
#include <cuda_fp16.h>
#include <cstdint>

#define BB 8
#define NN_ 8192
#define MM 2048
#define C1 128
#define C2 256
#define CIN 384
#define CO 256
#define NBX 512            // n-tiles total (BB * NN_/128)

typedef unsigned long long ull;

// ---------------- device scratch (no allocations allowed) ----------------
__device__ int    g_idx[BB * NN_];
__device__ float  g_y0[(size_t)BB * CO * NN_];       // pre-BN output of layer 0
__device__ float  g_ab0[2 * CO];
__device__ float  g_ab1[2 * CO];
__device__ float  g_f2t[(size_t)BB * MM * C2];       // f2 transposed [b][m][c2]
__device__ __half g_w0h[CO * CIN];
__device__ __half g_w1h[CO * CO];
__device__ float  g_psum[CO * NBX];
__device__ float  g_psq[CO * NBX];

// ---------------- helpers -------------------------------------------------
__device__ __forceinline__ ull f2_add(ull a, ull b) {
    ull r; asm("add.rn.f32x2 %0, %1, %2;" : "=l"(r) : "l"(a), "l"(b)); return r;
}
__device__ __forceinline__ ull f2_mul(ull a, ull b) {
    ull r; asm("mul.rn.f32x2 %0, %1, %2;" : "=l"(r) : "l"(a), "l"(b)); return r;
}
__device__ __forceinline__ ull f2_pack(float lo, float hi) {
    ull r; asm("mov.b64 %0, {%1, %2};" : "=l"(r) : "f"(lo), "f"(hi)); return r;
}
__device__ __forceinline__ void f2_unpack(float& lo, float& hi, ull v) {
    asm("mov.b64 {%0, %1}, %2;" : "=f"(lo), "=f"(hi) : "l"(v));
}
__device__ __forceinline__ uint32_t smem_u32(const void* p) {
    uint32_t a;
    asm("{ .reg .u64 t; cvta.to.shared.u64 t, %1; cvt.u32.u64 %0, t; }" : "=r"(a) : "l"(p));
    return a;
}
__device__ __forceinline__ void ldsm4(uint32_t& r0, uint32_t& r1, uint32_t& r2, uint32_t& r3,
                                      uint32_t addr) {
    asm volatile("ldmatrix.sync.aligned.m8n8.x4.shared.b16 {%0,%1,%2,%3}, [%4];"
                 : "=r"(r0), "=r"(r1), "=r"(r2), "=r"(r3) : "r"(addr));
}
__device__ __forceinline__ void ldsm4t(uint32_t& r0, uint32_t& r1, uint32_t& r2, uint32_t& r3,
                                       uint32_t addr) {
    asm volatile("ldmatrix.sync.aligned.m8n8.x4.trans.shared.b16 {%0,%1,%2,%3}, [%4];"
                 : "=r"(r0), "=r"(r1), "=r"(r2), "=r"(r3) : "r"(addr));
}
__device__ __forceinline__ void mma16816(float* c, const uint32_t* a, const uint32_t* b) {
    asm volatile("mma.sync.aligned.m16n8k16.row.col.f32.f16.f16.f32 "
                 "{%0,%1,%2,%3}, {%4,%5,%6,%7}, {%8,%9}, {%0,%1,%2,%3};"
                 : "+f"(c[0]), "+f"(c[1]), "+f"(c[2]), "+f"(c[3])
                 : "r"(a[0]), "r"(a[1]), "r"(a[2]), "r"(a[3]), "r"(b[0]), "r"(b[1]));
}
__device__ __forceinline__ uint32_t h2u(float a, float b) {
    __half2 h = __halves2half2(__float2half_rn(a), __float2half_rn(b));
    return *(uint32_t*)&h;
}
#define CP_ASYNC16(saddr, gptr) \
    asm volatile("cp.async.cg.shared.global [%0], [%1], 16;" :: "r"(saddr), "l"(gptr))
#define CP_COMMIT() asm volatile("cp.async.commit_group;" ::: "memory")
#define CP_WAIT0()  asm volatile("cp.async.wait_group 0;" ::: "memory")

// ---------------- 1) nearest neighbor (bitwise-matching argmin) ----------
__global__ __launch_bounds__(256) void nn_kernel(const float* __restrict__ xyz1,
                                                 const float* __restrict__ xyz2) {
    __shared__ __align__(16) float nq[3][MM];
    const int b  = blockIdx.y;
    const int n0 = blockIdx.x * 512;
    const int tid = threadIdx.x;

    const float* x2 = xyz2 + (size_t)b * MM * 3;
    for (int m = tid; m < MM; m += 256) {
        nq[0][m] = -x2[3 * m + 0];
        nq[1][m] = -x2[3 * m + 1];
        nq[2][m] = -x2[3 * m + 2];
    }
    __syncthreads();

    const ull* qx2 = (const ull*)nq[0];
    const ull* qy2 = (const ull*)nq[1];
    const ull* qz2 = (const ull*)nq[2];

    const int ng0 = n0 + tid;
    const int ng1 = n0 + tid + 256;
    const float* p0 = xyz1 + ((size_t)b * NN_ + ng0) * 3;
    const float* p1 = xyz1 + ((size_t)b * NN_ + ng1) * 3;

    const ull px0 = f2_pack(p0[0], p0[0]), py0 = f2_pack(p0[1], p0[1]), pz0 = f2_pack(p0[2], p0[2]);
    const ull px1 = f2_pack(p1[0], p1[0]), py1 = f2_pack(p1[1], p1[1]), pz1 = f2_pack(p1[2], p1[2]);

    float be0 = 3.0e38f, bo0 = 3.0e38f, be1 = 3.0e38f, bo1 = 3.0e38f;
    int   ie0 = 0, io0 = 1, ie1 = 0, io1 = 1;

#pragma unroll 8
    for (int m2 = 0; m2 < MM / 2; ++m2) {
        const ull qx = qx2[m2], qy = qy2[m2], qz = qz2[m2];
        {
            ull dx = f2_add(px0, qx), dy = f2_add(py0, qy), dz = f2_add(pz0, qz);
            ull d  = f2_add(f2_add(f2_mul(dx, dx), f2_mul(dy, dy)), f2_mul(dz, dz));
            float dl, dh; f2_unpack(dl, dh, d);
            const bool pe = dl < be0, po = dh < bo0;
            be0 = pe ? dl : be0; ie0 = pe ? 2 * m2 : ie0;
            bo0 = po ? dh : bo0; io0 = po ? 2 * m2 + 1 : io0;
        }
        {
            ull dx = f2_add(px1, qx), dy = f2_add(py1, qy), dz = f2_add(pz1, qz);
            ull d  = f2_add(f2_add(f2_mul(dx, dx), f2_mul(dy, dy)), f2_mul(dz, dz));
            float dl, dh; f2_unpack(dl, dh, d);
            const bool pe = dl < be1, po = dh < bo1;
            be1 = pe ? dl : be1; ie1 = pe ? 2 * m2 : ie1;
            bo1 = po ? dh : bo1; io1 = po ? 2 * m2 + 1 : io1;
        }
    }
    int bi0 = ie0;
    if (bo0 < be0 || (bo0 == be0 && io0 < ie0)) bi0 = io0;
    int bi1 = ie1;
    if (bo1 < be1 || (bo1 == be1 && io1 < ie1)) bi1 = io1;

    g_idx[b * NN_ + ng0] = bi0;
    g_idx[b * NN_ + ng1] = bi1;
}

// ---------------- 2) weight convert (single fp16) --------------------------
__global__ __launch_bounds__(256) void prep_w(const float* __restrict__ w0,
                                              const float* __restrict__ w1) {
    const int i = blockIdx.x * 256 + threadIdx.x;
    if (i < CO * CIN) g_w0h[i] = __float2half_rn(w0[i]);
    if (i < CO * CO)  g_w1h[i] = __float2half_rn(w1[i]);
}

// ---------------- 3) transpose f2 -> [b][m][c2] ---------------------------
__global__ void prep_f2t(const float* __restrict__ f2) {
    __shared__ float t[32][33];
    const int b = blockIdx.z, m0 = blockIdx.x * 32, c0 = blockIdx.y * 32;
    const int tx = threadIdx.x, ty = threadIdx.y;  // 32x8
#pragma unroll
    for (int k = 0; k < 4; k++)
        t[ty + 8 * k][tx] = f2[((size_t)(b * C2) + c0 + ty + 8 * k) * MM + m0 + tx];
    __syncthreads();
#pragma unroll
    for (int k = 0; k < 4; k++)
        g_f2t[((size_t)(b * MM) + m0 + ty + 8 * k) * C2 + c0 + tx] = t[tx][ty + 8 * k];
}

// ---------------- 4) pipelined HMMA GEMM, CTA 256(o) x 128(n) -------------
// 256 threads, 8 warps in 4(o) x 2(n), warp tile 64(o) x 64(n). CO=256 so
// one CTA covers the full o-range: LDSM per 128x128-equiv drops to ~64KB
// (W dup2, X dup4 over 2 tiles) and the X feed amortizes over 2x outputs.
// Single barrier per k-block; feed in MMA shadow (R9 structure).
#define PADK 72
#define PADN 136
#define W_TILE_B    (256 * PADK * 2)        // 36864
#define XBUF_OFF    (2 * W_TILE_B)          // 73728
#define XT_TILE_B   (64 * PADN * 2)         // 17408
#define SIDX_OFF    (XBUF_OFF + 2 * XT_TILE_B)  // 108544
#define GEMM_SMEM   (SIDX_OFF + 512)        // 109056

template <int LAYER>
__global__ __launch_bounds__(256, 1) void gemm_mma(const float* __restrict__ f1arg,
                                                   float* __restrict__ Yarg) {
    constexpr int KDIM = (LAYER == 0) ? CIN : CO;
    constexpr int NKB  = KDIM / 64;
    const __half* __restrict__ Wh = (LAYER == 0) ? g_w0h : g_w1h;
    float* __restrict__ Y = (LAYER == 0) ? g_y0 : Yarg;

    extern __shared__ __align__(16) char smem[];
    int* sidx = (int*)(smem + SIDX_OFF);

    const int tid = threadIdx.x, wid = tid >> 5, lane = tid & 31;
    const int bx = blockIdx.x;
    const int b  = bx >> 6;
    const int n0 = (bx & 63) << 7;

    const int warp_o = (wid & 3) * 64;
    const int warp_n = (wid >> 2) * 64;

    const uint32_t sb = smem_u32(smem);
    const int arow = warp_o + (lane & 15);
    const int acol = (lane >> 4) * 8;
    const uint32_t aW_off = (uint32_t)(arow * PADK + acol) * 2;
    const int krow = (lane & 7) + ((lane >> 3) & 1) * 8;
    const int noff = warp_n + ((lane >> 4) & 1) * 8;
    const uint32_t aXt_off = (uint32_t)(krow * PADN + noff) * 2;

    if (LAYER == 0 && tid < 128) sidx[tid] = g_idx[b * NN_ + n0 + tid];

    float acc[4][8][4] = {};
    float4 v[8];

    auto cp_w = [&](int buf, int k0) {
        const uint32_t wb = sb + buf * W_TILE_B;
#pragma unroll
        for (int it = 0; it < 8; ++it) {
            const int i = tid + it * 256;
            const int row = i >> 3, seg = i & 7;
            const uint32_t so = (uint32_t)(row * PADK + seg * 8) * 2;
            const size_t wk = (size_t)row * KDIM + k0 + seg * 8;
            CP_ASYNC16(wb + so, Wh + wk);
        }
    };
    auto loadX = [&](int k0) {
        if (LAYER == 0 && k0 >= C1) {
            const int n = tid & 127, kh = tid >> 7;   // kh: 0/1, 32 k's each
            const float* row = g_f2t + ((size_t)(b * MM) + sidx[n]) * C2 + (k0 - C1) + kh * 32;
#pragma unroll
            for (int q = 0; q < 8; ++q) v[q] = *(const float4*)(row + q * 4);
        } else {
            const int r = tid >> 2, qn = (tid & 3) << 5;
            const float* src = (LAYER == 0)
                ? f1arg + ((size_t)(b * C1) + k0 + r) * NN_ + n0 + qn
                : g_y0 + ((size_t)(b * CO) + k0 + r) * NN_ + n0 + qn;
#pragma unroll
            for (int q = 0; q < 8; ++q) v[q] = *(const float4*)(src + q * 4);
        }
    };
    auto storeX = [&](int k0, int buf) {
        __half* xh = (__half*)(smem + XBUF_OFF + buf * XT_TILE_B);
        if (LAYER == 0 && k0 >= C1) {
            const int n = tid & 127, kh = tid >> 7;
            const float* f = (const float*)v;
#pragma unroll
            for (int q = 0; q < 32; ++q)
                xh[(kh * 32 + q) * PADN + n] = __float2half_rn(f[q]);
        } else {
            const int r = tid >> 2, qn = (tid & 3) << 5;
            float a = 1.f, b2 = 0.f;
            if (LAYER == 1) { a = g_ab0[k0 + r]; b2 = g_ab0[CO + k0 + r]; }
            const float* f = (const float*)v;
            float x[32];
#pragma unroll
            for (int q = 0; q < 32; ++q)
                x[q] = (LAYER == 0) ? f[q] : fmaxf(fmaf(a, f[q], b2), 0.f);
            uint32_t u[16];
#pragma unroll
            for (int q = 0; q < 16; ++q) u[q] = h2u(x[2 * q], x[2 * q + 1]);
            __half* dh = xh + r * PADN + qn;
            *(uint4*)dh        = make_uint4(u[0],  u[1],  u[2],  u[3]);
            *(uint4*)(dh + 8)  = make_uint4(u[4],  u[5],  u[6],  u[7]);
            *(uint4*)(dh + 16) = make_uint4(u[8],  u[9],  u[10], u[11]);
            *(uint4*)(dh + 24) = make_uint4(u[12], u[13], u[14], u[15]);
        }
    };
    auto mma_kk = [&](int buf, int kk) {
        const uint32_t aW  = sb + buf * W_TILE_B + aW_off;
        const uint32_t aXt = sb + XBUF_OFF + buf * XT_TILE_B + aXt_off;
        uint32_t bh[4][4];
#pragma unroll
        for (int u = 0; u < 4; ++u)
            ldsm4t(bh[u][0], bh[u][1], bh[u][2], bh[u][3],
                   aXt + kk * 16 * PADN * 2 + u * 32);
#pragma unroll
        for (int t = 0; t < 4; ++t) {
            uint32_t a[4];
            ldsm4(a[0], a[1], a[2], a[3], aW + t * 16 * PADK * 2 + kk * 32);
#pragma unroll
            for (int j = 0; j < 8; ++j) {
                const uint32_t* pb = &bh[j >> 1][(j & 1) * 2];
                mma16816(acc[t][j], a, pb);
            }
        }
    };

    // ---- prologue: block 0 in smem, X(1) in regs ----
    cp_w(0, 0); CP_COMMIT();
    loadX(0);
    storeX(0, 0);
    if (NKB > 1) loadX(64);
    CP_WAIT0();
    __syncthreads();

    // ---- main pipeline: one barrier per k-block ----
    for (int kb = 0; kb < NKB; ++kb) {
        const int cur = kb & 1;
        mma_kk(cur, 0);                       // tensor pipe primed first
        if (kb + 1 < NKB) {
            cp_w(cur ^ 1, (kb + 1) * 64); CP_COMMIT();
            storeX((kb + 1) * 64, cur ^ 1);   // consumes v (loaded last iter)
            if (kb + 2 < NKB) loadX((kb + 2) * 64);
        }
        mma_kk(cur, 1);
        mma_kk(cur, 2);
        mma_kk(cur, 3);
        if (kb + 1 < NKB) {
            CP_WAIT0();
            __syncthreads();
        }
    }

    // ---- Y store ----
    const int ncol = n0 + warp_n + (lane & 3) * 2;
#pragma unroll
    for (int t = 0; t < 4; ++t) {
        const int orow = warp_o + t * 16 + (lane >> 2);
        float* d0 = Y + ((size_t)(b * CO) + orow) * NN_ + ncol;
        float* d1 = d0 + 8 * NN_;
#pragma unroll
        for (int j = 0; j < 8; ++j) {
            *(float2*)(d0 + j * 8) = make_float2(acc[t][j][0], acc[t][j][1]);
            *(float2*)(d1 + j * 8) = make_float2(acc[t][j][2], acc[t][j][3]);
        }
    }

    // ---- deterministic stats partials ----
    float rs[8] = {}, rq[8] = {};
#pragma unroll
    for (int t = 0; t < 4; ++t)
#pragma unroll
        for (int j = 0; j < 8; ++j) {
            rs[t * 2 + 0] += acc[t][j][0] + acc[t][j][1];
            rq[t * 2 + 0] += acc[t][j][0] * acc[t][j][0] + acc[t][j][1] * acc[t][j][1];
            rs[t * 2 + 1] += acc[t][j][2] + acc[t][j][3];
            rq[t * 2 + 1] += acc[t][j][2] * acc[t][j][2] + acc[t][j][3] * acc[t][j][3];
        }
#pragma unroll
    for (int w = 0; w < 8; ++w) {
        rs[w] += __shfl_xor_sync(0xffffffffu, rs[w], 1);
        rs[w] += __shfl_xor_sync(0xffffffffu, rs[w], 2);
        rq[w] += __shfl_xor_sync(0xffffffffu, rq[w], 1);
        rq[w] += __shfl_xor_sync(0xffffffffu, rq[w], 2);
    }
    __syncthreads();
    float* sSum = (float*)smem;        // [2 n-groups][256 rows]
    float* sSq  = sSum + 512;
    if ((lane & 3) == 0) {
        const int h = (wid >> 2) * 256;
#pragma unroll
        for (int t = 0; t < 4; ++t) {
            const int g = warp_o + t * 16 + (lane >> 2);
            sSum[h + g]     = rs[t * 2 + 0];
            sSum[h + g + 8] = rs[t * 2 + 1];
            sSq[h + g]      = rq[t * 2 + 0];
            sSq[h + g + 8]  = rq[t * 2 + 1];
        }
    }
    __syncthreads();
    if (tid < 256) {
        g_psum[(size_t)tid * NBX + bx] = sSum[tid] + sSum[256 + tid];
        g_psq[(size_t)tid * NBX + bx]  = sSq[tid] + sSq[256 + tid];
    }
}

// ---------------- 5) stats reduce: partials -> BN affine ------------------
template <int LAYER>
__global__ __launch_bounds__(256) void stats_reduce(const float* __restrict__ gamma,
                                                    const float* __restrict__ beta) {
    const int o = blockIdx.x, tid = threadIdx.x;
    float s = g_psum[(size_t)o * NBX + tid] + g_psum[(size_t)o * NBX + 256 + tid];
    float q = g_psq[(size_t)o * NBX + tid] + g_psq[(size_t)o * NBX + 256 + tid];
    __shared__ float ss[256], sq[256];
    ss[tid] = s; sq[tid] = q;
    __syncthreads();
    for (int st = 128; st > 0; st >>= 1) {
        if (tid < st) { ss[tid] += ss[tid + st]; sq[tid] += sq[tid + st]; }
        __syncthreads();
    }
    if (tid == 0) {
        const float inv = 1.f / (float)(BB * NN_);
        const float mu  = ss[0] * inv;
        const float var = sq[0] * inv - mu * mu;
        const float a   = gamma[o] * rsqrtf(var + 1e-5f);
        float* ab = (LAYER == 0) ? g_ab0 : g_ab1;
        ab[o]      = a;
        ab[CO + o] = beta[o] - mu * a;
    }
}

// ---------------- 6) final BN1 + ReLU in place on d_out ------------------
__global__ __launch_bounds__(256) void bnrelu_kernel(float* __restrict__ y) {
    const size_t i = ((size_t)blockIdx.x * blockDim.x + threadIdx.x) * 4;
    const int c = (int)((i >> 13) & (CO - 1));
    const float a = g_ab1[c], bb = g_ab1[CO + c];
    float4 v = *(float4*)(y + i);
    v.x = fmaxf(fmaf(a, v.x, bb), 0.f);
    v.y = fmaxf(fmaf(a, v.y, bb), 0.f);
    v.z = fmaxf(fmaf(a, v.z, bb), 0.f);
    v.w = fmaxf(fmaf(a, v.w, bb), 0.f);
    *(float4*)(y + i) = v;
}

// ---------------- launcher ------------------------------------------------
extern "C" void kernel_launch(void* const* d_in, const int* in_sizes, int n_in,
                              void* d_out, int out_size) {
    const float* xyz1   = (const float*)d_in[0];
    const float* xyz2   = (const float*)d_in[1];
    const float* f1     = (const float*)d_in[2];
    const float* f2     = (const float*)d_in[3];
    const float* w0     = (const float*)d_in[4];
    const float* gamma0 = (const float*)d_in[5];
    const float* beta0  = (const float*)d_in[6];
    const float* w1     = (const float*)d_in[7];
    const float* gamma1 = (const float*)d_in[8];
    const float* beta1  = (const float*)d_in[9];
    float* out = (float*)d_out;

    cudaFuncSetAttribute(gemm_mma<0>, cudaFuncAttributeMaxDynamicSharedMemorySize, GEMM_SMEM);
    cudaFuncSetAttribute(gemm_mma<1>, cudaFuncAttributeMaxDynamicSharedMemorySize, GEMM_SMEM);

    nn_kernel<<<dim3(NN_ / 512, BB), 256>>>(xyz1, xyz2);
    prep_w<<<(CO * CIN + 255) / 256, 256>>>(w0, w1);
    prep_f2t<<<dim3(MM / 32, C2 / 32, BB), dim3(32, 8)>>>(f2);

    gemm_mma<0><<<NBX, 256, GEMM_SMEM>>>(f1, nullptr);
    stats_reduce<0><<<CO, 256>>>(gamma0, beta0);

    gemm_mma<1><<<NBX, 256, GEMM_SMEM>>>(nullptr, out);
    stats_reduce<1><<<CO, 256>>>(gamma1, beta1);

    bnrelu_kernel<<<(BB * CO * NN_) / (4 * 256), 256>>>(out);
}